// round 1
// baseline (speedup 1.0000x reference)
#include <cuda_runtime.h>
#include <cuda_bf16.h>
#include <math.h>
#include <stdint.h>

using bf16 = __nv_bfloat16;

constexpr int NN  = 20000;      // nodes
constexpr int NE  = 320000;     // edges
constexpr int HID = 512;
constexpr int ED  = 64;
constexpr int KC1 = 2*HID + ED; // 1088
constexpr int KC3 = 2*HID;      // 1024

constexpr int BM = 128, BN = 64, BK = 32, PAD = 8, BKP = BK + PAD;

// ---------------- device scratch (static: no allocation allowed) ----------------
__device__ bf16 g_x_hi[NN*HID];
__device__ bf16 g_x_lo[NN*HID];
__device__ bf16 g_ea_hi[NE*ED];
__device__ bf16 g_ea_lo[NE*ED];
__device__ bf16 g_w1t_hi[HID*KC1];
__device__ bf16 g_w1t_lo[HID*KC1];
__device__ bf16 g_w2t_hi[HID*HID];
__device__ bf16 g_w2t_lo[HID*HID];
__device__ bf16 g_w3t_hi[HID*KC3];
__device__ bf16 g_w3t_lo[HID*KC3];
__device__ bf16 g_w4t_hi[HID*HID];
__device__ bf16 g_w4t_lo[HID*HID];
__device__ int   g_ei[2*NE];
__device__ float g_h[(size_t)NE*HID];   // 655 MB edge hidden
__device__ float g_agg[NN*HID];
__device__ float g_u[NN*HID];
__device__ float g_y[NN*HID];

// ---------------- helpers ----------------
__device__ __forceinline__ float mishf(float v){
    float sp = (v > 20.f) ? v : log1pf(__expf(v));
    return v * tanhf(sp);
}
__device__ __forceinline__ unsigned smem_u32(const void* p){
    return (unsigned)__cvta_generic_to_shared(p);
}
__device__ __forceinline__ void ldsm_x4(unsigned &r0, unsigned &r1, unsigned &r2, unsigned &r3, unsigned addr){
    asm volatile("ldmatrix.sync.aligned.m8n8.x4.shared.b16 {%0,%1,%2,%3}, [%4];"
                 : "=r"(r0), "=r"(r1), "=r"(r2), "=r"(r3) : "r"(addr));
}
__device__ __forceinline__ void mma_bf16(float* c, unsigned a0, unsigned a1, unsigned a2, unsigned a3,
                                         unsigned b0, unsigned b1){
    asm volatile("mma.sync.aligned.m16n8k16.row.col.f32.bf16.bf16.f32 "
                 "{%0,%1,%2,%3}, {%4,%5,%6,%7}, {%8,%9}, {%0,%1,%2,%3};"
                 : "+f"(c[0]), "+f"(c[1]), "+f"(c[2]), "+f"(c[3])
                 : "r"(a0), "r"(a1), "r"(a2), "r"(a3), "r"(b0), "r"(b1));
}
__device__ __forceinline__ void split1(float v, bf16 &h, bf16 &l){
    h = __float2bfloat16(v);
    l = __float2bfloat16(v - __bfloat162float(h));
}

// ---------------- prep kernels ----------------
// edge_index may arrive as int64 or int32 (JAX x64 flag). Detect per-thread
// (deterministic: inspects fixed leading entries) and normalize to int32.
__global__ void k_decode_idx(const void* __restrict__ ei_raw){
    int i = blockIdx.x * blockDim.x + threadIdx.x;
    if (i >= 2*NE) return;
    const long long* p64 = (const long long*)ei_raw;
    bool is64 = true;
    #pragma unroll
    for (int j = 0; j < 4; j++){
        long long v = p64[j];
        if (v < 0 || v >= NN) is64 = false;
    }
    if (is64) g_ei[i] = (int)p64[i];
    else      g_ei[i] = ((const int*)ei_raw)[i];
}

__global__ void k_split_x(const float* __restrict__ s){
    int i = blockIdx.x * blockDim.x + threadIdx.x;
    if (i < NN*HID){ bf16 h,l; split1(s[i], h, l); g_x_hi[i]=h; g_x_lo[i]=l; }
}
__global__ void k_split_ea(const float* __restrict__ s){
    int i = blockIdx.x * blockDim.x + threadIdx.x;
    if (i < NE*ED){ bf16 h,l; split1(s[i], h, l); g_ea_hi[i]=h; g_ea_lo[i]=l; }
}
// W[k][n] row-major -> transposed split Wt[n][k] (GEMM B operand, k-contiguous)
__global__ void k_split_w(const float* __restrict__ W, int K, int sel){
    int i = blockIdx.x * blockDim.x + threadIdx.x;
    if (i >= K*HID) return;
    int k = i / HID, n = i % HID;
    bf16 h, l; split1(W[i], h, l);
    bf16 *hi, *lo;
    if      (sel == 1){ hi = g_w1t_hi; lo = g_w1t_lo; }
    else if (sel == 2){ hi = g_w2t_hi; lo = g_w2t_lo; }
    else if (sel == 3){ hi = g_w3t_hi; lo = g_w3t_lo; }
    else              { hi = g_w4t_hi; lo = g_w4t_lo; }
    hi[(size_t)n*K + k] = h;
    lo[(size_t)n*K + k] = l;
}
__global__ void k_zero_agg(){
    int i = blockIdx.x * blockDim.x + threadIdx.x;
    if (i < NN*HID) g_agg[i] = 0.f;
}

// ---------------- fused split-bf16 GEMM ----------------
// MODE 1: h   = mish(gather(x[src],x[dst],ea) @ W1 + b1)          M=NE, K=1088
// MODE 2: msg = mish(h @ W2 + b2); atomic scatter into agg[dst]   M=NE, K=512
// MODE 3: u   = mish(concat(x, agg) @ W3 + b3)                    M=NN, K=1024
// MODE 4: y   = x + u @ W4 + b4                                   M=NN, K=512
template<int MODE>
__global__ __launch_bounds__(256)
void gemm_kernel(const float* __restrict__ bias, const float* __restrict__ xres)
{
    constexpr int KTOT = (MODE==1) ? KC1 : (MODE==3) ? KC3 : HID;

    __shared__ bf16 sA[2][BM][BKP];   // [hi/lo][row][k]
    __shared__ bf16 sB[2][BN][BKP];   // [hi/lo][n][k]
    __shared__ int  sSrc[BM];
    __shared__ int  sDst[BM];

    const int tid = threadIdx.x;
    const int m0  = blockIdx.x * BM;
    const int n0  = blockIdx.y * BN;

    if constexpr (MODE==1 || MODE==2){
        if (tid < BM){
            sSrc[tid] = g_ei[m0 + tid];
            sDst[tid] = g_ei[NE + m0 + tid];
        }
    }

    const int wid = tid >> 5, lane = tid & 31;
    const int wm  = wid >> 1, wn = wid & 1;   // 4x2 warp grid, 32x32 per warp
    const int g   = lane >> 2, t = lane & 3;

    float acc[2][4][4];
    #pragma unroll
    for (int a = 0; a < 2; a++)
        #pragma unroll
        for (int b = 0; b < 4; b++)
            #pragma unroll
            for (int c = 0; c < 4; c++) acc[a][b][c] = 0.f;

    const int rA = tid >> 1;            // A: 2 threads/row, each 16 elems
    const int co = (tid & 1) * 16;
    const int rB = tid >> 2;            // B: 4 threads/row, each 8 elems
    const int qB = (tid & 3) * 8;

    const bf16 *Wh, *Wl;
    if constexpr (MODE==1){ Wh = g_w1t_hi; Wl = g_w1t_lo; }
    else if constexpr (MODE==2){ Wh = g_w2t_hi; Wl = g_w2t_lo; }
    else if constexpr (MODE==3){ Wh = g_w3t_hi; Wl = g_w3t_lo; }
    else { Wh = g_w4t_hi; Wl = g_w4t_lo; }

    for (int kc = 0; kc < KTOT / BK; ++kc){
        const int k0 = kc * BK;
        __syncthreads();   // also orders sSrc/sDst writes on first iteration

        // ---- A tile ----
        if constexpr (MODE==1){
            const bf16 *ph, *pl;
            if (k0 < HID){
                size_t off = (size_t)sSrc[rA]*HID + (k0 + co);
                ph = g_x_hi + off; pl = g_x_lo + off;
            } else if (k0 < 2*HID){
                size_t off = (size_t)sDst[rA]*HID + (k0 - HID + co);
                ph = g_x_hi + off; pl = g_x_lo + off;
            } else {
                size_t off = (size_t)(m0 + rA)*ED + (k0 - 2*HID + co);
                ph = g_ea_hi + off; pl = g_ea_lo + off;
            }
            uint4 h0 = *(const uint4*)ph;
            uint4 h1 = *(const uint4*)(ph + 8);
            uint4 l0 = *(const uint4*)pl;
            uint4 l1 = *(const uint4*)(pl + 8);
            *(uint4*)&sA[0][rA][co]     = h0;
            *(uint4*)&sA[0][rA][co + 8] = h1;
            *(uint4*)&sA[1][rA][co]     = l0;
            *(uint4*)&sA[1][rA][co + 8] = l1;
        } else if constexpr (MODE==2 || MODE==4){
            int rowi = m0 + rA;
            if (MODE == 4) rowi = min(rowi, NN-1);
            const float* base = (MODE==2) ? g_h : g_u;
            const float4* src = (const float4*)(base + (size_t)rowi*HID + k0 + co);
            #pragma unroll
            for (int j = 0; j < 4; j++){
                float4 v = src[j];
                bf16 h0,l0,h1,l1,h2,l2,h3,l3;
                split1(v.x,h0,l0); split1(v.y,h1,l1); split1(v.z,h2,l2); split1(v.w,h3,l3);
                __nv_bfloat162 ph01; ph01.x=h0; ph01.y=h1;
                __nv_bfloat162 ph23; ph23.x=h2; ph23.y=h3;
                __nv_bfloat162 pl01; pl01.x=l0; pl01.y=l1;
                __nv_bfloat162 pl23; pl23.x=l2; pl23.y=l3;
                *(__nv_bfloat162*)&sA[0][rA][co + j*4]     = ph01;
                *(__nv_bfloat162*)&sA[0][rA][co + j*4 + 2] = ph23;
                *(__nv_bfloat162*)&sA[1][rA][co + j*4]     = pl01;
                *(__nv_bfloat162*)&sA[1][rA][co + j*4 + 2] = pl23;
            }
        } else { // MODE 3: [x | agg]
            const int node = min(m0 + rA, NN-1);
            if (k0 < HID){
                size_t off = (size_t)node*HID + k0 + co;
                uint4 h0 = *(const uint4*)(g_x_hi + off);
                uint4 h1 = *(const uint4*)(g_x_hi + off + 8);
                uint4 l0 = *(const uint4*)(g_x_lo + off);
                uint4 l1 = *(const uint4*)(g_x_lo + off + 8);
                *(uint4*)&sA[0][rA][co]     = h0;
                *(uint4*)&sA[0][rA][co + 8] = h1;
                *(uint4*)&sA[1][rA][co]     = l0;
                *(uint4*)&sA[1][rA][co + 8] = l1;
            } else {
                const float4* src = (const float4*)(g_agg + (size_t)node*HID + (k0 - HID) + co);
                #pragma unroll
                for (int j = 0; j < 4; j++){
                    float4 v = src[j];
                    bf16 h0,l0,h1,l1,h2,l2,h3,l3;
                    split1(v.x,h0,l0); split1(v.y,h1,l1); split1(v.z,h2,l2); split1(v.w,h3,l3);
                    __nv_bfloat162 ph01; ph01.x=h0; ph01.y=h1;
                    __nv_bfloat162 ph23; ph23.x=h2; ph23.y=h3;
                    __nv_bfloat162 pl01; pl01.x=l0; pl01.y=l1;
                    __nv_bfloat162 pl23; pl23.x=l2; pl23.y=l3;
                    *(__nv_bfloat162*)&sA[0][rA][co + j*4]     = ph01;
                    *(__nv_bfloat162*)&sA[0][rA][co + j*4 + 2] = ph23;
                    *(__nv_bfloat162*)&sA[1][rA][co + j*4]     = pl01;
                    *(__nv_bfloat162*)&sA[1][rA][co + j*4 + 2] = pl23;
                }
            }
        }

        // ---- B tile (Wt is [n][k], k-contiguous) ----
        {
            size_t off = (size_t)(n0 + rB)*KTOT + k0 + qB;
            uint4 vh = *(const uint4*)(Wh + off);
            uint4 vl = *(const uint4*)(Wl + off);
            *(uint4*)&sB[0][rB][qB] = vh;
            *(uint4*)&sB[1][rB][qB] = vl;
        }
        __syncthreads();

        // ---- compute: 2 k-steps of 16, 3-term split product ----
        #pragma unroll
        for (int ks = 0; ks < 2; ++ks){
            const int kk = ks * 16;
            unsigned af[2][2][4];
            #pragma unroll
            for (int mt = 0; mt < 2; ++mt){
                int row = wm*32 + mt*16 + (lane & 7) + ((lane >> 3) & 1) * 8;
                int col = kk + (lane >> 4) * 8;
                ldsm_x4(af[mt][0][0], af[mt][0][1], af[mt][0][2], af[mt][0][3],
                        smem_u32(&sA[0][row][col]));
                ldsm_x4(af[mt][1][0], af[mt][1][1], af[mt][1][2], af[mt][1][3],
                        smem_u32(&sA[1][row][col]));
            }
            unsigned bf[4][2][2];
            #pragma unroll
            for (int np = 0; np < 2; ++np){
                int ntl = 2*np + (lane >> 4);
                int row = wn*32 + ntl*8 + (lane & 7);
                int col = kk + ((lane >> 3) & 1) * 8;
                unsigned r0, r1, r2, r3;
                ldsm_x4(r0, r1, r2, r3, smem_u32(&sB[0][row][col]));
                bf[2*np][0][0]=r0; bf[2*np][0][1]=r1; bf[2*np+1][0][0]=r2; bf[2*np+1][0][1]=r3;
                ldsm_x4(r0, r1, r2, r3, smem_u32(&sB[1][row][col]));
                bf[2*np][1][0]=r0; bf[2*np][1][1]=r1; bf[2*np+1][1][0]=r2; bf[2*np+1][1][1]=r3;
            }
            #pragma unroll
            for (int mt = 0; mt < 2; ++mt)
                #pragma unroll
                for (int nt = 0; nt < 4; ++nt){
                    mma_bf16(acc[mt][nt], af[mt][0][0], af[mt][0][1], af[mt][0][2], af[mt][0][3],
                             bf[nt][0][0], bf[nt][0][1]);          // hi*hi
                    mma_bf16(acc[mt][nt], af[mt][0][0], af[mt][0][1], af[mt][0][2], af[mt][0][3],
                             bf[nt][1][0], bf[nt][1][1]);          // hi*lo
                    mma_bf16(acc[mt][nt], af[mt][1][0], af[mt][1][1], af[mt][1][2], af[mt][1][3],
                             bf[nt][0][0], bf[nt][0][1]);          // lo*hi
                }
        }
    }

    // ---- epilogue ----
    #pragma unroll
    for (int mt = 0; mt < 2; ++mt){
        const int rl0 = wm*32 + mt*16 + g;
        const int rl1 = rl0 + 8;
        #pragma unroll
        for (int nt = 0; nt < 4; ++nt){
            const int col = n0 + wn*32 + nt*8 + t*2;
            const float bv0 = bias[col];
            const float bv1 = bias[col+1];
            float v00 = acc[mt][nt][0] + bv0;
            float v01 = acc[mt][nt][1] + bv1;
            float v10 = acc[mt][nt][2] + bv0;
            float v11 = acc[mt][nt][3] + bv1;
            if constexpr (MODE==1){
                v00 = mishf(v00); v01 = mishf(v01); v10 = mishf(v10); v11 = mishf(v11);
                *(float2*)&g_h[(size_t)(m0+rl0)*HID + col] = make_float2(v00, v01);
                *(float2*)&g_h[(size_t)(m0+rl1)*HID + col] = make_float2(v10, v11);
            } else if constexpr (MODE==2){
                v00 = mishf(v00); v01 = mishf(v01); v10 = mishf(v10); v11 = mishf(v11);
                const int d0 = sDst[rl0], d1 = sDst[rl1];
                atomicAdd(&g_agg[(size_t)d0*HID + col],     v00);
                atomicAdd(&g_agg[(size_t)d0*HID + col + 1], v01);
                atomicAdd(&g_agg[(size_t)d1*HID + col],     v10);
                atomicAdd(&g_agg[(size_t)d1*HID + col + 1], v11);
            } else if constexpr (MODE==3){
                const int r0i = m0 + rl0, r1i = m0 + rl1;
                if (r0i < NN)
                    *(float2*)&g_u[(size_t)r0i*HID + col] = make_float2(mishf(v00), mishf(v01));
                if (r1i < NN)
                    *(float2*)&g_u[(size_t)r1i*HID + col] = make_float2(mishf(v10), mishf(v11));
            } else {
                const int r0i = m0 + rl0, r1i = m0 + rl1;
                if (r0i < NN){
                    float2 xv = *(const float2*)&xres[(size_t)r0i*HID + col];
                    *(float2*)&g_y[(size_t)r0i*HID + col] = make_float2(v00 + xv.x, v01 + xv.y);
                }
                if (r1i < NN){
                    float2 xv = *(const float2*)&xres[(size_t)r1i*HID + col];
                    *(float2*)&g_y[(size_t)r1i*HID + col] = make_float2(v10 + xv.x, v11 + xv.y);
                }
            }
        }
    }
}

// ---------------- LayerNorm ----------------
__global__ __launch_bounds__(128)
void ln_kernel(const float* __restrict__ gamma, const float* __restrict__ beta,
               float* __restrict__ out)
{
    const int row = blockIdx.x, tid = threadIdx.x;
    float4 v = *((const float4*)(g_y + (size_t)row*HID) + tid);
    float s  = v.x + v.y + v.z + v.w;
    float ss = fmaf(v.x, v.x, fmaf(v.y, v.y, fmaf(v.z, v.z, v.w*v.w)));
    #pragma unroll
    for (int o = 16; o > 0; o >>= 1){
        s  += __shfl_xor_sync(0xffffffffu, s,  o);
        ss += __shfl_xor_sync(0xffffffffu, ss, o);
    }
    __shared__ float sh_s[4], sh_ss[4];
    if ((tid & 31) == 0){ sh_s[tid >> 5] = s; sh_ss[tid >> 5] = ss; }
    __syncthreads();
    s  = sh_s[0]  + sh_s[1]  + sh_s[2]  + sh_s[3];
    ss = sh_ss[0] + sh_ss[1] + sh_ss[2] + sh_ss[3];
    const float mu  = s * (1.f / HID);
    const float var = ss * (1.f / HID) - mu * mu;
    const float inv = rsqrtf(var + 1e-5f);
    float4 gm = ((const float4*)gamma)[tid];
    float4 bt = ((const float4*)beta)[tid];
    float4 o;
    o.x = (v.x - mu) * inv * gm.x + bt.x;
    o.y = (v.y - mu) * inv * gm.y + bt.y;
    o.z = (v.z - mu) * inv * gm.z + bt.z;
    o.w = (v.w - mu) * inv * gm.w + bt.w;
    *((float4*)(out + (size_t)row*HID) + tid) = o;
}

// ---------------- launch ----------------
extern "C" void kernel_launch(void* const* d_in, const int* in_sizes, int n_in,
                              void* d_out, int out_size)
{
    (void)in_sizes; (void)n_in; (void)out_size;
    const float* x     = (const float*)d_in[0];
    const void*  ei    = d_in[1];
    const float* ea    = (const float*)d_in[2];
    const float* W1    = (const float*)d_in[3];
    const float* b1    = (const float*)d_in[4];
    const float* W2    = (const float*)d_in[5];
    const float* b2    = (const float*)d_in[6];
    const float* W3    = (const float*)d_in[7];
    const float* b3    = (const float*)d_in[8];
    const float* W4    = (const float*)d_in[9];
    const float* b4    = (const float*)d_in[10];
    const float* gamma = (const float*)d_in[11];
    const float* beta  = (const float*)d_in[12];
    float* out = (float*)d_out;

    k_decode_idx<<<(2*NE + 255)/256, 256>>>(ei);
    k_split_x  <<<(NN*HID + 255)/256, 256>>>(x);
    k_split_ea <<<(NE*ED + 255)/256, 256>>>(ea);
    k_split_w  <<<(KC1*HID + 255)/256, 256>>>(W1, KC1, 1);
    k_split_w  <<<(HID*HID + 255)/256, 256>>>(W2, HID, 2);
    k_split_w  <<<(KC3*HID + 255)/256, 256>>>(W3, KC3, 3);
    k_split_w  <<<(HID*HID + 255)/256, 256>>>(W4, HID, 4);
    k_zero_agg <<<(NN*HID + 255)/256, 256>>>();

    dim3 gE(NE/BM, HID/BN);                 // 2500 x 8
    dim3 gN((NN + BM - 1)/BM, HID/BN);      // 157 x 8
    gemm_kernel<1><<<gE, 256>>>(b1, nullptr);
    gemm_kernel<2><<<gE, 256>>>(b2, nullptr);
    gemm_kernel<3><<<gN, 256>>>(b3, nullptr);
    gemm_kernel<4><<<gN, 256>>>(b4, x);
    ln_kernel<<<NN, 128>>>(gamma, beta, out);
}

// round 3
// speedup vs baseline: 1.8767x; 1.8767x over previous
#include <cuda_runtime.h>
#include <cuda_bf16.h>
#include <math.h>
#include <stdint.h>

using bf16 = __nv_bfloat16;

constexpr int NN  = 20000;      // nodes
constexpr int NE  = 320000;     // edges
constexpr int HID = 512;
constexpr int ED  = 64;
constexpr int KC3 = 2*HID;      // 1024

constexpr int BM = 128, BN = 64, BK = 32, PAD = 8, BKP = BK + PAD;

// ---------------- device scratch (static: no allocation allowed) ----------------
__device__ bf16 g_x_hi[NN*HID],  g_x_lo[NN*HID];
__device__ bf16 g_ea_hi[NE*ED],  g_ea_lo[NE*ED];
__device__ bf16 g_w1a_hi[HID*HID], g_w1a_lo[HID*HID];   // W1 rows [0,512)    transposed
__device__ bf16 g_w1b_hi[HID*HID], g_w1b_lo[HID*HID];   // W1 rows [512,1024) transposed
__device__ bf16 g_w1c_hi[HID*ED],  g_w1c_lo[HID*ED];    // W1 rows [1024,1088) transposed
__device__ bf16 g_w2t_hi[HID*HID], g_w2t_lo[HID*HID];
__device__ bf16 g_w3t_hi[HID*KC3], g_w3t_lo[HID*KC3];
__device__ bf16 g_w4t_hi[HID*HID], g_w4t_lo[HID*HID];
__device__ int   g_ei[2*NE];
__device__ float g_P[NN*HID];                    // x @ W1a
__device__ float g_Q[NN*HID];                    // x @ W1b
__device__ bf16  g_h_hi[(size_t)NE*HID], g_h_lo[(size_t)NE*HID];
__device__ float g_agg[NN*HID];
__device__ float g_u[NN*HID];
__device__ float g_y[NN*HID];

// ---------------- helpers ----------------
__device__ __forceinline__ float mishf(float x){
    float t   = __expf(fminf(x, 15.f));
    float num = t * (t + 2.f);
    return x * __fdividef(num, num + 2.f);
}
__device__ __forceinline__ unsigned smem_u32(const void* p){
    return (unsigned)__cvta_generic_to_shared(p);
}
__device__ __forceinline__ void ldsm_x4(unsigned &r0, unsigned &r1, unsigned &r2, unsigned &r3, unsigned addr){
    asm volatile("ldmatrix.sync.aligned.m8n8.x4.shared.b16 {%0,%1,%2,%3}, [%4];"
                 : "=r"(r0), "=r"(r1), "=r"(r2), "=r"(r3) : "r"(addr));
}
__device__ __forceinline__ void mma_bf16(float* c, unsigned a0, unsigned a1, unsigned a2, unsigned a3,
                                         unsigned b0, unsigned b1){
    asm volatile("mma.sync.aligned.m16n8k16.row.col.f32.bf16.bf16.f32 "
                 "{%0,%1,%2,%3}, {%4,%5,%6,%7}, {%8,%9}, {%0,%1,%2,%3};"
                 : "+f"(c[0]), "+f"(c[1]), "+f"(c[2]), "+f"(c[3])
                 : "r"(a0), "r"(a1), "r"(a2), "r"(a3), "r"(b0), "r"(b1));
}
__device__ __forceinline__ void split1(float v, bf16 &h, bf16 &l){
    h = __float2bfloat16(v);
    l = __float2bfloat16(v - __bfloat162float(h));
}
__device__ __forceinline__ uint32_t pack2(bf16 a, bf16 b){
    __nv_bfloat162 p; p.x = a; p.y = b;
    return *(uint32_t*)&p;
}

// ---------------- prep kernels ----------------
__global__ void k_decode_idx(const void* __restrict__ ei_raw){
    int i = blockIdx.x * blockDim.x + threadIdx.x;
    if (i >= 2*NE) return;
    const long long* p64 = (const long long*)ei_raw;
    bool is64 = true;
    #pragma unroll
    for (int j = 0; j < 4; j++){
        long long v = p64[j];
        if (v < 0 || v >= NN) is64 = false;
    }
    g_ei[i] = is64 ? (int)p64[i] : ((const int*)ei_raw)[i];
}
__global__ void k_split_x(const float* __restrict__ s){
    int i = blockIdx.x * blockDim.x + threadIdx.x;
    if (i < NN*HID){ bf16 h,l; split1(s[i],h,l); g_x_hi[i]=h; g_x_lo[i]=l; }
}
__global__ void k_split_ea(const float* __restrict__ s){
    int i = blockIdx.x * blockDim.x + threadIdx.x;
    if (i < NE*ED){ bf16 h,l; split1(s[i],h,l); g_ea_hi[i]=h; g_ea_lo[i]=l; }
}
// W [K][HID] row-major -> transposed split Wt[n][k]
__global__ void k_split_w(const float* __restrict__ W, int K, int sel){
    int i = blockIdx.x * blockDim.x + threadIdx.x;
    if (i >= K*HID) return;
    int k = i / HID, n = i % HID;
    bf16 h, l; split1(W[i], h, l);
    bf16 *hi, *lo;
    if      (sel == 1){ hi = g_w1a_hi; lo = g_w1a_lo; }
    else if (sel == 2){ hi = g_w1b_hi; lo = g_w1b_lo; }
    else if (sel == 3){ hi = g_w1c_hi; lo = g_w1c_lo; }
    else if (sel == 4){ hi = g_w2t_hi; lo = g_w2t_lo; }
    else if (sel == 5){ hi = g_w3t_hi; lo = g_w3t_lo; }
    else              { hi = g_w4t_hi; lo = g_w4t_lo; }
    hi[(size_t)n*K + k] = h;
    lo[(size_t)n*K + k] = l;
}
__global__ void k_zero_agg(){
    int i = blockIdx.x * blockDim.x + threadIdx.x;
    if (i < NN*HID) g_agg[i] = 0.f;
}

// ---------------- fused split-bf16 GEMM (mma.sync core) ----------------
// MODE 5: P = x @ W1a                    M=NN, K=512  (no bias, no act)
// MODE 6: Q = x @ W1b                    M=NN, K=512
// MODE 1: h = mish(ea@W1c + P[src] + Q[dst] + b1) -> g_h hi/lo   M=NE, K=64
// MODE 2: msg = mish(h @ W2 + b2); atomic scatter into agg[dst]  M=NE, K=512
// MODE 3: u = mish([x|agg] @ W3 + b3)    M=NN, K=1024
// MODE 4: y = x + u @ W4 + b4            M=NN, K=512
template<int MODE>
__global__ __launch_bounds__(256)
void gemm_kernel(const float* __restrict__ bias, const float* __restrict__ xres)
{
    constexpr int KTOT = (MODE==1) ? ED : (MODE==3) ? KC3 : HID;
    constexpr bool HAS_BIAS = (MODE != 5 && MODE != 6);

    __shared__ bf16 sA[2][BM][BKP];
    __shared__ bf16 sB[2][BN][BKP];
    __shared__ int  sSrc[BM];
    __shared__ int  sDst[BM];

    const int tid = threadIdx.x;
    const int m0  = blockIdx.x * BM;
    const int n0  = blockIdx.y * BN;

    if constexpr (MODE==1 || MODE==2){
        if (tid < BM){
            if (MODE == 1) sSrc[tid] = g_ei[m0 + tid];
            sDst[tid] = g_ei[NE + m0 + tid];
        }
    }

    const int wid = tid >> 5, lane = tid & 31;
    const int wm  = wid >> 1, wn = wid & 1;   // 4x2 warp grid, 32x32 per warp
    const int g   = lane >> 2, t = lane & 3;

    float acc[2][4][4];
    #pragma unroll
    for (int a = 0; a < 2; a++)
        #pragma unroll
        for (int b = 0; b < 4; b++)
            #pragma unroll
            for (int c = 0; c < 4; c++) acc[a][b][c] = 0.f;

    const int rA = tid >> 1;            // A: 2 threads/row, each 16 elems
    const int co = (tid & 1) * 16;
    const int rB = tid >> 2;            // B: 4 threads/row, each 8 elems
    const int qB = (tid & 3) * 8;

    const bf16 *Wh, *Wl;
    if      constexpr (MODE==1){ Wh = g_w1c_hi; Wl = g_w1c_lo; }
    else if constexpr (MODE==2){ Wh = g_w2t_hi; Wl = g_w2t_lo; }
    else if constexpr (MODE==3){ Wh = g_w3t_hi; Wl = g_w3t_lo; }
    else if constexpr (MODE==4){ Wh = g_w4t_hi; Wl = g_w4t_lo; }
    else if constexpr (MODE==5){ Wh = g_w1a_hi; Wl = g_w1a_lo; }
    else                       { Wh = g_w1b_hi; Wl = g_w1b_lo; }

    for (int kc = 0; kc < KTOT / BK; ++kc){
        const int k0 = kc * BK;
        __syncthreads();   // also orders sSrc/sDst writes on first iteration

        // ---- A tile ----
        if constexpr (MODE==1){
            size_t off = (size_t)(m0 + rA)*ED + k0 + co;
            uint4 h0 = *(const uint4*)(g_ea_hi + off);
            uint4 h1 = *(const uint4*)(g_ea_hi + off + 8);
            uint4 l0 = *(const uint4*)(g_ea_lo + off);
            uint4 l1 = *(const uint4*)(g_ea_lo + off + 8);
            *(uint4*)&sA[0][rA][co]     = h0;
            *(uint4*)&sA[0][rA][co + 8] = h1;
            *(uint4*)&sA[1][rA][co]     = l0;
            *(uint4*)&sA[1][rA][co + 8] = l1;
        } else if constexpr (MODE==2){
            size_t off = (size_t)(m0 + rA)*HID + k0 + co;
            uint4 h0 = *(const uint4*)(g_h_hi + off);
            uint4 h1 = *(const uint4*)(g_h_hi + off + 8);
            uint4 l0 = *(const uint4*)(g_h_lo + off);
            uint4 l1 = *(const uint4*)(g_h_lo + off + 8);
            *(uint4*)&sA[0][rA][co]     = h0;
            *(uint4*)&sA[0][rA][co + 8] = h1;
            *(uint4*)&sA[1][rA][co]     = l0;
            *(uint4*)&sA[1][rA][co + 8] = l1;
        } else if constexpr (MODE==5 || MODE==6){
            const int node = min(m0 + rA, NN-1);
            size_t off = (size_t)node*HID + k0 + co;
            uint4 h0 = *(const uint4*)(g_x_hi + off);
            uint4 h1 = *(const uint4*)(g_x_hi + off + 8);
            uint4 l0 = *(const uint4*)(g_x_lo + off);
            uint4 l1 = *(const uint4*)(g_x_lo + off + 8);
            *(uint4*)&sA[0][rA][co]     = h0;
            *(uint4*)&sA[0][rA][co + 8] = h1;
            *(uint4*)&sA[1][rA][co]     = l0;
            *(uint4*)&sA[1][rA][co + 8] = l1;
        } else if constexpr (MODE==4){
            int rowi = min(m0 + rA, NN-1);
            const float4* src = (const float4*)(g_u + (size_t)rowi*HID + k0 + co);
            #pragma unroll
            for (int j = 0; j < 4; j++){
                float4 v = src[j];
                bf16 h0,l0,h1,l1,h2,l2,h3,l3;
                split1(v.x,h0,l0); split1(v.y,h1,l1); split1(v.z,h2,l2); split1(v.w,h3,l3);
                *(uint32_t*)&sA[0][rA][co + j*4]     = pack2(h0,h1);
                *(uint32_t*)&sA[0][rA][co + j*4 + 2] = pack2(h2,h3);
                *(uint32_t*)&sA[1][rA][co + j*4]     = pack2(l0,l1);
                *(uint32_t*)&sA[1][rA][co + j*4 + 2] = pack2(l2,l3);
            }
        } else { // MODE 3: [x | agg]
            const int node = min(m0 + rA, NN-1);
            if (k0 < HID){
                size_t off = (size_t)node*HID + k0 + co;
                uint4 h0 = *(const uint4*)(g_x_hi + off);
                uint4 h1 = *(const uint4*)(g_x_hi + off + 8);
                uint4 l0 = *(const uint4*)(g_x_lo + off);
                uint4 l1 = *(const uint4*)(g_x_lo + off + 8);
                *(uint4*)&sA[0][rA][co]     = h0;
                *(uint4*)&sA[0][rA][co + 8] = h1;
                *(uint4*)&sA[1][rA][co]     = l0;
                *(uint4*)&sA[1][rA][co + 8] = l1;
            } else {
                const float4* src = (const float4*)(g_agg + (size_t)node*HID + (k0 - HID) + co);
                #pragma unroll
                for (int j = 0; j < 4; j++){
                    float4 v = src[j];
                    bf16 h0,l0,h1,l1,h2,l2,h3,l3;
                    split1(v.x,h0,l0); split1(v.y,h1,l1); split1(v.z,h2,l2); split1(v.w,h3,l3);
                    *(uint32_t*)&sA[0][rA][co + j*4]     = pack2(h0,h1);
                    *(uint32_t*)&sA[0][rA][co + j*4 + 2] = pack2(h2,h3);
                    *(uint32_t*)&sA[1][rA][co + j*4]     = pack2(l0,l1);
                    *(uint32_t*)&sA[1][rA][co + j*4 + 2] = pack2(l2,l3);
                }
            }
        }

        // ---- B tile (Wt is [n][k], k-contiguous) ----
        {
            size_t off = (size_t)(n0 + rB)*KTOT + k0 + qB;
            uint4 vh = *(const uint4*)(Wh + off);
            uint4 vl = *(const uint4*)(Wl + off);
            *(uint4*)&sB[0][rB][qB] = vh;
            *(uint4*)&sB[1][rB][qB] = vl;
        }
        __syncthreads();

        // ---- compute: 2 k-steps of 16, 3-term split product ----
        #pragma unroll
        for (int ks = 0; ks < 2; ++ks){
            const int kk = ks * 16;
            unsigned af[2][2][4];
            #pragma unroll
            for (int mt = 0; mt < 2; ++mt){
                int row = wm*32 + mt*16 + (lane & 7) + ((lane >> 3) & 1) * 8;
                int col = kk + (lane >> 4) * 8;
                ldsm_x4(af[mt][0][0], af[mt][0][1], af[mt][0][2], af[mt][0][3],
                        smem_u32(&sA[0][row][col]));
                ldsm_x4(af[mt][1][0], af[mt][1][1], af[mt][1][2], af[mt][1][3],
                        smem_u32(&sA[1][row][col]));
            }
            unsigned bfm[4][2][2];
            #pragma unroll
            for (int np = 0; np < 2; ++np){
                int ntl = 2*np + (lane >> 4);
                int row = wn*32 + ntl*8 + (lane & 7);
                int col = kk + ((lane >> 3) & 1) * 8;
                unsigned r0, r1, r2, r3;
                ldsm_x4(r0, r1, r2, r3, smem_u32(&sB[0][row][col]));
                bfm[2*np][0][0]=r0; bfm[2*np][0][1]=r1; bfm[2*np+1][0][0]=r2; bfm[2*np+1][0][1]=r3;
                ldsm_x4(r0, r1, r2, r3, smem_u32(&sB[1][row][col]));
                bfm[2*np][1][0]=r0; bfm[2*np][1][1]=r1; bfm[2*np+1][1][0]=r2; bfm[2*np+1][1][1]=r3;
            }
            #pragma unroll
            for (int mt = 0; mt < 2; ++mt)
                #pragma unroll
                for (int nt = 0; nt < 4; ++nt){
                    mma_bf16(acc[mt][nt], af[mt][0][0], af[mt][0][1], af[mt][0][2], af[mt][0][3],
                             bfm[nt][0][0], bfm[nt][0][1]);          // hi*hi
                    mma_bf16(acc[mt][nt], af[mt][0][0], af[mt][0][1], af[mt][0][2], af[mt][0][3],
                             bfm[nt][1][0], bfm[nt][1][1]);          // hi*lo
                    mma_bf16(acc[mt][nt], af[mt][1][0], af[mt][1][1], af[mt][1][2], af[mt][1][3],
                             bfm[nt][0][0], bfm[nt][0][1]);          // lo*hi
                }
        }
    }

    // ---- epilogue ----
    #pragma unroll
    for (int mt = 0; mt < 2; ++mt){
        const int rl0 = wm*32 + mt*16 + g;
        const int rl1 = rl0 + 8;
        int s0 = 0, s1 = 0, d0 = 0, d1 = 0;
        if constexpr (MODE==1){ s0 = sSrc[rl0]; s1 = sSrc[rl1]; d0 = sDst[rl0]; d1 = sDst[rl1]; }
        if constexpr (MODE==2){ d0 = sDst[rl0]; d1 = sDst[rl1]; }
        #pragma unroll
        for (int nt = 0; nt < 4; ++nt){
            const int col = n0 + wn*32 + nt*8 + t*2;
            float bv0 = 0.f, bv1 = 0.f;
            if constexpr (HAS_BIAS){ bv0 = bias[col]; bv1 = bias[col+1]; }
            float v00 = acc[mt][nt][0] + bv0;
            float v01 = acc[mt][nt][1] + bv1;
            float v10 = acc[mt][nt][2] + bv0;
            float v11 = acc[mt][nt][3] + bv1;
            if constexpr (MODE==1){
                float2 p0 = *(const float2*)&g_P[(size_t)s0*HID + col];
                float2 q0 = *(const float2*)&g_Q[(size_t)d0*HID + col];
                float2 p1 = *(const float2*)&g_P[(size_t)s1*HID + col];
                float2 q1 = *(const float2*)&g_Q[(size_t)d1*HID + col];
                v00 = mishf(v00 + p0.x + q0.x);
                v01 = mishf(v01 + p0.y + q0.y);
                v10 = mishf(v10 + p1.x + q1.x);
                v11 = mishf(v11 + p1.y + q1.y);
                bf16 h00,l00,h01,l01,h10,l10,h11,l11;
                split1(v00,h00,l00); split1(v01,h01,l01);
                split1(v10,h10,l10); split1(v11,h11,l11);
                size_t o0 = (size_t)(m0+rl0)*HID + col;
                size_t o1 = (size_t)(m0+rl1)*HID + col;
                *(uint32_t*)&g_h_hi[o0] = pack2(h00,h01);
                *(uint32_t*)&g_h_lo[o0] = pack2(l00,l01);
                *(uint32_t*)&g_h_hi[o1] = pack2(h10,h11);
                *(uint32_t*)&g_h_lo[o1] = pack2(l10,l11);
            } else if constexpr (MODE==2){
                v00 = mishf(v00); v01 = mishf(v01); v10 = mishf(v10); v11 = mishf(v11);
                atomicAdd(&g_agg[(size_t)d0*HID + col],     v00);
                atomicAdd(&g_agg[(size_t)d0*HID + col + 1], v01);
                atomicAdd(&g_agg[(size_t)d1*HID + col],     v10);
                atomicAdd(&g_agg[(size_t)d1*HID + col + 1], v11);
            } else if constexpr (MODE==3){
                const int r0i = m0 + rl0, r1i = m0 + rl1;
                if (r0i < NN)
                    *(float2*)&g_u[(size_t)r0i*HID + col] = make_float2(mishf(v00), mishf(v01));
                if (r1i < NN)
                    *(float2*)&g_u[(size_t)r1i*HID + col] = make_float2(mishf(v10), mishf(v11));
            } else if constexpr (MODE==4){
                const int r0i = m0 + rl0, r1i = m0 + rl1;
                if (r0i < NN){
                    float2 xv = *(const float2*)&xres[(size_t)r0i*HID + col];
                    *(float2*)&g_y[(size_t)r0i*HID + col] = make_float2(v00 + xv.x, v01 + xv.y);
                }
                if (r1i < NN){
                    float2 xv = *(const float2*)&xres[(size_t)r1i*HID + col];
                    *(float2*)&g_y[(size_t)r1i*HID + col] = make_float2(v10 + xv.x, v11 + xv.y);
                }
            } else { // MODE 5/6: P or Q, fp32, no act
                float* dst = (MODE==5) ? g_P : g_Q;
                const int r0i = m0 + rl0, r1i = m0 + rl1;
                if (r0i < NN)
                    *(float2*)&dst[(size_t)r0i*HID + col] = make_float2(v00, v01);
                if (r1i < NN)
                    *(float2*)&dst[(size_t)r1i*HID + col] = make_float2(v10, v11);
            }
        }
    }
}

// ---------------- LayerNorm ----------------
__global__ __launch_bounds__(128)
void ln_kernel(const float* __restrict__ gamma, const float* __restrict__ beta,
               float* __restrict__ out)
{
    const int row = blockIdx.x, tid = threadIdx.x;
    float4 v = *((const float4*)(g_y + (size_t)row*HID) + tid);
    float s  = v.x + v.y + v.z + v.w;
    float ss = fmaf(v.x, v.x, fmaf(v.y, v.y, fmaf(v.z, v.z, v.w*v.w)));
    #pragma unroll
    for (int o = 16; o > 0; o >>= 1){
        s  += __shfl_xor_sync(0xffffffffu, s,  o);
        ss += __shfl_xor_sync(0xffffffffu, ss, o);
    }
    __shared__ float sh_s[4], sh_ss[4];
    if ((tid & 31) == 0){ sh_s[tid >> 5] = s; sh_ss[tid >> 5] = ss; }
    __syncthreads();
    s  = sh_s[0]  + sh_s[1]  + sh_s[2]  + sh_s[3];
    ss = sh_ss[0] + sh_ss[1] + sh_ss[2] + sh_ss[3];
    const float mu  = s * (1.f / HID);
    const float var = ss * (1.f / HID) - mu * mu;
    const float inv = rsqrtf(var + 1e-5f);
    float4 gm = ((const float4*)gamma)[tid];
    float4 bt = ((const float4*)beta)[tid];
    float4 o;
    o.x = (v.x - mu) * inv * gm.x + bt.x;
    o.y = (v.y - mu) * inv * gm.y + bt.y;
    o.z = (v.z - mu) * inv * gm.z + bt.z;
    o.w = (v.w - mu) * inv * gm.w + bt.w;
    *((float4*)(out + (size_t)row*HID) + tid) = o;
}

// ---------------- launch ----------------
extern "C" void kernel_launch(void* const* d_in, const int* in_sizes, int n_in,
                              void* d_out, int out_size)
{
    (void)in_sizes; (void)n_in; (void)out_size;
    const float* x     = (const float*)d_in[0];
    const void*  ei    = d_in[1];
    const float* ea    = (const float*)d_in[2];
    const float* W1    = (const float*)d_in[3];
    const float* b1    = (const float*)d_in[4];
    const float* W2    = (const float*)d_in[5];
    const float* b2    = (const float*)d_in[6];
    const float* W3    = (const float*)d_in[7];
    const float* b3    = (const float*)d_in[8];
    const float* W4    = (const float*)d_in[9];
    const float* b4    = (const float*)d_in[10];
    const float* gamma = (const float*)d_in[11];
    const float* beta  = (const float*)d_in[12];
    float* out = (float*)d_out;

    k_decode_idx<<<(2*NE + 255)/256, 256>>>(ei);
    k_split_x  <<<(NN*HID + 255)/256, 256>>>(x);
    k_split_ea <<<(NE*ED + 255)/256, 256>>>(ea);
    k_split_w  <<<(HID*HID + 255)/256, 256>>>(W1,               HID, 1);  // W1a
    k_split_w  <<<(HID*HID + 255)/256, 256>>>(W1 + HID*HID,     HID, 2);  // W1b
    k_split_w  <<<(ED*HID  + 255)/256, 256>>>(W1 + 2*HID*HID,   ED,  3);  // W1c
    k_split_w  <<<(HID*HID + 255)/256, 256>>>(W2,               HID, 4);
    k_split_w  <<<(KC3*HID + 255)/256, 256>>>(W3,               KC3, 5);
    k_split_w  <<<(HID*HID + 255)/256, 256>>>(W4,               HID, 6);
    k_zero_agg <<<(NN*HID + 255)/256, 256>>>();

    dim3 gE(NE/BM, HID/BN);                 // 2500 x 8
    dim3 gN((NN + BM - 1)/BM, HID/BN);      // 157 x 8
    gemm_kernel<5><<<gN, 256>>>(nullptr, nullptr);   // P = x @ W1a
    gemm_kernel<6><<<gN, 256>>>(nullptr, nullptr);   // Q = x @ W1b
    gemm_kernel<1><<<gE, 256>>>(b1, nullptr);        // h  (edge, K=64, fused gather)
    gemm_kernel<2><<<gE, 256>>>(b2, nullptr);        // messages + scatter
    gemm_kernel<3><<<gN, 256>>>(b3, nullptr);        // u
    gemm_kernel<4><<<gN, 256>>>(b4, x);              // y = x + u@W4+b4
    ln_kernel<<<NN, 128>>>(gamma, beta, out);
}

// round 4
// speedup vs baseline: 2.2271x; 1.1867x over previous
#include <cuda_runtime.h>
#include <cuda_bf16.h>
#include <math.h>
#include <stdint.h>

using bf16 = __nv_bfloat16;

constexpr int NN  = 20000;      // nodes
constexpr int NE  = 320000;     // edges
constexpr int HID = 512;
constexpr int ED  = 64;
constexpr int KC3 = 2*HID;      // 1024

constexpr int BM = 128, BN = 64, BK = 32, PAD = 8, BKP = BK + PAD;

// smem layout (elements): [stage][ Ahi | Alo | Bhi | Blo ]
constexpr int ASZ = BM*BKP;
constexpr int BSZ = BN*BKP;
constexpr int STG = 2*ASZ + 2*BSZ;
constexpr int SMEM_BYTES = 2*STG*(int)sizeof(bf16);   // 61440

// ---------------- device scratch ----------------
__device__ bf16 g_x_hi[NN*HID],  g_x_lo[NN*HID];
__device__ bf16 g_ea_hi[NE*ED],  g_ea_lo[NE*ED];
__device__ bf16 g_w1a_hi[HID*HID], g_w1a_lo[HID*HID];
__device__ bf16 g_w1b_hi[HID*HID], g_w1b_lo[HID*HID];
__device__ bf16 g_w1c_hi[HID*ED],  g_w1c_lo[HID*ED];
__device__ bf16 g_w2t_hi[HID*HID], g_w2t_lo[HID*HID];
__device__ bf16 g_w3t_hi[HID*KC3], g_w3t_lo[HID*KC3];
__device__ bf16 g_w4t_hi[HID*HID], g_w4t_lo[HID*HID];
__device__ int   g_ei[2*NE];
__device__ float g_P[NN*HID];
__device__ float g_Q[NN*HID];
__device__ bf16  g_h_hi[(size_t)NE*HID], g_h_lo[(size_t)NE*HID];
__device__ float g_agg[NN*HID];
__device__ bf16  g_agg_hi[NN*HID], g_agg_lo[NN*HID];
__device__ bf16  g_u_hi[NN*HID],   g_u_lo[NN*HID];
__device__ float g_y[NN*HID];

// ---------------- helpers ----------------
__device__ __forceinline__ float mishf(float x){
    float t   = __expf(fminf(x, 15.f));
    float num = t * (t + 2.f);
    return x * __fdividef(num, num + 2.f);
}
__device__ __forceinline__ unsigned smem_u32(const void* p){
    return (unsigned)__cvta_generic_to_shared(p);
}
__device__ __forceinline__ void ldsm_x4(unsigned &r0, unsigned &r1, unsigned &r2, unsigned &r3, unsigned addr){
    asm volatile("ldmatrix.sync.aligned.m8n8.x4.shared.b16 {%0,%1,%2,%3}, [%4];"
                 : "=r"(r0), "=r"(r1), "=r"(r2), "=r"(r3) : "r"(addr));
}
__device__ __forceinline__ void mma_bf16(float* c, unsigned a0, unsigned a1, unsigned a2, unsigned a3,
                                         unsigned b0, unsigned b1){
    asm volatile("mma.sync.aligned.m16n8k16.row.col.f32.bf16.bf16.f32 "
                 "{%0,%1,%2,%3}, {%4,%5,%6,%7}, {%8,%9}, {%0,%1,%2,%3};"
                 : "+f"(c[0]), "+f"(c[1]), "+f"(c[2]), "+f"(c[3])
                 : "r"(a0), "r"(a1), "r"(a2), "r"(a3), "r"(b0), "r"(b1));
}
__device__ __forceinline__ void split1(float v, bf16 &h, bf16 &l){
    h = __float2bfloat16(v);
    l = __float2bfloat16(v - __bfloat162float(h));
}
__device__ __forceinline__ uint32_t pack2(bf16 a, bf16 b){
    __nv_bfloat162 p; p.x = a; p.y = b;
    return *(uint32_t*)&p;
}
__device__ __forceinline__ void cp16(uint32_t dst, const void* src){
    asm volatile("cp.async.cg.shared.global [%0], [%1], 16;" :: "r"(dst), "l"(src));
}
#define CP_COMMIT() asm volatile("cp.async.commit_group;" ::: "memory")
#define CP_WAIT1()  asm volatile("cp.async.wait_group 1;" ::: "memory")
#define CP_WAIT0()  asm volatile("cp.async.wait_group 0;" ::: "memory")

// ---------------- prep kernels ----------------
__global__ void k_decode_idx(const void* __restrict__ ei_raw){
    int i = blockIdx.x * blockDim.x + threadIdx.x;
    if (i >= 2*NE) return;
    const long long* p64 = (const long long*)ei_raw;
    bool is64 = true;
    #pragma unroll
    for (int j = 0; j < 4; j++){
        long long v = p64[j];
        if (v < 0 || v >= NN) is64 = false;
    }
    g_ei[i] = is64 ? (int)p64[i] : ((const int*)ei_raw)[i];
}
__global__ void k_split_x(const float* __restrict__ s){
    int i = blockIdx.x * blockDim.x + threadIdx.x;
    if (i < NN*HID){ bf16 h,l; split1(s[i],h,l); g_x_hi[i]=h; g_x_lo[i]=l; }
}
__global__ void k_split_ea(const float* __restrict__ s){
    int i = blockIdx.x * blockDim.x + threadIdx.x;
    if (i < NE*ED){ bf16 h,l; split1(s[i],h,l); g_ea_hi[i]=h; g_ea_lo[i]=l; }
}
__global__ void k_split_w(const float* __restrict__ W, int K, int sel){
    int i = blockIdx.x * blockDim.x + threadIdx.x;
    if (i >= K*HID) return;
    int k = i / HID, n = i % HID;
    bf16 h, l; split1(W[i], h, l);
    bf16 *hi, *lo;
    if      (sel == 1){ hi = g_w1a_hi; lo = g_w1a_lo; }
    else if (sel == 2){ hi = g_w1b_hi; lo = g_w1b_lo; }
    else if (sel == 3){ hi = g_w1c_hi; lo = g_w1c_lo; }
    else if (sel == 4){ hi = g_w2t_hi; lo = g_w2t_lo; }
    else if (sel == 5){ hi = g_w3t_hi; lo = g_w3t_lo; }
    else              { hi = g_w4t_hi; lo = g_w4t_lo; }
    hi[(size_t)n*K + k] = h;
    lo[(size_t)n*K + k] = l;
}
__global__ void k_zero_agg(){
    int i = blockIdx.x * blockDim.x + threadIdx.x;
    if (i < NN*HID) g_agg[i] = 0.f;
}
__global__ void k_split_agg(){
    int i = blockIdx.x * blockDim.x + threadIdx.x;
    if (i < NN*HID){ bf16 h,l; split1(g_agg[i],h,l); g_agg_hi[i]=h; g_agg_lo[i]=l; }
}

// ---------------- fused split-bf16 GEMM (cp.async double-buffered) ----------------
// MODE 5: P = x @ W1a            MODE 6: Q = x @ W1b
// MODE 1: h = mish(ea@W1c + P[src] + Q[dst] + b1) -> g_h hi/lo
// MODE 2: msg = mish(h @ W2 + b2); atomic scatter into agg[dst]
// MODE 3: u = mish([x|agg_split] @ W3 + b3) -> g_u hi/lo
// MODE 4: y = x + u @ W4 + b4
// Grid: (n-blocks, m-blocks)  — consecutive blocks share the A tile via L2.
template<int MODE>
__global__ __launch_bounds__(256, 2)
void gemm_kernel(const float* __restrict__ bias, const float* __restrict__ xres)
{
    constexpr int KTOT = (MODE==1) ? ED : (MODE==3) ? KC3 : HID;
    constexpr int NCK  = KTOT / BK;
    constexpr bool HAS_BIAS = (MODE != 5 && MODE != 6);

    extern __shared__ __align__(16) char smem_raw[];
    bf16* sm = (bf16*)smem_raw;
    __shared__ int sSrc[BM];
    __shared__ int sDst[BM];

    const int tid = threadIdx.x;
    const int n0  = blockIdx.x * BN;
    const int m0  = blockIdx.y * BM;

    if constexpr (MODE==1 || MODE==2){
        if (tid < BM){
            if (MODE == 1) sSrc[tid] = g_ei[m0 + tid];
            sDst[tid] = g_ei[NE + m0 + tid];
        }
    }

    const int wid = tid >> 5, lane = tid & 31;
    const int wm  = wid >> 1, wn = wid & 1;   // 4x2 warp grid, 32x32 per warp
    const int g   = lane >> 2, t = lane & 3;

    float acc[2][4][4];
    #pragma unroll
    for (int a = 0; a < 2; a++)
        #pragma unroll
        for (int b = 0; b < 4; b++)
            #pragma unroll
            for (int c = 0; c < 4; c++) acc[a][b][c] = 0.f;

    const bf16 *Wh, *Wl;
    if      constexpr (MODE==1){ Wh = g_w1c_hi; Wl = g_w1c_lo; }
    else if constexpr (MODE==2){ Wh = g_w2t_hi; Wl = g_w2t_lo; }
    else if constexpr (MODE==3){ Wh = g_w3t_hi; Wl = g_w3t_lo; }
    else if constexpr (MODE==4){ Wh = g_w4t_hi; Wl = g_w4t_lo; }
    else if constexpr (MODE==5){ Wh = g_w1a_hi; Wl = g_w1a_lo; }
    else                       { Wh = g_w1b_hi; Wl = g_w1b_lo; }

    auto load_chunk = [&](int kc, int st){
        const int k0 = kc * BK;
        bf16* stg = sm + st*STG;
        // A: 128 rows x 32 cols = 512 16B-chunks per hi/lo -> 2 per thread
        #pragma unroll
        for (int j = 0; j < 2; j++){
            int p = tid + j*256;
            int r = p >> 2, c = (p & 3) * 8;
            int k = k0 + c;
            const bf16 *ph, *pl;
            if constexpr (MODE==1){
                size_t o = (size_t)(m0 + r)*ED + k;
                ph = g_ea_hi + o; pl = g_ea_lo + o;
            } else if constexpr (MODE==2){
                size_t o = (size_t)(m0 + r)*HID + k;
                ph = g_h_hi + o; pl = g_h_lo + o;
            } else if constexpr (MODE==3){
                int node = min(m0 + r, NN-1);
                if (k < HID){ size_t o = (size_t)node*HID + k;       ph = g_x_hi + o;   pl = g_x_lo + o; }
                else        { size_t o = (size_t)node*HID + (k-HID); ph = g_agg_hi + o; pl = g_agg_lo + o; }
            } else if constexpr (MODE==4){
                int node = min(m0 + r, NN-1);
                size_t o = (size_t)node*HID + k;
                ph = g_u_hi + o; pl = g_u_lo + o;
            } else {
                int node = min(m0 + r, NN-1);
                size_t o = (size_t)node*HID + k;
                ph = g_x_hi + o; pl = g_x_lo + o;
            }
            cp16(smem_u32(stg + 0*ASZ + r*BKP + c), ph);
            cp16(smem_u32(stg + 1*ASZ + r*BKP + c), pl);
        }
        // B: 64 rows x 32 cols = 256 16B-chunks per hi/lo -> 1 per thread
        {
            int r = tid >> 2, c = (tid & 3) * 8;
            size_t o = (size_t)(n0 + r)*KTOT + k0 + c;
            cp16(smem_u32(stg + 2*ASZ + 0   + r*BKP + c), Wh + o);
            cp16(smem_u32(stg + 2*ASZ + BSZ + r*BKP + c), Wl + o);
        }
        CP_COMMIT();
    };

    load_chunk(0, 0);

    for (int kc = 0; kc < NCK; ++kc){
        const int st = kc & 1;
        if (kc + 1 < NCK){
            load_chunk(kc + 1, (kc + 1) & 1);
            CP_WAIT1();
        } else {
            CP_WAIT0();
        }
        __syncthreads();

        bf16* stg = sm + st*STG;
        bf16* sAh = stg;
        bf16* sAl = stg + ASZ;
        bf16* sBh = stg + 2*ASZ;
        bf16* sBl = stg + 2*ASZ + BSZ;

        #pragma unroll
        for (int ks = 0; ks < 2; ++ks){
            const int kk = ks * 16;
            unsigned af[2][2][4];
            #pragma unroll
            for (int mt = 0; mt < 2; ++mt){
                int row = wm*32 + mt*16 + (lane & 7) + ((lane >> 3) & 1) * 8;
                int col = kk + (lane >> 4) * 8;
                ldsm_x4(af[mt][0][0], af[mt][0][1], af[mt][0][2], af[mt][0][3],
                        smem_u32(sAh + row*BKP + col));
                ldsm_x4(af[mt][1][0], af[mt][1][1], af[mt][1][2], af[mt][1][3],
                        smem_u32(sAl + row*BKP + col));
            }
            unsigned bfm[4][2][2];
            #pragma unroll
            for (int np = 0; np < 2; ++np){
                int ntl = 2*np + (lane >> 4);
                int row = wn*32 + ntl*8 + (lane & 7);
                int col = kk + ((lane >> 3) & 1) * 8;
                unsigned r0, r1, r2, r3;
                ldsm_x4(r0, r1, r2, r3, smem_u32(sBh + row*BKP + col));
                bfm[2*np][0][0]=r0; bfm[2*np][0][1]=r1; bfm[2*np+1][0][0]=r2; bfm[2*np+1][0][1]=r3;
                ldsm_x4(r0, r1, r2, r3, smem_u32(sBl + row*BKP + col));
                bfm[2*np][1][0]=r0; bfm[2*np][1][1]=r1; bfm[2*np+1][1][0]=r2; bfm[2*np+1][1][1]=r3;
            }
            #pragma unroll
            for (int mt = 0; mt < 2; ++mt)
                #pragma unroll
                for (int nt = 0; nt < 4; ++nt){
                    mma_bf16(acc[mt][nt], af[mt][0][0], af[mt][0][1], af[mt][0][2], af[mt][0][3],
                             bfm[nt][0][0], bfm[nt][0][1]);
                    mma_bf16(acc[mt][nt], af[mt][0][0], af[mt][0][1], af[mt][0][2], af[mt][0][3],
                             bfm[nt][1][0], bfm[nt][1][1]);
                    mma_bf16(acc[mt][nt], af[mt][1][0], af[mt][1][1], af[mt][1][2], af[mt][1][3],
                             bfm[nt][0][0], bfm[nt][0][1]);
                }
        }
        __syncthreads();
    }

    // ---- epilogue ----
    #pragma unroll
    for (int mt = 0; mt < 2; ++mt){
        const int rl0 = wm*32 + mt*16 + g;
        const int rl1 = rl0 + 8;
        int s0 = 0, s1 = 0, d0 = 0, d1 = 0;
        if constexpr (MODE==1){ s0 = sSrc[rl0]; s1 = sSrc[rl1]; d0 = sDst[rl0]; d1 = sDst[rl1]; }
        if constexpr (MODE==2){ d0 = sDst[rl0]; d1 = sDst[rl1]; }
        #pragma unroll
        for (int nt = 0; nt < 4; ++nt){
            const int col = n0 + wn*32 + nt*8 + t*2;
            float bv0 = 0.f, bv1 = 0.f;
            if constexpr (HAS_BIAS){ bv0 = bias[col]; bv1 = bias[col+1]; }
            float v00 = acc[mt][nt][0] + bv0;
            float v01 = acc[mt][nt][1] + bv1;
            float v10 = acc[mt][nt][2] + bv0;
            float v11 = acc[mt][nt][3] + bv1;
            if constexpr (MODE==1){
                float2 p0 = *(const float2*)&g_P[(size_t)s0*HID + col];
                float2 q0 = *(const float2*)&g_Q[(size_t)d0*HID + col];
                float2 p1 = *(const float2*)&g_P[(size_t)s1*HID + col];
                float2 q1 = *(const float2*)&g_Q[(size_t)d1*HID + col];
                v00 = mishf(v00 + p0.x + q0.x);
                v01 = mishf(v01 + p0.y + q0.y);
                v10 = mishf(v10 + p1.x + q1.x);
                v11 = mishf(v11 + p1.y + q1.y);
                bf16 h00,l00,h01,l01,h10,l10,h11,l11;
                split1(v00,h00,l00); split1(v01,h01,l01);
                split1(v10,h10,l10); split1(v11,h11,l11);
                size_t o0 = (size_t)(m0+rl0)*HID + col;
                size_t o1 = (size_t)(m0+rl1)*HID + col;
                *(uint32_t*)&g_h_hi[o0] = pack2(h00,h01);
                *(uint32_t*)&g_h_lo[o0] = pack2(l00,l01);
                *(uint32_t*)&g_h_hi[o1] = pack2(h10,h11);
                *(uint32_t*)&g_h_lo[o1] = pack2(l10,l11);
            } else if constexpr (MODE==2){
                v00 = mishf(v00); v01 = mishf(v01); v10 = mishf(v10); v11 = mishf(v11);
                atomicAdd(&g_agg[(size_t)d0*HID + col],     v00);
                atomicAdd(&g_agg[(size_t)d0*HID + col + 1], v01);
                atomicAdd(&g_agg[(size_t)d1*HID + col],     v10);
                atomicAdd(&g_agg[(size_t)d1*HID + col + 1], v11);
            } else if constexpr (MODE==3){
                const int r0i = m0 + rl0, r1i = m0 + rl1;
                if (r0i < NN){
                    float a = mishf(v00), b = mishf(v01);
                    bf16 ha,la,hb,lb; split1(a,ha,la); split1(b,hb,lb);
                    size_t o = (size_t)r0i*HID + col;
                    *(uint32_t*)&g_u_hi[o] = pack2(ha,hb);
                    *(uint32_t*)&g_u_lo[o] = pack2(la,lb);
                }
                if (r1i < NN){
                    float a = mishf(v10), b = mishf(v11);
                    bf16 ha,la,hb,lb; split1(a,ha,la); split1(b,hb,lb);
                    size_t o = (size_t)r1i*HID + col;
                    *(uint32_t*)&g_u_hi[o] = pack2(ha,hb);
                    *(uint32_t*)&g_u_lo[o] = pack2(la,lb);
                }
            } else if constexpr (MODE==4){
                const int r0i = m0 + rl0, r1i = m0 + rl1;
                if (r0i < NN){
                    float2 xv = *(const float2*)&xres[(size_t)r0i*HID + col];
                    *(float2*)&g_y[(size_t)r0i*HID + col] = make_float2(v00 + xv.x, v01 + xv.y);
                }
                if (r1i < NN){
                    float2 xv = *(const float2*)&xres[(size_t)r1i*HID + col];
                    *(float2*)&g_y[(size_t)r1i*HID + col] = make_float2(v10 + xv.x, v11 + xv.y);
                }
            } else {
                float* dst = (MODE==5) ? g_P : g_Q;
                const int r0i = m0 + rl0, r1i = m0 + rl1;
                if (r0i < NN)
                    *(float2*)&dst[(size_t)r0i*HID + col] = make_float2(v00, v01);
                if (r1i < NN)
                    *(float2*)&dst[(size_t)r1i*HID + col] = make_float2(v10, v11);
            }
        }
    }
}

// ---------------- LayerNorm ----------------
__global__ __launch_bounds__(128)
void ln_kernel(const float* __restrict__ gamma, const float* __restrict__ beta,
               float* __restrict__ out)
{
    const int row = blockIdx.x, tid = threadIdx.x;
    float4 v = *((const float4*)(g_y + (size_t)row*HID) + tid);
    float s  = v.x + v.y + v.z + v.w;
    float ss = fmaf(v.x, v.x, fmaf(v.y, v.y, fmaf(v.z, v.z, v.w*v.w)));
    #pragma unroll
    for (int o = 16; o > 0; o >>= 1){
        s  += __shfl_xor_sync(0xffffffffu, s,  o);
        ss += __shfl_xor_sync(0xffffffffu, ss, o);
    }
    __shared__ float sh_s[4], sh_ss[4];
    if ((tid & 31) == 0){ sh_s[tid >> 5] = s; sh_ss[tid >> 5] = ss; }
    __syncthreads();
    s  = sh_s[0]  + sh_s[1]  + sh_s[2]  + sh_s[3];
    ss = sh_ss[0] + sh_ss[1] + sh_ss[2] + sh_ss[3];
    const float mu  = s * (1.f / HID);
    const float var = ss * (1.f / HID) - mu * mu;
    const float inv = rsqrtf(var + 1e-5f);
    float4 gm = ((const float4*)gamma)[tid];
    float4 bt = ((const float4*)beta)[tid];
    float4 o;
    o.x = (v.x - mu) * inv * gm.x + bt.x;
    o.y = (v.y - mu) * inv * gm.y + bt.y;
    o.z = (v.z - mu) * inv * gm.z + bt.z;
    o.w = (v.w - mu) * inv * gm.w + bt.w;
    *((float4*)(out + (size_t)row*HID) + tid) = o;
}

// ---------------- launch ----------------
extern "C" void kernel_launch(void* const* d_in, const int* in_sizes, int n_in,
                              void* d_out, int out_size)
{
    (void)in_sizes; (void)n_in; (void)out_size;
    const float* x     = (const float*)d_in[0];
    const void*  ei    = d_in[1];
    const float* ea    = (const float*)d_in[2];
    const float* W1    = (const float*)d_in[3];
    const float* b1    = (const float*)d_in[4];
    const float* W2    = (const float*)d_in[5];
    const float* b2    = (const float*)d_in[6];
    const float* W3    = (const float*)d_in[7];
    const float* b3    = (const float*)d_in[8];
    const float* W4    = (const float*)d_in[9];
    const float* b4    = (const float*)d_in[10];
    const float* gamma = (const float*)d_in[11];
    const float* beta  = (const float*)d_in[12];
    float* out = (float*)d_out;

    cudaFuncSetAttribute(gemm_kernel<1>, cudaFuncAttributeMaxDynamicSharedMemorySize, SMEM_BYTES);
    cudaFuncSetAttribute(gemm_kernel<2>, cudaFuncAttributeMaxDynamicSharedMemorySize, SMEM_BYTES);
    cudaFuncSetAttribute(gemm_kernel<3>, cudaFuncAttributeMaxDynamicSharedMemorySize, SMEM_BYTES);
    cudaFuncSetAttribute(gemm_kernel<4>, cudaFuncAttributeMaxDynamicSharedMemorySize, SMEM_BYTES);
    cudaFuncSetAttribute(gemm_kernel<5>, cudaFuncAttributeMaxDynamicSharedMemorySize, SMEM_BYTES);
    cudaFuncSetAttribute(gemm_kernel<6>, cudaFuncAttributeMaxDynamicSharedMemorySize, SMEM_BYTES);

    k_decode_idx<<<(2*NE + 255)/256, 256>>>(ei);
    k_split_x  <<<(NN*HID + 255)/256, 256>>>(x);
    k_split_ea <<<(NE*ED + 255)/256, 256>>>(ea);
    k_split_w  <<<(HID*HID + 255)/256, 256>>>(W1,             HID, 1);  // W1a
    k_split_w  <<<(HID*HID + 255)/256, 256>>>(W1 + HID*HID,   HID, 2);  // W1b
    k_split_w  <<<(ED*HID  + 255)/256, 256>>>(W1 + 2*HID*HID, ED,  3);  // W1c
    k_split_w  <<<(HID*HID + 255)/256, 256>>>(W2,             HID, 4);
    k_split_w  <<<(KC3*HID + 255)/256, 256>>>(W3,             KC3, 5);
    k_split_w  <<<(HID*HID + 255)/256, 256>>>(W4,             HID, 6);
    k_zero_agg <<<(NN*HID + 255)/256, 256>>>();

    dim3 gE(HID/BN, NE/BM);                  // (8, 2500): n fastest -> A L2 reuse
    dim3 gN(HID/BN, (NN + BM - 1)/BM);       // (8, 157)
    gemm_kernel<5><<<gN, 256, SMEM_BYTES>>>(nullptr, nullptr);   // P = x @ W1a
    gemm_kernel<6><<<gN, 256, SMEM_BYTES>>>(nullptr, nullptr);   // Q = x @ W1b
    gemm_kernel<1><<<gE, 256, SMEM_BYTES>>>(b1, nullptr);        // h (edge, K=64)
    gemm_kernel<2><<<gE, 256, SMEM_BYTES>>>(b2, nullptr);        // messages + scatter
    k_split_agg<<<(NN*HID + 255)/256, 256>>>();
    gemm_kernel<3><<<gN, 256, SMEM_BYTES>>>(b3, nullptr);        // u
    gemm_kernel<4><<<gN, 256, SMEM_BYTES>>>(b4, x);              // y = x + u@W4+b4
    ln_kernel<<<NN, 128>>>(gamma, beta, out);
}

// round 6
// speedup vs baseline: 2.2501x; 1.0103x over previous
#include <cuda_runtime.h>
#include <cuda_bf16.h>
#include <math.h>
#include <stdint.h>

using bf16 = __nv_bfloat16;

constexpr int NN  = 20000;      // nodes
constexpr int NE  = 320000;     // edges
constexpr int HID = 512;
constexpr int ED  = 64;
constexpr int KC3 = 2*HID;      // 1024

constexpr int BM = 128, BN = 64, BK = 32, PAD = 8, BKP = BK + PAD;

constexpr int ASZ = BM*BKP;
constexpr int BSZ = BN*BKP;
constexpr int STG = 2*ASZ + 2*BSZ;
constexpr int SMEM_BYTES = 2*STG*(int)sizeof(bf16);   // 61440

// ---------------- device scratch ----------------
__device__ bf16 g_x_hi[NN*HID],  g_x_lo[NN*HID];
__device__ bf16 g_ea_hi[NE*ED],  g_ea_lo[NE*ED];
__device__ bf16 g_w1a_hi[HID*HID], g_w1a_lo[HID*HID];
__device__ bf16 g_w1b_hi[HID*HID], g_w1b_lo[HID*HID];
__device__ bf16 g_w1c_hi[HID*ED],  g_w1c_lo[HID*ED];
__device__ bf16 g_w2t_hi[HID*HID], g_w2t_lo[HID*HID];
__device__ bf16 g_w3t_hi[HID*KC3], g_w3t_lo[HID*KC3];
__device__ bf16 g_w4t_hi[HID*HID], g_w4t_lo[HID*HID];
__device__ int   g_ei[2*NE];
__device__ float g_P[NN*HID];
__device__ float g_Q[NN*HID];
__device__ bf16  g_h_hi[(size_t)NE*HID], g_h_lo[(size_t)NE*HID];
__device__ float g_agg[NN*HID];
__device__ bf16  g_agg_hi[NN*HID], g_agg_lo[NN*HID];
__device__ bf16  g_u_hi[NN*HID],   g_u_lo[NN*HID];
__device__ float g_y[NN*HID];

// ---------------- helpers ----------------
__device__ __forceinline__ float mishf(float x){
    float t   = __expf(fminf(x, 15.f));
    float num = t * (t + 2.f);
    return x * __fdividef(num, num + 2.f);
}
__device__ __forceinline__ unsigned smem_u32(const void* p){
    return (unsigned)__cvta_generic_to_shared(p);
}
__device__ __forceinline__ void ldsm_x4(unsigned &r0, unsigned &r1, unsigned &r2, unsigned &r3, unsigned addr){
    asm volatile("ldmatrix.sync.aligned.m8n8.x4.shared.b16 {%0,%1,%2,%3}, [%4];"
                 : "=r"(r0), "=r"(r1), "=r"(r2), "=r"(r3) : "r"(addr));
}
__device__ __forceinline__ void mma_bf16(float* c, unsigned a0, unsigned a1, unsigned a2, unsigned a3,
                                         unsigned b0, unsigned b1){
    asm volatile("mma.sync.aligned.m16n8k16.row.col.f32.bf16.bf16.f32 "
                 "{%0,%1,%2,%3}, {%4,%5,%6,%7}, {%8,%9}, {%0,%1,%2,%3};"
                 : "+f"(c[0]), "+f"(c[1]), "+f"(c[2]), "+f"(c[3])
                 : "r"(a0), "r"(a1), "r"(a2), "r"(a3), "r"(b0), "r"(b1));
}
__device__ __forceinline__ void split1(float v, bf16 &h, bf16 &l){
    h = __float2bfloat16(v);
    l = __float2bfloat16(v - __bfloat162float(h));
}
__device__ __forceinline__ uint32_t pack2(bf16 a, bf16 b){
    __nv_bfloat162 p; p.x = a; p.y = b;
    return *(uint32_t*)&p;
}
__device__ __forceinline__ void cp16(uint32_t dst, const void* src){
    asm volatile("cp.async.cg.shared.global [%0], [%1], 16;" :: "r"(dst), "l"(src));
}
#define CP_COMMIT() asm volatile("cp.async.commit_group;" ::: "memory")
#define CP_WAIT1()  asm volatile("cp.async.wait_group 1;" ::: "memory")
#define CP_WAIT0()  asm volatile("cp.async.wait_group 0;" ::: "memory")

// ---------------- prep kernels (fused) ----------------
constexpr int NX   = NN*HID;                 // 10,240,000
constexpr int NW1A = HID*HID;                // 262,144
constexpr int NW1B = HID*HID;
constexpr int NW1C = ED*HID;                 // 32,768
constexpr int NW2  = HID*HID;
constexpr int NW3  = KC3*HID;                // 524,288
constexpr int NW4  = HID*HID;
constexpr int SPLIT_ALL_TOT = NX + NW1A + NW1B + NW1C + NW2 + NW3 + NW4;

__global__ void k_split_all(const float* __restrict__ x,
                            const float* __restrict__ W1,
                            const float* __restrict__ W2,
                            const float* __restrict__ W3,
                            const float* __restrict__ W4){
    int i = blockIdx.x * blockDim.x + threadIdx.x;
    if (i >= SPLIT_ALL_TOT) return;
    if (i < NX){
        bf16 h,l; split1(x[i],h,l); g_x_hi[i]=h; g_x_lo[i]=l;
        return;
    }
    i -= NX;
    const float* src; bf16 *hi, *lo; int K;
    if      (i < NW1A){                              src = W1;                     hi=g_w1a_hi; lo=g_w1a_lo; K=HID; }
    else if ((i -= NW1A) < NW1B){                    src = W1 + (size_t)HID*HID;   hi=g_w1b_hi; lo=g_w1b_lo; K=HID; }
    else if ((i -= NW1B) < NW1C){                    src = W1 + (size_t)2*HID*HID; hi=g_w1c_hi; lo=g_w1c_lo; K=ED; }
    else if ((i -= NW1C) < NW2){                     src = W2;                     hi=g_w2t_hi; lo=g_w2t_lo; K=HID; }
    else if ((i -= NW2)  < NW3){                     src = W3;                     hi=g_w3t_hi; lo=g_w3t_lo; K=KC3; }
    else { i -= NW3;                                 src = W4;                     hi=g_w4t_hi; lo=g_w4t_lo; K=HID; }
    int k = i / HID, n = i % HID;
    bf16 h, l; split1(src[i], h, l);
    hi[(size_t)n*K + k] = h;
    lo[(size_t)n*K + k] = l;
}
__global__ void k_split_ea(const float* __restrict__ s){
    int i = blockIdx.x * blockDim.x + threadIdx.x;
    if (i < NE*ED){ bf16 h,l; split1(s[i],h,l); g_ea_hi[i]=h; g_ea_lo[i]=l; }
}
// decode edge_index (int64 vs int32 defensive) + zero agg in one kernel
__global__ void k_decode_zero(const void* __restrict__ ei_raw){
    int i = blockIdx.x * blockDim.x + threadIdx.x;
    if (i < 2*NE){
        const long long* p64 = (const long long*)ei_raw;
        bool is64 = true;
        #pragma unroll
        for (int j = 0; j < 4; j++){
            long long v = p64[j];
            if (v < 0 || v >= NN) is64 = false;
        }
        g_ei[i] = is64 ? (int)p64[i] : ((const int*)ei_raw)[i];
    }
    if (i < NN*HID) g_agg[i] = 0.f;
}
__global__ void k_split_agg(){
    int i = blockIdx.x * blockDim.x + threadIdx.x;
    if (i < NN*HID){ bf16 h,l; split1(g_agg[i],h,l); g_agg_hi[i]=h; g_agg_lo[i]=l; }
}

// ---------------- fused split-bf16 GEMM (cp.async double-buffered) ----------------
// MODE 7: [P|Q] = x @ [W1a|W1b]  (merged, N=1024)
// MODE 1: h = mish(ea@W1c + P[src] + Q[dst] + b1) -> g_h hi/lo
// MODE 2: msg = mish(h @ W2 + b2); float4 RED scatter into agg[dst]
// MODE 3: u = mish([x|agg_split] @ W3 + b3) -> g_u hi/lo
// MODE 4: y = x + u @ W4 + b4
// Grid: (n-blocks, m-blocks) — n fastest for A-tile L2 reuse.
template<int MODE>
__global__ __launch_bounds__(256, 2)
void gemm_kernel(const float* __restrict__ bias, const float* __restrict__ xres)
{
    constexpr int KTOT = (MODE==1) ? ED : (MODE==3) ? KC3 : HID;
    constexpr int NCK  = KTOT / BK;
    constexpr bool HAS_BIAS = (MODE != 7);

    extern __shared__ __align__(16) char smem_raw[];
    bf16* sm = (bf16*)smem_raw;
    __shared__ int sSrc[BM];
    __shared__ int sDst[BM];

    const int tid = threadIdx.x;
    const int n0  = blockIdx.x * BN;
    const int m0  = blockIdx.y * BM;

    if constexpr (MODE==1 || MODE==2){
        if (tid < BM){
            if (MODE == 1) sSrc[tid] = g_ei[m0 + tid];
            sDst[tid] = g_ei[NE + m0 + tid];
        }
    }

    const int wid = tid >> 5, lane = tid & 31;
    const int wm  = wid >> 1, wn = wid & 1;   // 4x2 warp grid, 32x32 per warp
    const int g   = lane >> 2, t = lane & 3;

    float acc[2][4][4];
    #pragma unroll
    for (int a = 0; a < 2; a++)
        #pragma unroll
        for (int b = 0; b < 4; b++)
            #pragma unroll
            for (int c = 0; c < 4; c++) acc[a][b][c] = 0.f;

    const bf16 *Wh, *Wl;
    if      constexpr (MODE==1){ Wh = g_w1c_hi; Wl = g_w1c_lo; }
    else if constexpr (MODE==2){ Wh = g_w2t_hi; Wl = g_w2t_lo; }
    else if constexpr (MODE==3){ Wh = g_w3t_hi; Wl = g_w3t_lo; }
    else if constexpr (MODE==4){ Wh = g_w4t_hi; Wl = g_w4t_lo; }
    else { // MODE 7: first 8 n-blocks -> W1a/P, next 8 -> W1b/Q
        if (n0 < HID){ Wh = g_w1a_hi; Wl = g_w1a_lo; }
        else         { Wh = g_w1b_hi; Wl = g_w1b_lo; }
    }
    const int nW = (MODE==7 && n0 >= HID) ? (n0 - HID) : n0;

    auto load_chunk = [&](int kc, int st){
        const int k0 = kc * BK;
        bf16* stg = sm + st*STG;
        #pragma unroll
        for (int j = 0; j < 2; j++){
            int p = tid + j*256;
            int r = p >> 2, c = (p & 3) * 8;
            int k = k0 + c;
            const bf16 *ph, *pl;
            if constexpr (MODE==1){
                size_t o = (size_t)(m0 + r)*ED + k;
                ph = g_ea_hi + o; pl = g_ea_lo + o;
            } else if constexpr (MODE==2){
                size_t o = (size_t)(m0 + r)*HID + k;
                ph = g_h_hi + o; pl = g_h_lo + o;
            } else if constexpr (MODE==3){
                int node = min(m0 + r, NN-1);
                if (k < HID){ size_t o = (size_t)node*HID + k;       ph = g_x_hi + o;   pl = g_x_lo + o; }
                else        { size_t o = (size_t)node*HID + (k-HID); ph = g_agg_hi + o; pl = g_agg_lo + o; }
            } else if constexpr (MODE==4){
                int node = min(m0 + r, NN-1);
                size_t o = (size_t)node*HID + k;
                ph = g_u_hi + o; pl = g_u_lo + o;
            } else {
                int node = min(m0 + r, NN-1);
                size_t o = (size_t)node*HID + k;
                ph = g_x_hi + o; pl = g_x_lo + o;
            }
            cp16(smem_u32(stg + 0*ASZ + r*BKP + c), ph);
            cp16(smem_u32(stg + 1*ASZ + r*BKP + c), pl);
        }
        {
            int r = tid >> 2, c = (tid & 3) * 8;
            size_t o = (size_t)(nW + r)*KTOT + k0 + c;
            cp16(smem_u32(stg + 2*ASZ + 0   + r*BKP + c), Wh + o);
            cp16(smem_u32(stg + 2*ASZ + BSZ + r*BKP + c), Wl + o);
        }
        CP_COMMIT();
    };

    load_chunk(0, 0);

    for (int kc = 0; kc < NCK; ++kc){
        const int st = kc & 1;
        if (kc + 1 < NCK){
            load_chunk(kc + 1, (kc + 1) & 1);
            CP_WAIT1();
        } else {
            CP_WAIT0();
        }
        __syncthreads();

        bf16* stg = sm + st*STG;
        bf16* sAh = stg;
        bf16* sAl = stg + ASZ;
        bf16* sBh = stg + 2*ASZ;
        bf16* sBl = stg + 2*ASZ + BSZ;

        #pragma unroll
        for (int ks = 0; ks < 2; ++ks){
            const int kk = ks * 16;
            unsigned af[2][2][4];
            #pragma unroll
            for (int mt = 0; mt < 2; ++mt){
                int row = wm*32 + mt*16 + (lane & 7) + ((lane >> 3) & 1) * 8;
                int col = kk + (lane >> 4) * 8;
                ldsm_x4(af[mt][0][0], af[mt][0][1], af[mt][0][2], af[mt][0][3],
                        smem_u32(sAh + row*BKP + col));
                ldsm_x4(af[mt][1][0], af[mt][1][1], af[mt][1][2], af[mt][1][3],
                        smem_u32(sAl + row*BKP + col));
            }
            unsigned bfm[4][2][2];
            #pragma unroll
            for (int np = 0; np < 2; ++np){
                int ntl = 2*np + (lane >> 4);
                int row = wn*32 + ntl*8 + (lane & 7);
                int col = kk + ((lane >> 3) & 1) * 8;
                unsigned r0, r1, r2, r3;
                ldsm_x4(r0, r1, r2, r3, smem_u32(sBh + row*BKP + col));
                bfm[2*np][0][0]=r0; bfm[2*np][0][1]=r1; bfm[2*np+1][0][0]=r2; bfm[2*np+1][0][1]=r3;
                ldsm_x4(r0, r1, r2, r3, smem_u32(sBl + row*BKP + col));
                bfm[2*np][1][0]=r0; bfm[2*np][1][1]=r1; bfm[2*np+1][1][0]=r2; bfm[2*np+1][1][1]=r3;
            }
            #pragma unroll
            for (int mt = 0; mt < 2; ++mt)
                #pragma unroll
                for (int nt = 0; nt < 4; ++nt){
                    mma_bf16(acc[mt][nt], af[mt][0][0], af[mt][0][1], af[mt][0][2], af[mt][0][3],
                             bfm[nt][0][0], bfm[nt][0][1]);
                    mma_bf16(acc[mt][nt], af[mt][0][0], af[mt][0][1], af[mt][0][2], af[mt][0][3],
                             bfm[nt][1][0], bfm[nt][1][1]);
                    mma_bf16(acc[mt][nt], af[mt][1][0], af[mt][1][1], af[mt][1][2], af[mt][1][3],
                             bfm[nt][0][0], bfm[nt][0][1]);
                }
        }
        __syncthreads();
    }

    // ---- epilogue ----
    #pragma unroll
    for (int mt = 0; mt < 2; ++mt){
        const int rl0 = wm*32 + mt*16 + g;
        const int rl1 = rl0 + 8;
        int s0 = 0, s1 = 0, d0 = 0, d1 = 0;
        if constexpr (MODE==1){ s0 = sSrc[rl0]; s1 = sSrc[rl1]; d0 = sDst[rl0]; d1 = sDst[rl1]; }
        if constexpr (MODE==2){ d0 = sDst[rl0]; d1 = sDst[rl1]; }
        #pragma unroll
        for (int nt = 0; nt < 4; ++nt){
            const int col = n0 + wn*32 + nt*8 + t*2;
            float bv0 = 0.f, bv1 = 0.f;
            if constexpr (HAS_BIAS){ bv0 = bias[col]; bv1 = bias[col+1]; }
            float v00 = acc[mt][nt][0] + bv0;
            float v01 = acc[mt][nt][1] + bv1;
            float v10 = acc[mt][nt][2] + bv0;
            float v11 = acc[mt][nt][3] + bv1;
            if constexpr (MODE==1){
                float2 p0 = *(const float2*)&g_P[(size_t)s0*HID + col];
                float2 q0 = *(const float2*)&g_Q[(size_t)d0*HID + col];
                float2 p1 = *(const float2*)&g_P[(size_t)s1*HID + col];
                float2 q1 = *(const float2*)&g_Q[(size_t)d1*HID + col];
                v00 = mishf(v00 + p0.x + q0.x);
                v01 = mishf(v01 + p0.y + q0.y);
                v10 = mishf(v10 + p1.x + q1.x);
                v11 = mishf(v11 + p1.y + q1.y);
                bf16 h00,l00,h01,l01,h10,l10,h11,l11;
                split1(v00,h00,l00); split1(v01,h01,l01);
                split1(v10,h10,l10); split1(v11,h11,l11);
                size_t o0 = (size_t)(m0+rl0)*HID + col;
                size_t o1 = (size_t)(m0+rl1)*HID + col;
                *(uint32_t*)&g_h_hi[o0] = pack2(h00,h01);
                *(uint32_t*)&g_h_lo[o0] = pack2(l00,l01);
                *(uint32_t*)&g_h_hi[o1] = pack2(h10,h11);
                *(uint32_t*)&g_h_lo[o1] = pack2(l10,l11);
            } else if constexpr (MODE==2){
                v00 = mishf(v00); v01 = mishf(v01); v10 = mishf(v10); v11 = mishf(v11);
                // pair lanes t<->t^1: even t issues one float4 RED covering 4 cols
                float p00 = __shfl_xor_sync(0xffffffffu, v00, 1);
                float p01 = __shfl_xor_sync(0xffffffffu, v01, 1);
                float p10 = __shfl_xor_sync(0xffffffffu, v10, 1);
                float p11 = __shfl_xor_sync(0xffffffffu, v11, 1);
                if ((t & 1) == 0){
                    atomicAdd((float4*)&g_agg[(size_t)d0*HID + col], make_float4(v00, v01, p00, p01));
                    atomicAdd((float4*)&g_agg[(size_t)d1*HID + col], make_float4(v10, v11, p10, p11));
                }
            } else if constexpr (MODE==3){
                const int r0i = m0 + rl0, r1i = m0 + rl1;
                if (r0i < NN){
                    float a = mishf(v00), b = mishf(v01);
                    bf16 ha,la,hb,lb; split1(a,ha,la); split1(b,hb,lb);
                    size_t o = (size_t)r0i*HID + col;
                    *(uint32_t*)&g_u_hi[o] = pack2(ha,hb);
                    *(uint32_t*)&g_u_lo[o] = pack2(la,lb);
                }
                if (r1i < NN){
                    float a = mishf(v10), b = mishf(v11);
                    bf16 ha,la,hb,lb; split1(a,ha,la); split1(b,hb,lb);
                    size_t o = (size_t)r1i*HID + col;
                    *(uint32_t*)&g_u_hi[o] = pack2(ha,hb);
                    *(uint32_t*)&g_u_lo[o] = pack2(la,lb);
                }
            } else if constexpr (MODE==4){
                const int r0i = m0 + rl0, r1i = m0 + rl1;
                if (r0i < NN){
                    float2 xv = *(const float2*)&xres[(size_t)r0i*HID + col];
                    *(float2*)&g_y[(size_t)r0i*HID + col] = make_float2(v00 + xv.x, v01 + xv.y);
                }
                if (r1i < NN){
                    float2 xv = *(const float2*)&xres[(size_t)r1i*HID + col];
                    *(float2*)&g_y[(size_t)r1i*HID + col] = make_float2(v10 + xv.x, v11 + xv.y);
                }
            } else { // MODE 7
                float* dst = (n0 < HID) ? g_P : g_Q;
                const int cw = nW + wn*32 + nt*8 + t*2;
                const int r0i = m0 + rl0, r1i = m0 + rl1;
                if (r0i < NN)
                    *(float2*)&dst[(size_t)r0i*HID + cw] = make_float2(v00, v01);
                if (r1i < NN)
                    *(float2*)&dst[(size_t)r1i*HID + cw] = make_float2(v10, v11);
            }
        }
    }
}

// ---------------- LayerNorm ----------------
__global__ __launch_bounds__(128)
void ln_kernel(const float* __restrict__ gamma, const float* __restrict__ beta,
               float* __restrict__ out)
{
    const int row = blockIdx.x, tid = threadIdx.x;
    float4 v = *((const float4*)(g_y + (size_t)row*HID) + tid);
    float s  = v.x + v.y + v.z + v.w;
    float ss = fmaf(v.x, v.x, fmaf(v.y, v.y, fmaf(v.z, v.z, v.w*v.w)));
    #pragma unroll
    for (int o = 16; o > 0; o >>= 1){
        s  += __shfl_xor_sync(0xffffffffu, s,  o);
        ss += __shfl_xor_sync(0xffffffffu, ss, o);
    }
    __shared__ float sh_s[4], sh_ss[4];
    if ((tid & 31) == 0){ sh_s[tid >> 5] = s; sh_ss[tid >> 5] = ss; }
    __syncthreads();
    s  = sh_s[0]  + sh_s[1]  + sh_s[2]  + sh_s[3];
    ss = sh_ss[0] + sh_ss[1] + sh_ss[2] + sh_ss[3];
    const float mu  = s * (1.f / HID);
    const float var = ss * (1.f / HID) - mu * mu;
    const float inv = rsqrtf(var + 1e-5f);
    float4 gm = ((const float4*)gamma)[tid];
    float4 bt = ((const float4*)beta)[tid];
    float4 o;
    o.x = (v.x - mu) * inv * gm.x + bt.x;
    o.y = (v.y - mu) * inv * gm.y + bt.y;
    o.z = (v.z - mu) * inv * gm.z + bt.z;
    o.w = (v.w - mu) * inv * gm.w + bt.w;
    *((float4*)(out + (size_t)row*HID) + tid) = o;
}

// ---------------- launch ----------------
extern "C" void kernel_launch(void* const* d_in, const int* in_sizes, int n_in,
                              void* d_out, int out_size)
{
    (void)in_sizes; (void)n_in; (void)out_size;
    const float* x     = (const float*)d_in[0];
    const void*  ei    = d_in[1];
    const float* ea    = (const float*)d_in[2];
    const float* W1    = (const float*)d_in[3];
    const float* b1    = (const float*)d_in[4];
    const float* W2    = (const float*)d_in[5];
    const float* b2    = (const float*)d_in[6];
    const float* W3    = (const float*)d_in[7];
    const float* b3    = (const float*)d_in[8];
    const float* W4    = (const float*)d_in[9];
    const float* b4    = (const float*)d_in[10];
    const float* gamma = (const float*)d_in[11];
    const float* beta  = (const float*)d_in[12];
    float* out = (float*)d_out;

    cudaFuncSetAttribute(gemm_kernel<1>, cudaFuncAttributeMaxDynamicSharedMemorySize, SMEM_BYTES);
    cudaFuncSetAttribute(gemm_kernel<2>, cudaFuncAttributeMaxDynamicSharedMemorySize, SMEM_BYTES);
    cudaFuncSetAttribute(gemm_kernel<3>, cudaFuncAttributeMaxDynamicSharedMemorySize, SMEM_BYTES);
    cudaFuncSetAttribute(gemm_kernel<4>, cudaFuncAttributeMaxDynamicSharedMemorySize, SMEM_BYTES);
    cudaFuncSetAttribute(gemm_kernel<7>, cudaFuncAttributeMaxDynamicSharedMemorySize, SMEM_BYTES);

    // Launch order tuned so ncu (-s 5 -c 1) captures launch #6 = MODE 2 (dominant).
    k_split_all  <<<(SPLIT_ALL_TOT + 255)/256, 256>>>(x, W1, W2, W3, W4);   // 1
    k_split_ea   <<<(NE*ED + 255)/256, 256>>>(ea);                          // 2
    k_decode_zero<<<(NN*HID + 255)/256, 256>>>(ei);                         // 3

    dim3 gPQ(2*HID/BN, (NN + BM - 1)/BM);    // (16, 157)
    dim3 gE(HID/BN, NE/BM);                  // (8, 2500)
    dim3 gN(HID/BN, (NN + BM - 1)/BM);       // (8, 157)
    gemm_kernel<7><<<gPQ, 256, SMEM_BYTES>>>(nullptr, nullptr);  // 4: P|Q
    gemm_kernel<1><<<gE, 256, SMEM_BYTES>>>(b1, nullptr);        // 5: h
    gemm_kernel<2><<<gE, 256, SMEM_BYTES>>>(b2, nullptr);        // 6: messages+scatter  <- ncu
    k_split_agg  <<<(NN*HID + 255)/256, 256>>>();                // 7
    gemm_kernel<3><<<gN, 256, SMEM_BYTES>>>(b3, nullptr);        // 8: u
    gemm_kernel<4><<<gN, 256, SMEM_BYTES>>>(b4, x);              // 9: y
    ln_kernel<<<NN, 128>>>(gamma, beta, out);                    // 10
}

// round 7
// speedup vs baseline: 2.2574x; 1.0033x over previous
#include <cuda_runtime.h>
#include <cuda_bf16.h>
#include <math.h>
#include <stdint.h>

using bf16 = __nv_bfloat16;

constexpr int NN  = 20000;      // nodes
constexpr int NE  = 320000;     // edges
constexpr int HID = 512;
constexpr int ED  = 64;
constexpr int KC3 = 2*HID;      // 1024

constexpr int BM = 128, BN = 64, BK = 32, PAD = 8, BKP = BK + PAD;

constexpr int ASZ = BM*BKP;
constexpr int BSZ = BN*BKP;
constexpr int STG = 2*ASZ + 2*BSZ;
constexpr int SMEM_BYTES = 2*STG*(int)sizeof(bf16);   // 61440

// ---------------- device scratch ----------------
__device__ bf16 g_x_hi[NN*HID],  g_x_lo[NN*HID];
__device__ bf16 g_ea_hi[NE*ED],  g_ea_lo[NE*ED];
__device__ bf16 g_w1a_hi[HID*HID], g_w1a_lo[HID*HID];
__device__ bf16 g_w1b_hi[HID*HID], g_w1b_lo[HID*HID];
__device__ bf16 g_w1c_hi[HID*ED],  g_w1c_lo[HID*ED];
__device__ bf16 g_w2t_hi[HID*HID], g_w2t_lo[HID*HID];
__device__ bf16 g_w3t_hi[HID*KC3], g_w3t_lo[HID*KC3];
__device__ bf16 g_w4t_hi[HID*HID], g_w4t_lo[HID*HID];
__device__ int   g_ei[2*NE];
__device__ float g_P[NN*HID];
__device__ float g_Q[NN*HID];
__device__ bf16  g_h_hi[(size_t)NE*HID], g_h_lo[(size_t)NE*HID];
__device__ float g_agg[NN*HID];
__device__ bf16  g_agg_hi[NN*HID], g_agg_lo[NN*HID];
__device__ bf16  g_u_hi[NN*HID],   g_u_lo[NN*HID];
__device__ float g_y[NN*HID];

// ---------------- helpers ----------------
__device__ __forceinline__ float mishf(float x){
    float t   = __expf(fminf(x, 15.f));
    float num = t * (t + 2.f);
    return x * __fdividef(num, num + 2.f);
}
__device__ __forceinline__ unsigned smem_u32(const void* p){
    return (unsigned)__cvta_generic_to_shared(p);
}
__device__ __forceinline__ void ldsm_x4(unsigned &r0, unsigned &r1, unsigned &r2, unsigned &r3, unsigned addr){
    asm volatile("ldmatrix.sync.aligned.m8n8.x4.shared.b16 {%0,%1,%2,%3}, [%4];"
                 : "=r"(r0), "=r"(r1), "=r"(r2), "=r"(r3) : "r"(addr));
}
__device__ __forceinline__ void mma_bf16(float* c, unsigned a0, unsigned a1, unsigned a2, unsigned a3,
                                         unsigned b0, unsigned b1){
    asm volatile("mma.sync.aligned.m16n8k16.row.col.f32.bf16.bf16.f32 "
                 "{%0,%1,%2,%3}, {%4,%5,%6,%7}, {%8,%9}, {%0,%1,%2,%3};"
                 : "+f"(c[0]), "+f"(c[1]), "+f"(c[2]), "+f"(c[3])
                 : "r"(a0), "r"(a1), "r"(a2), "r"(a3), "r"(b0), "r"(b1));
}
__device__ __forceinline__ void split1(float v, bf16 &h, bf16 &l){
    h = __float2bfloat16(v);
    l = __float2bfloat16(v - __bfloat162float(h));
}
__device__ __forceinline__ uint32_t pack2(bf16 a, bf16 b){
    __nv_bfloat162 p; p.x = a; p.y = b;
    return *(uint32_t*)&p;
}
__device__ __forceinline__ void cp16(uint32_t dst, const void* src){
    asm volatile("cp.async.cg.shared.global [%0], [%1], 16;" :: "r"(dst), "l"(src));
}
#define CP_COMMIT() asm volatile("cp.async.commit_group;" ::: "memory")
#define CP_WAIT1()  asm volatile("cp.async.wait_group 1;" ::: "memory")
#define CP_WAIT0()  asm volatile("cp.async.wait_group 0;" ::: "memory")

// ---------------- prep kernels (fused) ----------------
constexpr int NX   = NN*HID;                 // 10,240,000
constexpr int NW1A = HID*HID;                // 262,144
constexpr int NW1B = HID*HID;
constexpr int NW1C = ED*HID;                 // 32,768
constexpr int NW2  = HID*HID;
constexpr int NW3  = KC3*HID;                // 524,288
constexpr int NW4  = HID*HID;
constexpr int SPLIT_ALL_TOT = NX + NW1A + NW1B + NW1C + NW2 + NW3 + NW4;

__global__ void k_split_all(const float* __restrict__ x,
                            const float* __restrict__ W1,
                            const float* __restrict__ W2,
                            const float* __restrict__ W3,
                            const float* __restrict__ W4){
    int i = blockIdx.x * blockDim.x + threadIdx.x;
    if (i >= SPLIT_ALL_TOT) return;
    if (i < NX){
        bf16 h,l; split1(x[i],h,l); g_x_hi[i]=h; g_x_lo[i]=l;
        return;
    }
    i -= NX;
    const float* src; bf16 *hi, *lo; int K;
    if      (i < NW1A){                              src = W1;                     hi=g_w1a_hi; lo=g_w1a_lo; K=HID; }
    else if ((i -= NW1A) < NW1B){                    src = W1 + (size_t)HID*HID;   hi=g_w1b_hi; lo=g_w1b_lo; K=HID; }
    else if ((i -= NW1B) < NW1C){                    src = W1 + (size_t)2*HID*HID; hi=g_w1c_hi; lo=g_w1c_lo; K=ED; }
    else if ((i -= NW1C) < NW2){                     src = W2;                     hi=g_w2t_hi; lo=g_w2t_lo; K=HID; }
    else if ((i -= NW2)  < NW3){                     src = W3;                     hi=g_w3t_hi; lo=g_w3t_lo; K=KC3; }
    else { i -= NW3;                                 src = W4;                     hi=g_w4t_hi; lo=g_w4t_lo; K=HID; }
    int k = i / HID, n = i % HID;
    bf16 h, l; split1(src[i], h, l);
    hi[(size_t)n*K + k] = h;
    lo[(size_t)n*K + k] = l;
}
__global__ void k_split_ea(const float* __restrict__ s){
    int i = blockIdx.x * blockDim.x + threadIdx.x;
    if (i < NE*ED){ bf16 h,l; split1(s[i],h,l); g_ea_hi[i]=h; g_ea_lo[i]=l; }
}
// decode edge_index (int64 vs int32 defensive) + zero agg in one kernel
__global__ void k_decode_zero(const void* __restrict__ ei_raw){
    int i = blockIdx.x * blockDim.x + threadIdx.x;
    if (i < 2*NE){
        const long long* p64 = (const long long*)ei_raw;
        bool is64 = true;
        #pragma unroll
        for (int j = 0; j < 4; j++){
            long long v = p64[j];
            if (v < 0 || v >= NN) is64 = false;
        }
        g_ei[i] = is64 ? (int)p64[i] : ((const int*)ei_raw)[i];
    }
    if (i < NN*HID) g_agg[i] = 0.f;
}
__global__ void k_split_agg(){
    int i = blockIdx.x * blockDim.x + threadIdx.x;
    if (i < NN*HID){ bf16 h,l; split1(g_agg[i],h,l); g_agg_hi[i]=h; g_agg_lo[i]=l; }
}

// ---------------- fused split-bf16 GEMM (cp.async double-buffered) ----------------
// MODE 7: [P|Q] = x @ [W1a|W1b]  (merged, N=1024)
// MODE 1: h = mish(ea@W1c + P[src] + Q[dst] + b1) -> g_h hi/lo
// MODE 2: msg = mish(h @ W2 + b2); float4 RED scatter into agg[dst]
// MODE 3: u = mish([x|agg_split] @ W3 + b3) -> g_u hi/lo
// MODE 4: y = x + u @ W4 + b4
// Grid: (n-blocks, m-blocks) — n fastest for A-tile L2 reuse.
template<int MODE>
__global__ __launch_bounds__(256, 2)
void gemm_kernel(const float* __restrict__ bias, const float* __restrict__ xres)
{
    constexpr int KTOT = (MODE==1) ? ED : (MODE==3) ? KC3 : HID;
    constexpr int NCK  = KTOT / BK;
    constexpr bool HAS_BIAS = (MODE != 7);

    extern __shared__ __align__(16) char smem_raw[];
    bf16* sm = (bf16*)smem_raw;
    __shared__ int sSrc[BM];
    __shared__ int sDst[BM];

    const int tid = threadIdx.x;
    const int n0  = blockIdx.x * BN;
    const int m0  = blockIdx.y * BM;

    if constexpr (MODE==1 || MODE==2){
        if (tid < BM){
            if (MODE == 1) sSrc[tid] = g_ei[m0 + tid];
            sDst[tid] = g_ei[NE + m0 + tid];
        }
    }

    const int wid = tid >> 5, lane = tid & 31;
    const int wm  = wid >> 1, wn = wid & 1;   // 4x2 warp grid, 32x32 per warp
    const int g   = lane >> 2, t = lane & 3;

    float acc[2][4][4];
    #pragma unroll
    for (int a = 0; a < 2; a++)
        #pragma unroll
        for (int b = 0; b < 4; b++)
            #pragma unroll
            for (int c = 0; c < 4; c++) acc[a][b][c] = 0.f;

    const bf16 *Wh, *Wl;
    if      constexpr (MODE==1){ Wh = g_w1c_hi; Wl = g_w1c_lo; }
    else if constexpr (MODE==2){ Wh = g_w2t_hi; Wl = g_w2t_lo; }
    else if constexpr (MODE==3){ Wh = g_w3t_hi; Wl = g_w3t_lo; }
    else if constexpr (MODE==4){ Wh = g_w4t_hi; Wl = g_w4t_lo; }
    else { // MODE 7: first 8 n-blocks -> W1a/P, next 8 -> W1b/Q
        if (n0 < HID){ Wh = g_w1a_hi; Wl = g_w1a_lo; }
        else         { Wh = g_w1b_hi; Wl = g_w1b_lo; }
    }
    const int nW = (MODE==7 && n0 >= HID) ? (n0 - HID) : n0;

    auto load_chunk = [&](int kc, int st){
        const int k0 = kc * BK;
        bf16* stg = sm + st*STG;
        #pragma unroll
        for (int j = 0; j < 2; j++){
            int p = tid + j*256;
            int r = p >> 2, c = (p & 3) * 8;
            int k = k0 + c;
            const bf16 *ph, *pl;
            if constexpr (MODE==1){
                size_t o = (size_t)(m0 + r)*ED + k;
                ph = g_ea_hi + o; pl = g_ea_lo + o;
            } else if constexpr (MODE==2){
                size_t o = (size_t)(m0 + r)*HID + k;
                ph = g_h_hi + o; pl = g_h_lo + o;
            } else if constexpr (MODE==3){
                int node = min(m0 + r, NN-1);
                if (k < HID){ size_t o = (size_t)node*HID + k;       ph = g_x_hi + o;   pl = g_x_lo + o; }
                else        { size_t o = (size_t)node*HID + (k-HID); ph = g_agg_hi + o; pl = g_agg_lo + o; }
            } else if constexpr (MODE==4){
                int node = min(m0 + r, NN-1);
                size_t o = (size_t)node*HID + k;
                ph = g_u_hi + o; pl = g_u_lo + o;
            } else {
                int node = min(m0 + r, NN-1);
                size_t o = (size_t)node*HID + k;
                ph = g_x_hi + o; pl = g_x_lo + o;
            }
            cp16(smem_u32(stg + 0*ASZ + r*BKP + c), ph);
            cp16(smem_u32(stg + 1*ASZ + r*BKP + c), pl);
        }
        {
            int r = tid >> 2, c = (tid & 3) * 8;
            size_t o = (size_t)(nW + r)*KTOT + k0 + c;
            cp16(smem_u32(stg + 2*ASZ + 0   + r*BKP + c), Wh + o);
            cp16(smem_u32(stg + 2*ASZ + BSZ + r*BKP + c), Wl + o);
        }
        CP_COMMIT();
    };

    load_chunk(0, 0);

    for (int kc = 0; kc < NCK; ++kc){
        const int st = kc & 1;
        if (kc + 1 < NCK){
            load_chunk(kc + 1, (kc + 1) & 1);
            CP_WAIT1();
        } else {
            CP_WAIT0();
        }
        __syncthreads();

        bf16* stg = sm + st*STG;
        bf16* sAh = stg;
        bf16* sAl = stg + ASZ;
        bf16* sBh = stg + 2*ASZ;
        bf16* sBl = stg + 2*ASZ + BSZ;

        #pragma unroll
        for (int ks = 0; ks < 2; ++ks){
            const int kk = ks * 16;
            unsigned af[2][2][4];
            #pragma unroll
            for (int mt = 0; mt < 2; ++mt){
                int row = wm*32 + mt*16 + (lane & 7) + ((lane >> 3) & 1) * 8;
                int col = kk + (lane >> 4) * 8;
                ldsm_x4(af[mt][0][0], af[mt][0][1], af[mt][0][2], af[mt][0][3],
                        smem_u32(sAh + row*BKP + col));
                ldsm_x4(af[mt][1][0], af[mt][1][1], af[mt][1][2], af[mt][1][3],
                        smem_u32(sAl + row*BKP + col));
            }
            unsigned bfm[4][2][2];
            #pragma unroll
            for (int np = 0; np < 2; ++np){
                int ntl = 2*np + (lane >> 4);
                int row = wn*32 + ntl*8 + (lane & 7);
                int col = kk + ((lane >> 3) & 1) * 8;
                unsigned r0, r1, r2, r3;
                ldsm_x4(r0, r1, r2, r3, smem_u32(sBh + row*BKP + col));
                bfm[2*np][0][0]=r0; bfm[2*np][0][1]=r1; bfm[2*np+1][0][0]=r2; bfm[2*np+1][0][1]=r3;
                ldsm_x4(r0, r1, r2, r3, smem_u32(sBl + row*BKP + col));
                bfm[2*np][1][0]=r0; bfm[2*np][1][1]=r1; bfm[2*np+1][1][0]=r2; bfm[2*np+1][1][1]=r3;
            }
            // TERM-MAJOR issue order: all 8 independent accumulators per term,
            // so same-acc dependent MMAs are 8 issue slots apart (hides HMMA
            // accumulator RAW latency; asm volatile pins program order).
            #pragma unroll
            for (int mt = 0; mt < 2; ++mt)
                #pragma unroll
                for (int nt = 0; nt < 4; ++nt)
                    mma_bf16(acc[mt][nt], af[mt][0][0], af[mt][0][1], af[mt][0][2], af[mt][0][3],
                             bfm[nt][0][0], bfm[nt][0][1]);          // hi*hi
            #pragma unroll
            for (int mt = 0; mt < 2; ++mt)
                #pragma unroll
                for (int nt = 0; nt < 4; ++nt)
                    mma_bf16(acc[mt][nt], af[mt][0][0], af[mt][0][1], af[mt][0][2], af[mt][0][3],
                             bfm[nt][1][0], bfm[nt][1][1]);          // hi*lo
            #pragma unroll
            for (int mt = 0; mt < 2; ++mt)
                #pragma unroll
                for (int nt = 0; nt < 4; ++nt)
                    mma_bf16(acc[mt][nt], af[mt][1][0], af[mt][1][1], af[mt][1][2], af[mt][1][3],
                             bfm[nt][0][0], bfm[nt][0][1]);          // lo*hi
        }
        __syncthreads();
    }

    // ---- epilogue ----
    #pragma unroll
    for (int mt = 0; mt < 2; ++mt){
        const int rl0 = wm*32 + mt*16 + g;
        const int rl1 = rl0 + 8;
        int s0 = 0, s1 = 0, d0 = 0, d1 = 0;
        if constexpr (MODE==1){ s0 = sSrc[rl0]; s1 = sSrc[rl1]; d0 = sDst[rl0]; d1 = sDst[rl1]; }
        if constexpr (MODE==2){ d0 = sDst[rl0]; d1 = sDst[rl1]; }
        #pragma unroll
        for (int nt = 0; nt < 4; ++nt){
            const int col = n0 + wn*32 + nt*8 + t*2;
            float bv0 = 0.f, bv1 = 0.f;
            if constexpr (HAS_BIAS){ bv0 = bias[col]; bv1 = bias[col+1]; }
            float v00 = acc[mt][nt][0] + bv0;
            float v01 = acc[mt][nt][1] + bv1;
            float v10 = acc[mt][nt][2] + bv0;
            float v11 = acc[mt][nt][3] + bv1;
            if constexpr (MODE==1){
                float2 p0 = *(const float2*)&g_P[(size_t)s0*HID + col];
                float2 q0 = *(const float2*)&g_Q[(size_t)d0*HID + col];
                float2 p1 = *(const float2*)&g_P[(size_t)s1*HID + col];
                float2 q1 = *(const float2*)&g_Q[(size_t)d1*HID + col];
                v00 = mishf(v00 + p0.x + q0.x);
                v01 = mishf(v01 + p0.y + q0.y);
                v10 = mishf(v10 + p1.x + q1.x);
                v11 = mishf(v11 + p1.y + q1.y);
                bf16 h00,l00,h01,l01,h10,l10,h11,l11;
                split1(v00,h00,l00); split1(v01,h01,l01);
                split1(v10,h10,l10); split1(v11,h11,l11);
                size_t o0 = (size_t)(m0+rl0)*HID + col;
                size_t o1 = (size_t)(m0+rl1)*HID + col;
                *(uint32_t*)&g_h_hi[o0] = pack2(h00,h01);
                *(uint32_t*)&g_h_lo[o0] = pack2(l00,l01);
                *(uint32_t*)&g_h_hi[o1] = pack2(h10,h11);
                *(uint32_t*)&g_h_lo[o1] = pack2(l10,l11);
            } else if constexpr (MODE==2){
                v00 = mishf(v00); v01 = mishf(v01); v10 = mishf(v10); v11 = mishf(v11);
                // pair lanes t<->t^1: even t issues one float4 RED covering 4 cols
                float p00 = __shfl_xor_sync(0xffffffffu, v00, 1);
                float p01 = __shfl_xor_sync(0xffffffffu, v01, 1);
                float p10 = __shfl_xor_sync(0xffffffffu, v10, 1);
                float p11 = __shfl_xor_sync(0xffffffffu, v11, 1);
                if ((t & 1) == 0){
                    atomicAdd((float4*)&g_agg[(size_t)d0*HID + col], make_float4(v00, v01, p00, p01));
                    atomicAdd((float4*)&g_agg[(size_t)d1*HID + col], make_float4(v10, v11, p10, p11));
                }
            } else if constexpr (MODE==3){
                const int r0i = m0 + rl0, r1i = m0 + rl1;
                if (r0i < NN){
                    float a = mishf(v00), b = mishf(v01);
                    bf16 ha,la,hb,lb; split1(a,ha,la); split1(b,hb,lb);
                    size_t o = (size_t)r0i*HID + col;
                    *(uint32_t*)&g_u_hi[o] = pack2(ha,hb);
                    *(uint32_t*)&g_u_lo[o] = pack2(la,lb);
                }
                if (r1i < NN){
                    float a = mishf(v10), b = mishf(v11);
                    bf16 ha,la,hb,lb; split1(a,ha,la); split1(b,hb,lb);
                    size_t o = (size_t)r1i*HID + col;
                    *(uint32_t*)&g_u_hi[o] = pack2(ha,hb);
                    *(uint32_t*)&g_u_lo[o] = pack2(la,lb);
                }
            } else if constexpr (MODE==4){
                const int r0i = m0 + rl0, r1i = m0 + rl1;
                if (r0i < NN){
                    float2 xv = *(const float2*)&xres[(size_t)r0i*HID + col];
                    *(float2*)&g_y[(size_t)r0i*HID + col] = make_float2(v00 + xv.x, v01 + xv.y);
                }
                if (r1i < NN){
                    float2 xv = *(const float2*)&xres[(size_t)r1i*HID + col];
                    *(float2*)&g_y[(size_t)r1i*HID + col] = make_float2(v10 + xv.x, v11 + xv.y);
                }
            } else { // MODE 7
                float* dst = (n0 < HID) ? g_P : g_Q;
                const int cw = nW + wn*32 + nt*8 + t*2;
                const int r0i = m0 + rl0, r1i = m0 + rl1;
                if (r0i < NN)
                    *(float2*)&dst[(size_t)r0i*HID + cw] = make_float2(v00, v01);
                if (r1i < NN)
                    *(float2*)&dst[(size_t)r1i*HID + cw] = make_float2(v10, v11);
            }
        }
    }
}

// ---------------- LayerNorm ----------------
__global__ __launch_bounds__(128)
void ln_kernel(const float* __restrict__ gamma, const float* __restrict__ beta,
               float* __restrict__ out)
{
    const int row = blockIdx.x, tid = threadIdx.x;
    float4 v = *((const float4*)(g_y + (size_t)row*HID) + tid);
    float s  = v.x + v.y + v.z + v.w;
    float ss = fmaf(v.x, v.x, fmaf(v.y, v.y, fmaf(v.z, v.z, v.w*v.w)));
    #pragma unroll
    for (int o = 16; o > 0; o >>= 1){
        s  += __shfl_xor_sync(0xffffffffu, s,  o);
        ss += __shfl_xor_sync(0xffffffffu, ss, o);
    }
    __shared__ float sh_s[4], sh_ss[4];
    if ((tid & 31) == 0){ sh_s[tid >> 5] = s; sh_ss[tid >> 5] = ss; }
    __syncthreads();
    s  = sh_s[0]  + sh_s[1]  + sh_s[2]  + sh_s[3];
    ss = sh_ss[0] + sh_ss[1] + sh_ss[2] + sh_ss[3];
    const float mu  = s * (1.f / HID);
    const float var = ss * (1.f / HID) - mu * mu;
    const float inv = rsqrtf(var + 1e-5f);
    float4 gm = ((const float4*)gamma)[tid];
    float4 bt = ((const float4*)beta)[tid];
    float4 o;
    o.x = (v.x - mu) * inv * gm.x + bt.x;
    o.y = (v.y - mu) * inv * gm.y + bt.y;
    o.z = (v.z - mu) * inv * gm.z + bt.z;
    o.w = (v.w - mu) * inv * gm.w + bt.w;
    *((float4*)(out + (size_t)row*HID) + tid) = o;
}

// ---------------- launch ----------------
extern "C" void kernel_launch(void* const* d_in, const int* in_sizes, int n_in,
                              void* d_out, int out_size)
{
    (void)in_sizes; (void)n_in; (void)out_size;
    const float* x     = (const float*)d_in[0];
    const void*  ei    = d_in[1];
    const float* ea    = (const float*)d_in[2];
    const float* W1    = (const float*)d_in[3];
    const float* b1    = (const float*)d_in[4];
    const float* W2    = (const float*)d_in[5];
    const float* b2    = (const float*)d_in[6];
    const float* W3    = (const float*)d_in[7];
    const float* b3    = (const float*)d_in[8];
    const float* W4    = (const float*)d_in[9];
    const float* b4    = (const float*)d_in[10];
    const float* gamma = (const float*)d_in[11];
    const float* beta  = (const float*)d_in[12];
    float* out = (float*)d_out;

    cudaFuncSetAttribute(gemm_kernel<1>, cudaFuncAttributeMaxDynamicSharedMemorySize, SMEM_BYTES);
    cudaFuncSetAttribute(gemm_kernel<2>, cudaFuncAttributeMaxDynamicSharedMemorySize, SMEM_BYTES);
    cudaFuncSetAttribute(gemm_kernel<3>, cudaFuncAttributeMaxDynamicSharedMemorySize, SMEM_BYTES);
    cudaFuncSetAttribute(gemm_kernel<4>, cudaFuncAttributeMaxDynamicSharedMemorySize, SMEM_BYTES);
    cudaFuncSetAttribute(gemm_kernel<7>, cudaFuncAttributeMaxDynamicSharedMemorySize, SMEM_BYTES);

    k_split_all  <<<(SPLIT_ALL_TOT + 255)/256, 256>>>(x, W1, W2, W3, W4);   // 1
    k_split_ea   <<<(NE*ED + 255)/256, 256>>>(ea);                          // 2
    k_decode_zero<<<(NN*HID + 255)/256, 256>>>(ei);                         // 3

    dim3 gPQ(2*HID/BN, (NN + BM - 1)/BM);    // (16, 157)
    dim3 gE(HID/BN, NE/BM);                  // (8, 2500)
    dim3 gN(HID/BN, (NN + BM - 1)/BM);       // (8, 157)
    gemm_kernel<7><<<gPQ, 256, SMEM_BYTES>>>(nullptr, nullptr);  // 4: P|Q
    gemm_kernel<1><<<gE, 256, SMEM_BYTES>>>(b1, nullptr);        // 5: h
    gemm_kernel<2><<<gE, 256, SMEM_BYTES>>>(b2, nullptr);        // 6: messages+scatter
    k_split_agg  <<<(NN*HID + 255)/256, 256>>>();                // 7
    gemm_kernel<3><<<gN, 256, SMEM_BYTES>>>(b3, nullptr);        // 8: u
    gemm_kernel<4><<<gN, 256, SMEM_BYTES>>>(b4, x);              // 9: y
    ln_kernel<<<NN, 128>>>(gamma, beta, out);                    // 10
}

// round 8
// speedup vs baseline: 2.9392x; 1.3020x over previous
#include <cuda_runtime.h>
#include <cuda_fp16.h>
#include <math.h>
#include <stdint.h>

using fp16 = __half;

constexpr int NN  = 20000;      // nodes
constexpr int NE  = 320000;     // edges
constexpr int HID = 512;
constexpr int ED  = 64;
constexpr int KC3 = 2*HID;      // 1024

constexpr int BM = 128, BN = 64, BK = 32, PAD = 8, BKP = BK + PAD;

constexpr int ASZ = BM*BKP;             // A tile (single)
constexpr int BSZ = BN*BKP;             // B tile (per hi/lo)
constexpr int STG = ASZ + 2*BSZ;
constexpr int SMEM_BYTES = 2*STG*(int)sizeof(fp16);   // 40960

constexpr float WSC  = 32.0f;           // weight pre-scale (keeps Wlo normal-range fp16)
constexpr float WINV = 1.0f/32.0f;

// ---------------- device scratch ----------------
__device__ fp16 g_x[NN*HID];
__device__ fp16 g_ea[NE*ED];
__device__ fp16 g_w1a_hi[HID*HID], g_w1a_lo[HID*HID];
__device__ fp16 g_w1b_hi[HID*HID], g_w1b_lo[HID*HID];
__device__ fp16 g_w1c_hi[HID*ED],  g_w1c_lo[HID*ED];
__device__ fp16 g_w2t_hi[HID*HID], g_w2t_lo[HID*HID];
__device__ fp16 g_w3t_hi[HID*KC3], g_w3t_lo[HID*KC3];
__device__ fp16 g_w4t_hi[HID*HID], g_w4t_lo[HID*HID];
__device__ int   g_ei[2*NE];
__device__ float g_P[NN*HID];
__device__ float g_Q[NN*HID];
__device__ fp16  g_h[(size_t)NE*HID];   // 328 MB (was 655)
__device__ float g_agg[NN*HID];
__device__ fp16  g_agg_h[NN*HID];
__device__ fp16  g_u[NN*HID];
__device__ float g_y[NN*HID];

// ---------------- helpers ----------------
__device__ __forceinline__ float mishf(float x){
    float t   = __expf(fminf(x, 15.f));
    float num = t * (t + 2.f);
    return x * __fdividef(num, num + 2.f);
}
__device__ __forceinline__ unsigned smem_u32(const void* p){
    return (unsigned)__cvta_generic_to_shared(p);
}
__device__ __forceinline__ void ldsm_x4(unsigned &r0, unsigned &r1, unsigned &r2, unsigned &r3, unsigned addr){
    asm volatile("ldmatrix.sync.aligned.m8n8.x4.shared.b16 {%0,%1,%2,%3}, [%4];"
                 : "=r"(r0), "=r"(r1), "=r"(r2), "=r"(r3) : "r"(addr));
}
__device__ __forceinline__ void mma_f16(float* c, unsigned a0, unsigned a1, unsigned a2, unsigned a3,
                                        unsigned b0, unsigned b1){
    asm volatile("mma.sync.aligned.m16n8k16.row.col.f32.f16.f16.f32 "
                 "{%0,%1,%2,%3}, {%4,%5,%6,%7}, {%8,%9}, {%0,%1,%2,%3};"
                 : "+f"(c[0]), "+f"(c[1]), "+f"(c[2]), "+f"(c[3])
                 : "r"(a0), "r"(a1), "r"(a2), "r"(a3), "r"(b0), "r"(b1));
}
__device__ __forceinline__ void splitw(float v, fp16 &h, fp16 &l){
    h = __float2half(v);
    l = __float2half(v - __half2float(h));
}
__device__ __forceinline__ uint32_t pack2h(fp16 a, fp16 b){
    __half2 p; p.x = a; p.y = b;
    return *(uint32_t*)&p;
}
__device__ __forceinline__ void cp16(uint32_t dst, const void* src){
    asm volatile("cp.async.cg.shared.global [%0], [%1], 16;" :: "r"(dst), "l"(src));
}
#define CP_COMMIT() asm volatile("cp.async.commit_group;" ::: "memory")
#define CP_WAIT1()  asm volatile("cp.async.wait_group 1;" ::: "memory")
#define CP_WAIT0()  asm volatile("cp.async.wait_group 0;" ::: "memory")

// ---------------- prep kernels (fused) ----------------
constexpr int NX   = NN*HID;
constexpr int NW1A = HID*HID;
constexpr int NW1B = HID*HID;
constexpr int NW1C = ED*HID;
constexpr int NW2  = HID*HID;
constexpr int NW3  = KC3*HID;
constexpr int NW4  = HID*HID;
constexpr int SPLIT_ALL_TOT = NX + NW1A + NW1B + NW1C + NW2 + NW3 + NW4;

__global__ void k_split_all(const float* __restrict__ x,
                            const float* __restrict__ W1,
                            const float* __restrict__ W2,
                            const float* __restrict__ W3,
                            const float* __restrict__ W4){
    int i = blockIdx.x * blockDim.x + threadIdx.x;
    if (i >= SPLIT_ALL_TOT) return;
    if (i < NX){
        g_x[i] = __float2half(x[i]);
        return;
    }
    i -= NX;
    const float* src; fp16 *hi, *lo; int K;
    if      (i < NW1A){                              src = W1;                     hi=g_w1a_hi; lo=g_w1a_lo; K=HID; }
    else if ((i -= NW1A) < NW1B){                    src = W1 + (size_t)HID*HID;   hi=g_w1b_hi; lo=g_w1b_lo; K=HID; }
    else if ((i -= NW1B) < NW1C){                    src = W1 + (size_t)2*HID*HID; hi=g_w1c_hi; lo=g_w1c_lo; K=ED; }
    else if ((i -= NW1C) < NW2){                     src = W2;                     hi=g_w2t_hi; lo=g_w2t_lo; K=HID; }
    else if ((i -= NW2)  < NW3){                     src = W3;                     hi=g_w3t_hi; lo=g_w3t_lo; K=KC3; }
    else { i -= NW3;                                 src = W4;                     hi=g_w4t_hi; lo=g_w4t_lo; K=HID; }
    int k = i / HID, n = i % HID;
    fp16 h, l; splitw(src[i] * WSC, h, l);
    hi[(size_t)n*K + k] = h;
    lo[(size_t)n*K + k] = l;
}
__global__ void k_split_ea(const float* __restrict__ s){
    int i = blockIdx.x * blockDim.x + threadIdx.x;
    if (i < NE*ED) g_ea[i] = __float2half(s[i]);
}
// decode edge_index (int64 vs int32 defensive) + zero agg
__global__ void k_decode_zero(const void* __restrict__ ei_raw){
    int i = blockIdx.x * blockDim.x + threadIdx.x;
    if (i < 2*NE){
        const long long* p64 = (const long long*)ei_raw;
        bool is64 = true;
        #pragma unroll
        for (int j = 0; j < 4; j++){
            long long v = p64[j];
            if (v < 0 || v >= NN) is64 = false;
        }
        g_ei[i] = is64 ? (int)p64[i] : ((const int*)ei_raw)[i];
    }
    if (i < NN*HID) g_agg[i] = 0.f;
}
__global__ void k_split_agg(){
    int i = blockIdx.x * blockDim.x + threadIdx.x;
    if (i < NN*HID) g_agg_h[i] = __float2half(g_agg[i]);
}

// ---------------- 2-term fp16 GEMM (A single fp16, W split hi/lo ×32) ----------------
// MODE 7: [P|Q] = x @ [W1a|W1b]
// MODE 1: h = mish(ea@W1c + P[src] + Q[dst] + b1) -> g_h fp16
// MODE 2: msg = mish(h @ W2 + b2); float4 RED scatter into agg[dst]
// MODE 3: u = mish([x|agg_h] @ W3 + b3) -> g_u fp16
// MODE 4: y = x + u @ W4 + b4
template<int MODE>
__global__ __launch_bounds__(256, 2)
void gemm_kernel(const float* __restrict__ bias, const float* __restrict__ xres)
{
    constexpr int KTOT = (MODE==1) ? ED : (MODE==3) ? KC3 : HID;
    constexpr int NCK  = KTOT / BK;
    constexpr bool HAS_BIAS = (MODE != 7);

    extern __shared__ __align__(16) char smem_raw[];
    fp16* sm = (fp16*)smem_raw;
    __shared__ int sSrc[BM];
    __shared__ int sDst[BM];

    const int tid = threadIdx.x;
    const int n0  = blockIdx.x * BN;
    const int m0  = blockIdx.y * BM;

    if constexpr (MODE==1 || MODE==2){
        if (tid < BM){
            if (MODE == 1) sSrc[tid] = g_ei[m0 + tid];
            sDst[tid] = g_ei[NE + m0 + tid];
        }
    }

    const int wid = tid >> 5, lane = tid & 31;
    const int wm  = wid >> 1, wn = wid & 1;   // 4x2 warp grid, 32x32 per warp
    const int g   = lane >> 2, t = lane & 3;

    float acc[2][4][4];
    #pragma unroll
    for (int a = 0; a < 2; a++)
        #pragma unroll
        for (int b = 0; b < 4; b++)
            #pragma unroll
            for (int c = 0; c < 4; c++) acc[a][b][c] = 0.f;

    const fp16 *Wh, *Wl;
    if      constexpr (MODE==1){ Wh = g_w1c_hi; Wl = g_w1c_lo; }
    else if constexpr (MODE==2){ Wh = g_w2t_hi; Wl = g_w2t_lo; }
    else if constexpr (MODE==3){ Wh = g_w3t_hi; Wl = g_w3t_lo; }
    else if constexpr (MODE==4){ Wh = g_w4t_hi; Wl = g_w4t_lo; }
    else {
        if (n0 < HID){ Wh = g_w1a_hi; Wl = g_w1a_lo; }
        else         { Wh = g_w1b_hi; Wl = g_w1b_lo; }
    }
    const int nW = (MODE==7 && n0 >= HID) ? (n0 - HID) : n0;

    auto load_chunk = [&](int kc, int st){
        const int k0 = kc * BK;
        fp16* stg = sm + st*STG;
        // A: 128x32 fp16 = 512 16B-chunks -> 2 per thread
        #pragma unroll
        for (int j = 0; j < 2; j++){
            int p = tid + j*256;
            int r = p >> 2, c = (p & 3) * 8;
            int k = k0 + c;
            const fp16 *pa;
            if constexpr (MODE==1){
                pa = g_ea + (size_t)(m0 + r)*ED + k;
            } else if constexpr (MODE==2){
                pa = g_h + (size_t)(m0 + r)*HID + k;
            } else if constexpr (MODE==3){
                int node = min(m0 + r, NN-1);
                if (k < HID) pa = g_x     + (size_t)node*HID + k;
                else         pa = g_agg_h + (size_t)node*HID + (k - HID);
            } else if constexpr (MODE==4){
                int node = min(m0 + r, NN-1);
                pa = g_u + (size_t)node*HID + k;
            } else {
                int node = min(m0 + r, NN-1);
                pa = g_x + (size_t)node*HID + k;
            }
            cp16(smem_u32(stg + r*BKP + c), pa);
        }
        // B: 64x32 per hi/lo = 256 chunks each -> 1+1 per thread
        {
            int r = tid >> 2, c = (tid & 3) * 8;
            size_t o = (size_t)(nW + r)*KTOT + k0 + c;
            cp16(smem_u32(stg + ASZ + 0   + r*BKP + c), Wh + o);
            cp16(smem_u32(stg + ASZ + BSZ + r*BKP + c), Wl + o);
        }
        CP_COMMIT();
    };

    load_chunk(0, 0);

    for (int kc = 0; kc < NCK; ++kc){
        const int st = kc & 1;
        if (kc + 1 < NCK){
            load_chunk(kc + 1, (kc + 1) & 1);
            CP_WAIT1();
        } else {
            CP_WAIT0();
        }
        __syncthreads();

        fp16* stg = sm + st*STG;
        fp16* sA  = stg;
        fp16* sBh = stg + ASZ;
        fp16* sBl = stg + ASZ + BSZ;

        #pragma unroll
        for (int ks = 0; ks < 2; ++ks){
            const int kk = ks * 16;
            unsigned af[2][4];
            #pragma unroll
            for (int mt = 0; mt < 2; ++mt){
                int row = wm*32 + mt*16 + (lane & 7) + ((lane >> 3) & 1) * 8;
                int col = kk + (lane >> 4) * 8;
                ldsm_x4(af[mt][0], af[mt][1], af[mt][2], af[mt][3],
                        smem_u32(sA + row*BKP + col));
            }
            unsigned bh[4][2], bl[4][2];
            #pragma unroll
            for (int np = 0; np < 2; ++np){
                int ntl = 2*np + (lane >> 4);
                int row = wn*32 + ntl*8 + (lane & 7);
                int col = kk + ((lane >> 3) & 1) * 8;
                unsigned r0, r1, r2, r3;
                ldsm_x4(r0, r1, r2, r3, smem_u32(sBh + row*BKP + col));
                bh[2*np][0]=r0; bh[2*np][1]=r1; bh[2*np+1][0]=r2; bh[2*np+1][1]=r3;
                ldsm_x4(r0, r1, r2, r3, smem_u32(sBl + row*BKP + col));
                bl[2*np][0]=r0; bl[2*np][1]=r1; bl[2*np+1][0]=r2; bl[2*np+1][1]=r3;
            }
            // term-major: 8 independent accs between same-acc reuses
            #pragma unroll
            for (int mt = 0; mt < 2; ++mt)
                #pragma unroll
                for (int nt = 0; nt < 4; ++nt)
                    mma_f16(acc[mt][nt], af[mt][0], af[mt][1], af[mt][2], af[mt][3],
                            bh[nt][0], bh[nt][1]);                // A * Whi
            #pragma unroll
            for (int mt = 0; mt < 2; ++mt)
                #pragma unroll
                for (int nt = 0; nt < 4; ++nt)
                    mma_f16(acc[mt][nt], af[mt][0], af[mt][1], af[mt][2], af[mt][3],
                            bl[nt][0], bl[nt][1]);                // A * Wlo
        }
        __syncthreads();
    }

    // ---- epilogue (acc carries 32x result; scale by WINV) ----
    #pragma unroll
    for (int mt = 0; mt < 2; ++mt){
        const int rl0 = wm*32 + mt*16 + g;
        const int rl1 = rl0 + 8;
        int s0 = 0, s1 = 0, d0 = 0, d1 = 0;
        if constexpr (MODE==1){ s0 = sSrc[rl0]; s1 = sSrc[rl1]; d0 = sDst[rl0]; d1 = sDst[rl1]; }
        if constexpr (MODE==2){ d0 = sDst[rl0]; d1 = sDst[rl1]; }
        #pragma unroll
        for (int nt = 0; nt < 4; ++nt){
            const int col = n0 + wn*32 + nt*8 + t*2;
            float bv0 = 0.f, bv1 = 0.f;
            if constexpr (HAS_BIAS){ bv0 = bias[col]; bv1 = bias[col+1]; }
            float v00 = acc[mt][nt][0]*WINV + bv0;
            float v01 = acc[mt][nt][1]*WINV + bv1;
            float v10 = acc[mt][nt][2]*WINV + bv0;
            float v11 = acc[mt][nt][3]*WINV + bv1;
            if constexpr (MODE==1){
                float2 p0 = *(const float2*)&g_P[(size_t)s0*HID + col];
                float2 q0 = *(const float2*)&g_Q[(size_t)d0*HID + col];
                float2 p1 = *(const float2*)&g_P[(size_t)s1*HID + col];
                float2 q1 = *(const float2*)&g_Q[(size_t)d1*HID + col];
                v00 = mishf(v00 + p0.x + q0.x);
                v01 = mishf(v01 + p0.y + q0.y);
                v10 = mishf(v10 + p1.x + q1.x);
                v11 = mishf(v11 + p1.y + q1.y);
                size_t o0 = (size_t)(m0+rl0)*HID + col;
                size_t o1 = (size_t)(m0+rl1)*HID + col;
                *(uint32_t*)&g_h[o0] = pack2h(__float2half(v00), __float2half(v01));
                *(uint32_t*)&g_h[o1] = pack2h(__float2half(v10), __float2half(v11));
            } else if constexpr (MODE==2){
                v00 = mishf(v00); v01 = mishf(v01); v10 = mishf(v10); v11 = mishf(v11);
                float p00 = __shfl_xor_sync(0xffffffffu, v00, 1);
                float p01 = __shfl_xor_sync(0xffffffffu, v01, 1);
                float p10 = __shfl_xor_sync(0xffffffffu, v10, 1);
                float p11 = __shfl_xor_sync(0xffffffffu, v11, 1);
                if ((t & 1) == 0){
                    atomicAdd((float4*)&g_agg[(size_t)d0*HID + col], make_float4(v00, v01, p00, p01));
                    atomicAdd((float4*)&g_agg[(size_t)d1*HID + col], make_float4(v10, v11, p10, p11));
                }
            } else if constexpr (MODE==3){
                const int r0i = m0 + rl0, r1i = m0 + rl1;
                if (r0i < NN){
                    size_t o = (size_t)r0i*HID + col;
                    *(uint32_t*)&g_u[o] = pack2h(__float2half(mishf(v00)), __float2half(mishf(v01)));
                }
                if (r1i < NN){
                    size_t o = (size_t)r1i*HID + col;
                    *(uint32_t*)&g_u[o] = pack2h(__float2half(mishf(v10)), __float2half(mishf(v11)));
                }
            } else if constexpr (MODE==4){
                const int r0i = m0 + rl0, r1i = m0 + rl1;
                if (r0i < NN){
                    float2 xv = *(const float2*)&xres[(size_t)r0i*HID + col];
                    *(float2*)&g_y[(size_t)r0i*HID + col] = make_float2(v00 + xv.x, v01 + xv.y);
                }
                if (r1i < NN){
                    float2 xv = *(const float2*)&xres[(size_t)r1i*HID + col];
                    *(float2*)&g_y[(size_t)r1i*HID + col] = make_float2(v10 + xv.x, v11 + xv.y);
                }
            } else { // MODE 7
                float* dst = (n0 < HID) ? g_P : g_Q;
                const int cw = nW + wn*32 + nt*8 + t*2;
                const int r0i = m0 + rl0, r1i = m0 + rl1;
                if (r0i < NN)
                    *(float2*)&dst[(size_t)r0i*HID + cw] = make_float2(v00, v01);
                if (r1i < NN)
                    *(float2*)&dst[(size_t)r1i*HID + cw] = make_float2(v10, v11);
            }
        }
    }
}

// ---------------- LayerNorm ----------------
__global__ __launch_bounds__(128)
void ln_kernel(const float* __restrict__ gamma, const float* __restrict__ beta,
               float* __restrict__ out)
{
    const int row = blockIdx.x, tid = threadIdx.x;
    float4 v = *((const float4*)(g_y + (size_t)row*HID) + tid);
    float s  = v.x + v.y + v.z + v.w;
    float ss = fmaf(v.x, v.x, fmaf(v.y, v.y, fmaf(v.z, v.z, v.w*v.w)));
    #pragma unroll
    for (int o = 16; o > 0; o >>= 1){
        s  += __shfl_xor_sync(0xffffffffu, s,  o);
        ss += __shfl_xor_sync(0xffffffffu, ss, o);
    }
    __shared__ float sh_s[4], sh_ss[4];
    if ((tid & 31) == 0){ sh_s[tid >> 5] = s; sh_ss[tid >> 5] = ss; }
    __syncthreads();
    s  = sh_s[0]  + sh_s[1]  + sh_s[2]  + sh_s[3];
    ss = sh_ss[0] + sh_ss[1] + sh_ss[2] + sh_ss[3];
    const float mu  = s * (1.f / HID);
    const float var = ss * (1.f / HID) - mu * mu;
    const float inv = rsqrtf(var + 1e-5f);
    float4 gm = ((const float4*)gamma)[tid];
    float4 bt = ((const float4*)beta)[tid];
    float4 o;
    o.x = (v.x - mu) * inv * gm.x + bt.x;
    o.y = (v.y - mu) * inv * gm.y + bt.y;
    o.z = (v.z - mu) * inv * gm.z + bt.z;
    o.w = (v.w - mu) * inv * gm.w + bt.w;
    *((float4*)(out + (size_t)row*HID) + tid) = o;
}

// ---------------- launch ----------------
extern "C" void kernel_launch(void* const* d_in, const int* in_sizes, int n_in,
                              void* d_out, int out_size)
{
    (void)in_sizes; (void)n_in; (void)out_size;
    const float* x     = (const float*)d_in[0];
    const void*  ei    = d_in[1];
    const float* ea    = (const float*)d_in[2];
    const float* W1    = (const float*)d_in[3];
    const float* b1    = (const float*)d_in[4];
    const float* W2    = (const float*)d_in[5];
    const float* b2    = (const float*)d_in[6];
    const float* W3    = (const float*)d_in[7];
    const float* b3    = (const float*)d_in[8];
    const float* W4    = (const float*)d_in[9];
    const float* b4    = (const float*)d_in[10];
    const float* gamma = (const float*)d_in[11];
    const float* beta  = (const float*)d_in[12];
    float* out = (float*)d_out;

    cudaFuncSetAttribute(gemm_kernel<1>, cudaFuncAttributeMaxDynamicSharedMemorySize, SMEM_BYTES);
    cudaFuncSetAttribute(gemm_kernel<2>, cudaFuncAttributeMaxDynamicSharedMemorySize, SMEM_BYTES);
    cudaFuncSetAttribute(gemm_kernel<3>, cudaFuncAttributeMaxDynamicSharedMemorySize, SMEM_BYTES);
    cudaFuncSetAttribute(gemm_kernel<4>, cudaFuncAttributeMaxDynamicSharedMemorySize, SMEM_BYTES);
    cudaFuncSetAttribute(gemm_kernel<7>, cudaFuncAttributeMaxDynamicSharedMemorySize, SMEM_BYTES);

    k_split_all  <<<(SPLIT_ALL_TOT + 255)/256, 256>>>(x, W1, W2, W3, W4);   // 1
    k_split_ea   <<<(NE*ED + 255)/256, 256>>>(ea);                          // 2
    k_decode_zero<<<(NN*HID + 255)/256, 256>>>(ei);                         // 3

    dim3 gPQ(2*HID/BN, (NN + BM - 1)/BM);    // (16, 157)
    dim3 gE(HID/BN, NE/BM);                  // (8, 2500)
    dim3 gN(HID/BN, (NN + BM - 1)/BM);       // (8, 157)
    gemm_kernel<7><<<gPQ, 256, SMEM_BYTES>>>(nullptr, nullptr);  // 4: P|Q
    gemm_kernel<1><<<gE, 256, SMEM_BYTES>>>(b1, nullptr);        // 5: h
    gemm_kernel<2><<<gE, 256, SMEM_BYTES>>>(b2, nullptr);        // 6: messages+scatter  <- ncu
    k_split_agg  <<<(NN*HID + 255)/256, 256>>>();                // 7
    gemm_kernel<3><<<gN, 256, SMEM_BYTES>>>(b3, nullptr);        // 8: u
    gemm_kernel<4><<<gN, 256, SMEM_BYTES>>>(b4, x);              // 9: y
    ln_kernel<<<NN, 128>>>(gamma, beta, out);                    // 10
}

// round 10
// speedup vs baseline: 3.7241x; 1.2670x over previous
#include <cuda_runtime.h>
#include <cuda_fp16.h>
#include <math.h>
#include <stdint.h>

using fp16 = __half;

constexpr int NN  = 20000;      // nodes
constexpr int NE  = 320000;     // edges
constexpr int HID = 512;
constexpr int ED  = 64;
constexpr int KC3 = 2*HID;      // 1024

constexpr int BM = 128, BN = 64, BK = 32, PAD = 8, BKP = BK + PAD;

constexpr int ASZ = BM*BKP;             // A tile (single)
constexpr int BSZ = BN*BKP;             // B tile (per hi/lo)
constexpr int STG = ASZ + 2*BSZ;
constexpr int SMEM_BYTES = 2*STG*(int)sizeof(fp16);   // 40960

constexpr float WSC  = 32.0f;           // weight pre-scale (keeps Wlo normal-range fp16)
constexpr float WINV = 1.0f/32.0f;

// ---------------- device scratch ----------------
__device__ fp16 g_x[NN*HID];
__device__ fp16 g_ea[NE*ED];
__device__ fp16 g_w1a_hi[HID*HID], g_w1a_lo[HID*HID];
__device__ fp16 g_w1b_hi[HID*HID], g_w1b_lo[HID*HID];
__device__ fp16 g_w1c_hi[HID*ED],  g_w1c_lo[HID*ED];
__device__ fp16 g_w2t_hi[HID*HID], g_w2t_lo[HID*HID];
__device__ fp16 g_w3t_hi[HID*KC3], g_w3t_lo[HID*KC3];
__device__ fp16 g_w4t_hi[HID*HID], g_w4t_lo[HID*HID];
__device__ int   g_ei[2*NE];
__device__ float g_P[NN*HID];
__device__ float g_Q[NN*HID];
__device__ fp16  g_h[(size_t)NE*HID];
__device__ float g_agg[NN*HID];
__device__ fp16  g_agg_h[NN*HID];
__device__ fp16  g_u[NN*HID];
__device__ float g_y[NN*HID];

// ---------------- helpers ----------------
__device__ __forceinline__ float mishf(float x){
    float t   = __expf(fminf(x, 15.f));
    float num = t * (t + 2.f);
    return x * __fdividef(num, num + 2.f);
}
__device__ __forceinline__ unsigned smem_u32(const void* p){
    return (unsigned)__cvta_generic_to_shared(p);
}
__device__ __forceinline__ void ldsm_x4(unsigned &r0, unsigned &r1, unsigned &r2, unsigned &r3, unsigned addr){
    asm volatile("ldmatrix.sync.aligned.m8n8.x4.shared.b16 {%0,%1,%2,%3}, [%4];"
                 : "=r"(r0), "=r"(r1), "=r"(r2), "=r"(r3) : "r"(addr));
}
__device__ __forceinline__ void mma_f16(float* c, unsigned a0, unsigned a1, unsigned a2, unsigned a3,
                                        unsigned b0, unsigned b1){
    asm volatile("mma.sync.aligned.m16n8k16.row.col.f32.f16.f16.f32 "
                 "{%0,%1,%2,%3}, {%4,%5,%6,%7}, {%8,%9}, {%0,%1,%2,%3};"
                 : "+f"(c[0]), "+f"(c[1]), "+f"(c[2]), "+f"(c[3])
                 : "r"(a0), "r"(a1), "r"(a2), "r"(a3), "r"(b0), "r"(b1));
}
__device__ __forceinline__ void splitw(float v, fp16 &h, fp16 &l){
    h = __float2half(v);
    l = __float2half(v - __half2float(h));
}
__device__ __forceinline__ uint32_t pack2h(fp16 a, fp16 b){
    __half2 p; p.x = a; p.y = b;
    return *(uint32_t*)&p;
}
__device__ __forceinline__ void cp16(uint32_t dst, const void* src){
    asm volatile("cp.async.cg.shared.global [%0], [%1], 16;" :: "r"(dst), "l"(src));
}
#define CP_COMMIT() asm volatile("cp.async.commit_group;" ::: "memory")
#define CP_WAIT1()  asm volatile("cp.async.wait_group 1;" ::: "memory")
#define CP_WAIT0()  asm volatile("cp.async.wait_group 0;" ::: "memory")

// ---------------- prep kernels (fused) ----------------
constexpr int NX   = NN*HID;
constexpr int NW1A = HID*HID;
constexpr int NW1B = HID*HID;
constexpr int NW1C = ED*HID;
constexpr int NW2  = HID*HID;
constexpr int NW3  = KC3*HID;
constexpr int NW4  = HID*HID;
constexpr int SPLIT_ALL_TOT = NX + NW1A + NW1B + NW1C + NW2 + NW3 + NW4;

__global__ void k_split_all(const float* __restrict__ x,
                            const float* __restrict__ W1,
                            const float* __restrict__ W2,
                            const float* __restrict__ W3,
                            const float* __restrict__ W4){
    int i = blockIdx.x * blockDim.x + threadIdx.x;
    if (i >= SPLIT_ALL_TOT) return;
    if (i < NX){
        g_x[i] = __float2half(x[i]);
        return;
    }
    i -= NX;
    const float* src; fp16 *hi, *lo; int K;
    if      (i < NW1A){                              src = W1;                     hi=g_w1a_hi; lo=g_w1a_lo; K=HID; }
    else if ((i -= NW1A) < NW1B){                    src = W1 + (size_t)HID*HID;   hi=g_w1b_hi; lo=g_w1b_lo; K=HID; }
    else if ((i -= NW1B) < NW1C){                    src = W1 + (size_t)2*HID*HID; hi=g_w1c_hi; lo=g_w1c_lo; K=ED; }
    else if ((i -= NW1C) < NW2){                     src = W2;                     hi=g_w2t_hi; lo=g_w2t_lo; K=HID; }
    else if ((i -= NW2)  < NW3){                     src = W3;                     hi=g_w3t_hi; lo=g_w3t_lo; K=KC3; }
    else { i -= NW3;                                 src = W4;                     hi=g_w4t_hi; lo=g_w4t_lo; K=HID; }
    int k = i / HID, n = i % HID;
    fp16 h, l; splitw(src[i] * WSC, h, l);
    hi[(size_t)n*K + k] = h;
    lo[(size_t)n*K + k] = l;
}
__global__ void k_split_ea(const float* __restrict__ s){
    int i = blockIdx.x * blockDim.x + threadIdx.x;
    if (i < NE*ED) g_ea[i] = __float2half(s[i]);
}
// decode edge_index (int64 vs int32 defensive) + zero agg
__global__ void k_decode_zero(const void* __restrict__ ei_raw){
    int i = blockIdx.x * blockDim.x + threadIdx.x;
    if (i < 2*NE){
        const long long* p64 = (const long long*)ei_raw;
        bool is64 = true;
        #pragma unroll
        for (int j = 0; j < 4; j++){
            long long v = p64[j];
            if (v < 0 || v >= NN) is64 = false;
        }
        g_ei[i] = is64 ? (int)p64[i] : ((const int*)ei_raw)[i];
    }
    if (i < NN*HID) g_agg[i] = 0.f;
}
__global__ void k_split_agg(){
    int i = blockIdx.x * blockDim.x + threadIdx.x;
    if (i < NN*HID) g_agg_h[i] = __float2half(g_agg[i]);
}

// ---------------- fp16 GEMM: edge GEMMs 1-term, node GEMMs 2-term W split ----------------
// MODE 7: [P|Q] = x @ [W1a|W1b]                      (2-term: feeds all edges in fp32)
// MODE 1: h = mish(ea@W1c + P[src] + Q[dst] + b1)    (1-term: ea already fp16-rounded)
// MODE 2: msg = mish(h @ W2 + b2); RED scatter       (1-term: h already fp16-rounded)
// MODE 3: u = mish([x|agg_h] @ W3 + b3)              (2-term)
// MODE 4: y = x + u @ W4 + b4                        (2-term)
template<int MODE>
__global__ __launch_bounds__(256, 2)
void gemm_kernel(const float* __restrict__ bias, const float* __restrict__ xres)
{
    constexpr int KTOT  = (MODE==1) ? ED : (MODE==3) ? KC3 : HID;
    constexpr int NCK   = KTOT / BK;
    constexpr int TERMS = (MODE==1 || MODE==2) ? 1 : 2;
    constexpr bool HAS_BIAS = (MODE != 7);

    extern __shared__ __align__(16) char smem_raw[];
    fp16* sm = (fp16*)smem_raw;
    __shared__ int sSrc[BM];
    __shared__ int sDst[BM];

    const int tid = threadIdx.x;
    const int n0  = blockIdx.x * BN;
    const int m0  = blockIdx.y * BM;

    if constexpr (MODE==1 || MODE==2){
        if (tid < BM){
            if (MODE == 1) sSrc[tid] = g_ei[m0 + tid];
            sDst[tid] = g_ei[NE + m0 + tid];
        }
    }

    const int wid = tid >> 5, lane = tid & 31;
    const int wm  = wid >> 1, wn = wid & 1;   // 4x2 warp grid, 32x32 per warp
    const int g   = lane >> 2, t = lane & 3;

    float acc[2][4][4];
    #pragma unroll
    for (int a = 0; a < 2; a++)
        #pragma unroll
        for (int b = 0; b < 4; b++)
            #pragma unroll
            for (int c = 0; c < 4; c++) acc[a][b][c] = 0.f;

    const fp16 *Wh, *Wl;
    if      constexpr (MODE==1){ Wh = g_w1c_hi; Wl = g_w1c_lo; }
    else if constexpr (MODE==2){ Wh = g_w2t_hi; Wl = g_w2t_lo; }
    else if constexpr (MODE==3){ Wh = g_w3t_hi; Wl = g_w3t_lo; }
    else if constexpr (MODE==4){ Wh = g_w4t_hi; Wl = g_w4t_lo; }
    else {
        if (n0 < HID){ Wh = g_w1a_hi; Wl = g_w1a_lo; }
        else         { Wh = g_w1b_hi; Wl = g_w1b_lo; }
    }
    const int nW = (MODE==7 && n0 >= HID) ? (n0 - HID) : n0;

    auto load_chunk = [&](int kc, int st){
        const int k0 = kc * BK;
        fp16* stg = sm + st*STG;
        // A: 128x32 fp16 = 512 16B-chunks -> 2 per thread
        #pragma unroll
        for (int j = 0; j < 2; j++){
            int p = tid + j*256;
            int r = p >> 2, c = (p & 3) * 8;
            int k = k0 + c;
            const fp16 *pa;
            if constexpr (MODE==1){
                pa = g_ea + (size_t)(m0 + r)*ED + k;
            } else if constexpr (MODE==2){
                pa = g_h + (size_t)(m0 + r)*HID + k;
            } else if constexpr (MODE==3){
                int node = min(m0 + r, NN-1);
                if (k < HID) pa = g_x     + (size_t)node*HID + k;
                else         pa = g_agg_h + (size_t)node*HID + (k - HID);
            } else if constexpr (MODE==4){
                int node = min(m0 + r, NN-1);
                pa = g_u + (size_t)node*HID + k;
            } else {
                int node = min(m0 + r, NN-1);
                pa = g_x + (size_t)node*HID + k;
            }
            cp16(smem_u32(stg + r*BKP + c), pa);
        }
        // B: 64x32 per term
        {
            int r = tid >> 2, c = (tid & 3) * 8;
            size_t o = (size_t)(nW + r)*KTOT + k0 + c;
            cp16(smem_u32(stg + ASZ + 0 + r*BKP + c), Wh + o);
            if constexpr (TERMS == 2)
                cp16(smem_u32(stg + ASZ + BSZ + r*BKP + c), Wl + o);
        }
        CP_COMMIT();
    };

    load_chunk(0, 0);

    for (int kc = 0; kc < NCK; ++kc){
        const int st = kc & 1;
        if (kc + 1 < NCK){
            load_chunk(kc + 1, (kc + 1) & 1);
            CP_WAIT1();
        } else {
            CP_WAIT0();
        }
        __syncthreads();

        fp16* stg = sm + st*STG;
        fp16* sA  = stg;
        fp16* sBh = stg + ASZ;
        fp16* sBl = stg + ASZ + BSZ;

        #pragma unroll
        for (int ks = 0; ks < 2; ++ks){
            const int kk = ks * 16;
            unsigned af[2][4];
            #pragma unroll
            for (int mt = 0; mt < 2; ++mt){
                int row = wm*32 + mt*16 + (lane & 7) + ((lane >> 3) & 1) * 8;
                int col = kk + (lane >> 4) * 8;
                ldsm_x4(af[mt][0], af[mt][1], af[mt][2], af[mt][3],
                        smem_u32(sA + row*BKP + col));
            }
            unsigned bh[4][2], bl[4][2];
            #pragma unroll
            for (int np = 0; np < 2; ++np){
                int ntl = 2*np + (lane >> 4);
                int row = wn*32 + ntl*8 + (lane & 7);
                int col = kk + ((lane >> 3) & 1) * 8;
                unsigned r0, r1, r2, r3;
                ldsm_x4(r0, r1, r2, r3, smem_u32(sBh + row*BKP + col));
                bh[2*np][0]=r0; bh[2*np][1]=r1; bh[2*np+1][0]=r2; bh[2*np+1][1]=r3;
                if constexpr (TERMS == 2){
                    ldsm_x4(r0, r1, r2, r3, smem_u32(sBl + row*BKP + col));
                    bl[2*np][0]=r0; bl[2*np][1]=r1; bl[2*np+1][0]=r2; bl[2*np+1][1]=r3;
                }
            }
            #pragma unroll
            for (int mt = 0; mt < 2; ++mt)
                #pragma unroll
                for (int nt = 0; nt < 4; ++nt)
                    mma_f16(acc[mt][nt], af[mt][0], af[mt][1], af[mt][2], af[mt][3],
                            bh[nt][0], bh[nt][1]);                // A * Whi
            if constexpr (TERMS == 2){
                #pragma unroll
                for (int mt = 0; mt < 2; ++mt)
                    #pragma unroll
                    for (int nt = 0; nt < 4; ++nt)
                        mma_f16(acc[mt][nt], af[mt][0], af[mt][1], af[mt][2], af[mt][3],
                                bl[nt][0], bl[nt][1]);            // A * Wlo
            }
        }
        __syncthreads();
    }

    // ---- epilogue (acc carries 32x result; scale by WINV) ----
    #pragma unroll
    for (int mt = 0; mt < 2; ++mt){
        const int rl0 = wm*32 + mt*16 + g;
        const int rl1 = rl0 + 8;
        int s0 = 0, s1 = 0, d0 = 0, d1 = 0;
        if constexpr (MODE==1){ s0 = sSrc[rl0]; s1 = sSrc[rl1]; d0 = sDst[rl0]; d1 = sDst[rl1]; }
        if constexpr (MODE==2){ d0 = sDst[rl0]; d1 = sDst[rl1]; }
        #pragma unroll
        for (int nt = 0; nt < 4; ++nt){
            const int col = n0 + wn*32 + nt*8 + t*2;
            float bv0 = 0.f, bv1 = 0.f;
            if constexpr (HAS_BIAS){ bv0 = bias[col]; bv1 = bias[col+1]; }
            float v00 = acc[mt][nt][0]*WINV + bv0;
            float v01 = acc[mt][nt][1]*WINV + bv1;
            float v10 = acc[mt][nt][2]*WINV + bv0;
            float v11 = acc[mt][nt][3]*WINV + bv1;
            if constexpr (MODE==1){
                float2 p0 = *(const float2*)&g_P[(size_t)s0*HID + col];
                float2 q0 = *(const float2*)&g_Q[(size_t)d0*HID + col];
                float2 p1 = *(const float2*)&g_P[(size_t)s1*HID + col];
                float2 q1 = *(const float2*)&g_Q[(size_t)d1*HID + col];
                v00 = mishf(v00 + p0.x + q0.x);
                v01 = mishf(v01 + p0.y + q0.y);
                v10 = mishf(v10 + p1.x + q1.x);
                v11 = mishf(v11 + p1.y + q1.y);
                size_t o0 = (size_t)(m0+rl0)*HID + col;
                size_t o1 = (size_t)(m0+rl1)*HID + col;
                *(uint32_t*)&g_h[o0] = pack2h(__float2half(v00), __float2half(v01));
                *(uint32_t*)&g_h[o1] = pack2h(__float2half(v10), __float2half(v11));
            } else if constexpr (MODE==2){
                v00 = mishf(v00); v01 = mishf(v01); v10 = mishf(v10); v11 = mishf(v11);
                float p00 = __shfl_xor_sync(0xffffffffu, v00, 1);
                float p01 = __shfl_xor_sync(0xffffffffu, v01, 1);
                float p10 = __shfl_xor_sync(0xffffffffu, v10, 1);
                float p11 = __shfl_xor_sync(0xffffffffu, v11, 1);
                if ((t & 1) == 0){
                    atomicAdd((float4*)&g_agg[(size_t)d0*HID + col], make_float4(v00, v01, p00, p01));
                    atomicAdd((float4*)&g_agg[(size_t)d1*HID + col], make_float4(v10, v11, p10, p11));
                }
            } else if constexpr (MODE==3){
                const int r0i = m0 + rl0, r1i = m0 + rl1;
                if (r0i < NN){
                    size_t o = (size_t)r0i*HID + col;
                    *(uint32_t*)&g_u[o] = pack2h(__float2half(mishf(v00)), __float2half(mishf(v01)));
                }
                if (r1i < NN){
                    size_t o = (size_t)r1i*HID + col;
                    *(uint32_t*)&g_u[o] = pack2h(__float2half(mishf(v10)), __float2half(mishf(v11)));
                }
            } else if constexpr (MODE==4){
                const int r0i = m0 + rl0, r1i = m0 + rl1;
                if (r0i < NN){
                    float2 xv = *(const float2*)&xres[(size_t)r0i*HID + col];
                    *(float2*)&g_y[(size_t)r0i*HID + col] = make_float2(v00 + xv.x, v01 + xv.y);
                }
                if (r1i < NN){
                    float2 xv = *(const float2*)&xres[(size_t)r1i*HID + col];
                    *(float2*)&g_y[(size_t)r1i*HID + col] = make_float2(v10 + xv.x, v11 + xv.y);
                }
            } else { // MODE 7
                float* dst = (n0 < HID) ? g_P : g_Q;
                const int cw = nW + wn*32 + nt*8 + t*2;
                const int r0i = m0 + rl0, r1i = m0 + rl1;
                if (r0i < NN)
                    *(float2*)&dst[(size_t)r0i*HID + cw] = make_float2(v00, v01);
                if (r1i < NN)
                    *(float2*)&dst[(size_t)r1i*HID + cw] = make_float2(v10, v11);
            }
        }
    }
}

// ---------------- LayerNorm ----------------
__global__ __launch_bounds__(128)
void ln_kernel(const float* __restrict__ gamma, const float* __restrict__ beta,
               float* __restrict__ out)
{
    const int row = blockIdx.x, tid = threadIdx.x;
    float4 v = *((const float4*)(g_y + (size_t)row*HID) + tid);
    float s  = v.x + v.y + v.z + v.w;
    float ss = fmaf(v.x, v.x, fmaf(v.y, v.y, fmaf(v.z, v.z, v.w*v.w)));
    #pragma unroll
    for (int o = 16; o > 0; o >>= 1){
        s  += __shfl_xor_sync(0xffffffffu, s,  o);
        ss += __shfl_xor_sync(0xffffffffu, ss, o);
    }
    __shared__ float sh_s[4], sh_ss[4];
    if ((tid & 31) == 0){ sh_s[tid >> 5] = s; sh_ss[tid >> 5] = ss; }
    __syncthreads();
    s  = sh_s[0]  + sh_s[1]  + sh_s[2]  + sh_s[3];
    ss = sh_ss[0] + sh_ss[1] + sh_ss[2] + sh_ss[3];
    const float mu  = s * (1.f / HID);
    const float var = ss * (1.f / HID) - mu * mu;
    const float inv = rsqrtf(var + 1e-5f);
    float4 gm = ((const float4*)gamma)[tid];
    float4 bt = ((const float4*)beta)[tid];
    float4 o;
    o.x = (v.x - mu) * inv * gm.x + bt.x;
    o.y = (v.y - mu) * inv * gm.y + bt.y;
    o.z = (v.z - mu) * inv * gm.z + bt.z;
    o.w = (v.w - mu) * inv * gm.w + bt.w;
    *((float4*)(out + (size_t)row*HID) + tid) = o;
}

// ---------------- launch ----------------
extern "C" void kernel_launch(void* const* d_in, const int* in_sizes, int n_in,
                              void* d_out, int out_size)
{
    (void)in_sizes; (void)n_in; (void)out_size;
    const float* x     = (const float*)d_in[0];
    const void*  ei    = d_in[1];
    const float* ea    = (const float*)d_in[2];
    const float* W1    = (const float*)d_in[3];
    const float* b1    = (const float*)d_in[4];
    const float* W2    = (const float*)d_in[5];
    const float* b2    = (const float*)d_in[6];
    const float* W3    = (const float*)d_in[7];
    const float* b3    = (const float*)d_in[8];
    const float* W4    = (const float*)d_in[9];
    const float* b4    = (const float*)d_in[10];
    const float* gamma = (const float*)d_in[11];
    const float* beta  = (const float*)d_in[12];
    float* out = (float*)d_out;

    cudaFuncSetAttribute(gemm_kernel<1>, cudaFuncAttributeMaxDynamicSharedMemorySize, SMEM_BYTES);
    cudaFuncSetAttribute(gemm_kernel<2>, cudaFuncAttributeMaxDynamicSharedMemorySize, SMEM_BYTES);
    cudaFuncSetAttribute(gemm_kernel<3>, cudaFuncAttributeMaxDynamicSharedMemorySize, SMEM_BYTES);
    cudaFuncSetAttribute(gemm_kernel<4>, cudaFuncAttributeMaxDynamicSharedMemorySize, SMEM_BYTES);
    cudaFuncSetAttribute(gemm_kernel<7>, cudaFuncAttributeMaxDynamicSharedMemorySize, SMEM_BYTES);

    k_split_all  <<<(SPLIT_ALL_TOT + 255)/256, 256>>>(x, W1, W2, W3, W4);   // 1
    k_split_ea   <<<(NE*ED + 255)/256, 256>>>(ea);                          // 2
    k_decode_zero<<<(NN*HID + 255)/256, 256>>>(ei);                         // 3

    dim3 gPQ(2*HID/BN, (NN + BM - 1)/BM);    // (16, 157)
    dim3 gE(HID/BN, NE/BM);                  // (8, 2500)
    dim3 gN(HID/BN, (NN + BM - 1)/BM);       // (8, 157)
    gemm_kernel<7><<<gPQ, 256, SMEM_BYTES>>>(nullptr, nullptr);  // 4: P|Q
    gemm_kernel<1><<<gE, 256, SMEM_BYTES>>>(b1, nullptr);        // 5: h
    gemm_kernel<2><<<gE, 256, SMEM_BYTES>>>(b2, nullptr);        // 6: messages+scatter  <- ncu
    k_split_agg  <<<(NN*HID + 255)/256, 256>>>();                // 7
    gemm_kernel<3><<<gN, 256, SMEM_BYTES>>>(b3, nullptr);        // 8: u
    gemm_kernel<4><<<gN, 256, SMEM_BYTES>>>(b4, x);              // 9: y
    ln_kernel<<<NN, 128>>>(gamma, beta, out);                    // 10
}

// round 11
// speedup vs baseline: 4.1790x; 1.1222x over previous
#include <cuda_runtime.h>
#include <cuda_fp16.h>
#include <math.h>
#include <stdint.h>

using fp16 = __half;

constexpr int NN  = 20000;      // nodes
constexpr int NE  = 320000;     // edges
constexpr int HID = 512;
constexpr int ED  = 64;
constexpr int KC3 = 2*HID;      // 1024

constexpr int BM = 128, BN = 128, BK = 32, PAD = 8, BKP = BK + PAD;

constexpr int ASZ = BM*BKP;             // A tile
constexpr int BSZ = BN*BKP;             // B tile (per term)
constexpr int STG = ASZ + 2*BSZ;
constexpr int SMEM_BYTES = 2*STG*(int)sizeof(fp16);   // 61440

constexpr float WSC  = 32.0f;           // weight pre-scale (keeps Wlo normal-range fp16)
constexpr float WINV = 1.0f/32.0f;

// ---------------- device scratch ----------------
__device__ fp16 g_x[NN*HID];
__device__ fp16 g_ea[NE*ED];
__device__ fp16 g_w1a_hi[HID*HID], g_w1a_lo[HID*HID];
__device__ fp16 g_w1b_hi[HID*HID], g_w1b_lo[HID*HID];
__device__ fp16 g_w1c_hi[HID*ED],  g_w1c_lo[HID*ED];
__device__ fp16 g_w2t_hi[HID*HID], g_w2t_lo[HID*HID];
__device__ fp16 g_w3t_hi[HID*KC3], g_w3t_lo[HID*KC3];
__device__ fp16 g_w4t_hi[HID*HID], g_w4t_lo[HID*HID];
__device__ int   g_ei[2*NE];
__device__ float g_P[NN*HID];
__device__ float g_Q[NN*HID];
__device__ fp16  g_h[(size_t)NE*HID];
__device__ float g_agg[NN*HID];
__device__ fp16  g_agg_h[NN*HID];
__device__ fp16  g_u[NN*HID];
__device__ float g_y[NN*HID];

// ---------------- helpers ----------------
__device__ __forceinline__ float mishf(float x){
    float t   = __expf(fminf(x, 15.f));
    float num = t * (t + 2.f);
    return x * __fdividef(num, num + 2.f);
}
__device__ __forceinline__ unsigned smem_u32(const void* p){
    return (unsigned)__cvta_generic_to_shared(p);
}
__device__ __forceinline__ void ldsm_x4(unsigned &r0, unsigned &r1, unsigned &r2, unsigned &r3, unsigned addr){
    asm volatile("ldmatrix.sync.aligned.m8n8.x4.shared.b16 {%0,%1,%2,%3}, [%4];"
                 : "=r"(r0), "=r"(r1), "=r"(r2), "=r"(r3) : "r"(addr));
}
__device__ __forceinline__ void mma_f16(float* c, unsigned a0, unsigned a1, unsigned a2, unsigned a3,
                                        unsigned b0, unsigned b1){
    asm volatile("mma.sync.aligned.m16n8k16.row.col.f32.f16.f16.f32 "
                 "{%0,%1,%2,%3}, {%4,%5,%6,%7}, {%8,%9}, {%0,%1,%2,%3};"
                 : "+f"(c[0]), "+f"(c[1]), "+f"(c[2]), "+f"(c[3])
                 : "r"(a0), "r"(a1), "r"(a2), "r"(a3), "r"(b0), "r"(b1));
}
__device__ __forceinline__ void splitw(float v, fp16 &h, fp16 &l){
    h = __float2half(v);
    l = __float2half(v - __half2float(h));
}
__device__ __forceinline__ uint32_t pack2h(fp16 a, fp16 b){
    __half2 p; p.x = a; p.y = b;
    return *(uint32_t*)&p;
}
__device__ __forceinline__ void cp16(uint32_t dst, const void* src){
    asm volatile("cp.async.cg.shared.global [%0], [%1], 16;" :: "r"(dst), "l"(src));
}
#define CP_COMMIT() asm volatile("cp.async.commit_group;" ::: "memory")
#define CP_WAIT1()  asm volatile("cp.async.wait_group 1;" ::: "memory")
#define CP_WAIT0()  asm volatile("cp.async.wait_group 0;" ::: "memory")

// ---------------- prep kernels (fused) ----------------
constexpr int NX   = NN*HID;
constexpr int NW1A = HID*HID;
constexpr int NW1B = HID*HID;
constexpr int NW1C = ED*HID;
constexpr int NW2  = HID*HID;
constexpr int NW3  = KC3*HID;
constexpr int NW4  = HID*HID;
constexpr int SPLIT_ALL_TOT = NX + NW1A + NW1B + NW1C + NW2 + NW3 + NW4;

__global__ void k_split_all(const float* __restrict__ x,
                            const float* __restrict__ W1,
                            const float* __restrict__ W2,
                            const float* __restrict__ W3,
                            const float* __restrict__ W4){
    int i = blockIdx.x * blockDim.x + threadIdx.x;
    if (i >= SPLIT_ALL_TOT) return;
    if (i < NX){
        g_x[i] = __float2half(x[i]);
        return;
    }
    i -= NX;
    const float* src; fp16 *hi, *lo; int K;
    if      (i < NW1A){                              src = W1;                     hi=g_w1a_hi; lo=g_w1a_lo; K=HID; }
    else if ((i -= NW1A) < NW1B){                    src = W1 + (size_t)HID*HID;   hi=g_w1b_hi; lo=g_w1b_lo; K=HID; }
    else if ((i -= NW1B) < NW1C){                    src = W1 + (size_t)2*HID*HID; hi=g_w1c_hi; lo=g_w1c_lo; K=ED; }
    else if ((i -= NW1C) < NW2){                     src = W2;                     hi=g_w2t_hi; lo=g_w2t_lo; K=HID; }
    else if ((i -= NW2)  < NW3){                     src = W3;                     hi=g_w3t_hi; lo=g_w3t_lo; K=KC3; }
    else { i -= NW3;                                 src = W4;                     hi=g_w4t_hi; lo=g_w4t_lo; K=HID; }
    int k = i / HID, n = i % HID;
    fp16 h, l; splitw(src[i] * WSC, h, l);
    hi[(size_t)n*K + k] = h;
    lo[(size_t)n*K + k] = l;
}
__global__ void k_split_ea(const float* __restrict__ s){
    int i = blockIdx.x * blockDim.x + threadIdx.x;
    if (i < NE*ED) g_ea[i] = __float2half(s[i]);
}
// decode edge_index (int64 vs int32 defensive) + zero agg
__global__ void k_decode_zero(const void* __restrict__ ei_raw){
    int i = blockIdx.x * blockDim.x + threadIdx.x;
    if (i < 2*NE){
        const long long* p64 = (const long long*)ei_raw;
        bool is64 = true;
        #pragma unroll
        for (int j = 0; j < 4; j++){
            long long v = p64[j];
            if (v < 0 || v >= NN) is64 = false;
        }
        g_ei[i] = is64 ? (int)p64[i] : ((const int*)ei_raw)[i];
    }
    if (i < NN*HID) g_agg[i] = 0.f;
}
__global__ void k_split_agg(){
    int i = blockIdx.x * blockDim.x + threadIdx.x;
    if (i < NN*HID) g_agg_h[i] = __float2half(g_agg[i]);
}

// ---------------- fp16 GEMM, BN=128 (warp tile 32x64) ----------------
// MODE 7: [P|Q] = x @ [W1a|W1b]                      (2-term W split)
// MODE 1: h = mish(ea@W1c + P[src] + Q[dst] + b1)    (1-term)
// MODE 2: msg = mish(h @ W2 + b2); RED scatter       (1-term)
// MODE 3: u = mish([x|agg_h] @ W3 + b3)              (2-term)
// MODE 4: y = x + u @ W4 + b4                        (2-term)
template<int MODE>
__global__ __launch_bounds__(256, 2)
void gemm_kernel(const float* __restrict__ bias, const float* __restrict__ xres)
{
    constexpr int KTOT  = (MODE==1) ? ED : (MODE==3) ? KC3 : HID;
    constexpr int NCK   = KTOT / BK;
    constexpr int TERMS = (MODE==1 || MODE==2) ? 1 : 2;
    constexpr bool HAS_BIAS = (MODE != 7);

    extern __shared__ __align__(16) char smem_raw[];
    fp16* sm = (fp16*)smem_raw;
    __shared__ int sSrc[BM];
    __shared__ int sDst[BM];

    const int tid = threadIdx.x;
    const int n0  = blockIdx.x * BN;
    const int m0  = blockIdx.y * BM;

    if constexpr (MODE==1 || MODE==2){
        if (tid < BM){
            if (MODE == 1) sSrc[tid] = g_ei[m0 + tid];
            sDst[tid] = g_ei[NE + m0 + tid];
        }
    }

    const int wid = tid >> 5, lane = tid & 31;
    const int wm  = wid >> 1, wn = wid & 1;   // 4x2 warp grid, warp tile 32x64
    const int g   = lane >> 2, t = lane & 3;

    float acc[2][8][4];
    #pragma unroll
    for (int a = 0; a < 2; a++)
        #pragma unroll
        for (int b = 0; b < 8; b++)
            #pragma unroll
            for (int c = 0; c < 4; c++) acc[a][b][c] = 0.f;

    const fp16 *Wh, *Wl;
    if      constexpr (MODE==1){ Wh = g_w1c_hi; Wl = g_w1c_lo; }
    else if constexpr (MODE==2){ Wh = g_w2t_hi; Wl = g_w2t_lo; }
    else if constexpr (MODE==3){ Wh = g_w3t_hi; Wl = g_w3t_lo; }
    else if constexpr (MODE==4){ Wh = g_w4t_hi; Wl = g_w4t_lo; }
    else {
        if (n0 < HID){ Wh = g_w1a_hi; Wl = g_w1a_lo; }
        else         { Wh = g_w1b_hi; Wl = g_w1b_lo; }
    }
    const int nW = (MODE==7 && n0 >= HID) ? (n0 - HID) : n0;

    auto load_chunk = [&](int kc, int st){
        const int k0 = kc * BK;
        fp16* stg = sm + st*STG;
        // A: 128x32 fp16 = 512 16B-chunks -> 2 per thread
        #pragma unroll
        for (int j = 0; j < 2; j++){
            int p = tid + j*256;
            int r = p >> 2, c = (p & 3) * 8;
            int k = k0 + c;
            const fp16 *pa;
            if constexpr (MODE==1){
                pa = g_ea + (size_t)(m0 + r)*ED + k;
            } else if constexpr (MODE==2){
                pa = g_h + (size_t)(m0 + r)*HID + k;
            } else if constexpr (MODE==3){
                int node = min(m0 + r, NN-1);
                if (k < HID) pa = g_x     + (size_t)node*HID + k;
                else         pa = g_agg_h + (size_t)node*HID + (k - HID);
            } else if constexpr (MODE==4){
                int node = min(m0 + r, NN-1);
                pa = g_u + (size_t)node*HID + k;
            } else {
                int node = min(m0 + r, NN-1);
                pa = g_x + (size_t)node*HID + k;
            }
            cp16(smem_u32(stg + r*BKP + c), pa);
        }
        // B: 128x32 per term = 512 chunks -> 2 per thread per term
        #pragma unroll
        for (int j = 0; j < 2; j++){
            int p = tid + j*256;
            int r = p >> 2, c = (p & 3) * 8;
            size_t o = (size_t)(nW + r)*KTOT + k0 + c;
            cp16(smem_u32(stg + ASZ + 0 + r*BKP + c), Wh + o);
            if constexpr (TERMS == 2)
                cp16(smem_u32(stg + ASZ + BSZ + r*BKP + c), Wl + o);
        }
        CP_COMMIT();
    };

    load_chunk(0, 0);

    for (int kc = 0; kc < NCK; ++kc){
        const int st = kc & 1;
        if (kc + 1 < NCK){
            load_chunk(kc + 1, (kc + 1) & 1);
            CP_WAIT1();
        } else {
            CP_WAIT0();
        }
        __syncthreads();

        fp16* stg = sm + st*STG;
        fp16* sA  = stg;
        fp16* sBh = stg + ASZ;
        fp16* sBl = stg + ASZ + BSZ;

        #pragma unroll
        for (int ks = 0; ks < 2; ++ks){
            const int kk = ks * 16;
            unsigned af[2][4];
            #pragma unroll
            for (int mt = 0; mt < 2; ++mt){
                int row = wm*32 + mt*16 + (lane & 7) + ((lane >> 3) & 1) * 8;
                int col = kk + (lane >> 4) * 8;
                ldsm_x4(af[mt][0], af[mt][1], af[mt][2], af[mt][3],
                        smem_u32(sA + row*BKP + col));
            }
            unsigned bf[8][2];
            #pragma unroll
            for (int np = 0; np < 4; ++np){
                int ntl = 2*np + (lane >> 4);
                int row = wn*64 + ntl*8 + (lane & 7);
                int col = kk + ((lane >> 3) & 1) * 8;
                unsigned r0, r1, r2, r3;
                ldsm_x4(r0, r1, r2, r3, smem_u32(sBh + row*BKP + col));
                bf[2*np][0]=r0; bf[2*np][1]=r1; bf[2*np+1][0]=r2; bf[2*np+1][1]=r3;
            }
            #pragma unroll
            for (int mt = 0; mt < 2; ++mt)
                #pragma unroll
                for (int nt = 0; nt < 8; ++nt)
                    mma_f16(acc[mt][nt], af[mt][0], af[mt][1], af[mt][2], af[mt][3],
                            bf[nt][0], bf[nt][1]);                // A * Whi
            if constexpr (TERMS == 2){
                // reuse bf registers for the Wlo fragments
                #pragma unroll
                for (int np = 0; np < 4; ++np){
                    int ntl = 2*np + (lane >> 4);
                    int row = wn*64 + ntl*8 + (lane & 7);
                    int col = kk + ((lane >> 3) & 1) * 8;
                    unsigned r0, r1, r2, r3;
                    ldsm_x4(r0, r1, r2, r3, smem_u32(sBl + row*BKP + col));
                    bf[2*np][0]=r0; bf[2*np][1]=r1; bf[2*np+1][0]=r2; bf[2*np+1][1]=r3;
                }
                #pragma unroll
                for (int mt = 0; mt < 2; ++mt)
                    #pragma unroll
                    for (int nt = 0; nt < 8; ++nt)
                        mma_f16(acc[mt][nt], af[mt][0], af[mt][1], af[mt][2], af[mt][3],
                                bf[nt][0], bf[nt][1]);            // A * Wlo
            }
        }
        __syncthreads();
    }

    // ---- epilogue (scale by WINV) ----
    #pragma unroll
    for (int mt = 0; mt < 2; ++mt){
        const int rl0 = wm*32 + mt*16 + g;
        const int rl1 = rl0 + 8;
        int s0 = 0, s1 = 0, d0 = 0, d1 = 0;
        if constexpr (MODE==1){ s0 = sSrc[rl0]; s1 = sSrc[rl1]; d0 = sDst[rl0]; d1 = sDst[rl1]; }
        if constexpr (MODE==2){ d0 = sDst[rl0]; d1 = sDst[rl1]; }
        #pragma unroll
        for (int nt = 0; nt < 8; ++nt){
            const int col = n0 + wn*64 + nt*8 + t*2;
            float bv0 = 0.f, bv1 = 0.f;
            if constexpr (HAS_BIAS){ bv0 = bias[col]; bv1 = bias[col+1]; }
            float v00 = acc[mt][nt][0]*WINV + bv0;
            float v01 = acc[mt][nt][1]*WINV + bv1;
            float v10 = acc[mt][nt][2]*WINV + bv0;
            float v11 = acc[mt][nt][3]*WINV + bv1;
            if constexpr (MODE==1){
                float2 p0 = *(const float2*)&g_P[(size_t)s0*HID + col];
                float2 q0 = *(const float2*)&g_Q[(size_t)d0*HID + col];
                float2 p1 = *(const float2*)&g_P[(size_t)s1*HID + col];
                float2 q1 = *(const float2*)&g_Q[(size_t)d1*HID + col];
                v00 = mishf(v00 + p0.x + q0.x);
                v01 = mishf(v01 + p0.y + q0.y);
                v10 = mishf(v10 + p1.x + q1.x);
                v11 = mishf(v11 + p1.y + q1.y);
                size_t o0 = (size_t)(m0+rl0)*HID + col;
                size_t o1 = (size_t)(m0+rl1)*HID + col;
                *(uint32_t*)&g_h[o0] = pack2h(__float2half(v00), __float2half(v01));
                *(uint32_t*)&g_h[o1] = pack2h(__float2half(v10), __float2half(v11));
            } else if constexpr (MODE==2){
                v00 = mishf(v00); v01 = mishf(v01); v10 = mishf(v10); v11 = mishf(v11);
                float p00 = __shfl_xor_sync(0xffffffffu, v00, 1);
                float p01 = __shfl_xor_sync(0xffffffffu, v01, 1);
                float p10 = __shfl_xor_sync(0xffffffffu, v10, 1);
                float p11 = __shfl_xor_sync(0xffffffffu, v11, 1);
                if ((t & 1) == 0){
                    atomicAdd((float4*)&g_agg[(size_t)d0*HID + col], make_float4(v00, v01, p00, p01));
                    atomicAdd((float4*)&g_agg[(size_t)d1*HID + col], make_float4(v10, v11, p10, p11));
                }
            } else if constexpr (MODE==3){
                const int r0i = m0 + rl0, r1i = m0 + rl1;
                if (r0i < NN){
                    size_t o = (size_t)r0i*HID + col;
                    *(uint32_t*)&g_u[o] = pack2h(__float2half(mishf(v00)), __float2half(mishf(v01)));
                }
                if (r1i < NN){
                    size_t o = (size_t)r1i*HID + col;
                    *(uint32_t*)&g_u[o] = pack2h(__float2half(mishf(v10)), __float2half(mishf(v11)));
                }
            } else if constexpr (MODE==4){
                const int r0i = m0 + rl0, r1i = m0 + rl1;
                if (r0i < NN){
                    float2 xv = *(const float2*)&xres[(size_t)r0i*HID + col];
                    *(float2*)&g_y[(size_t)r0i*HID + col] = make_float2(v00 + xv.x, v01 + xv.y);
                }
                if (r1i < NN){
                    float2 xv = *(const float2*)&xres[(size_t)r1i*HID + col];
                    *(float2*)&g_y[(size_t)r1i*HID + col] = make_float2(v10 + xv.x, v11 + xv.y);
                }
            } else { // MODE 7
                float* dst = (n0 < HID) ? g_P : g_Q;
                const int cw = nW + wn*64 + nt*8 + t*2;
                const int r0i = m0 + rl0, r1i = m0 + rl1;
                if (r0i < NN)
                    *(float2*)&dst[(size_t)r0i*HID + cw] = make_float2(v00, v01);
                if (r1i < NN)
                    *(float2*)&dst[(size_t)r1i*HID + cw] = make_float2(v10, v11);
            }
        }
    }
}

// ---------------- LayerNorm ----------------
__global__ __launch_bounds__(128)
void ln_kernel(const float* __restrict__ gamma, const float* __restrict__ beta,
               float* __restrict__ out)
{
    const int row = blockIdx.x, tid = threadIdx.x;
    float4 v = *((const float4*)(g_y + (size_t)row*HID) + tid);
    float s  = v.x + v.y + v.z + v.w;
    float ss = fmaf(v.x, v.x, fmaf(v.y, v.y, fmaf(v.z, v.z, v.w*v.w)));
    #pragma unroll
    for (int o = 16; o > 0; o >>= 1){
        s  += __shfl_xor_sync(0xffffffffu, s,  o);
        ss += __shfl_xor_sync(0xffffffffu, ss, o);
    }
    __shared__ float sh_s[4], sh_ss[4];
    if ((tid & 31) == 0){ sh_s[tid >> 5] = s; sh_ss[tid >> 5] = ss; }
    __syncthreads();
    s  = sh_s[0]  + sh_s[1]  + sh_s[2]  + sh_s[3];
    ss = sh_ss[0] + sh_ss[1] + sh_ss[2] + sh_ss[3];
    const float mu  = s * (1.f / HID);
    const float var = ss * (1.f / HID) - mu * mu;
    const float inv = rsqrtf(var + 1e-5f);
    float4 gm = ((const float4*)gamma)[tid];
    float4 bt = ((const float4*)beta)[tid];
    float4 o;
    o.x = (v.x - mu) * inv * gm.x + bt.x;
    o.y = (v.y - mu) * inv * gm.y + bt.y;
    o.z = (v.z - mu) * inv * gm.z + bt.z;
    o.w = (v.w - mu) * inv * gm.w + bt.w;
    *((float4*)(out + (size_t)row*HID) + tid) = o;
}

// ---------------- launch ----------------
extern "C" void kernel_launch(void* const* d_in, const int* in_sizes, int n_in,
                              void* d_out, int out_size)
{
    (void)in_sizes; (void)n_in; (void)out_size;
    const float* x     = (const float*)d_in[0];
    const void*  ei    = d_in[1];
    const float* ea    = (const float*)d_in[2];
    const float* W1    = (const float*)d_in[3];
    const float* b1    = (const float*)d_in[4];
    const float* W2    = (const float*)d_in[5];
    const float* b2    = (const float*)d_in[6];
    const float* W3    = (const float*)d_in[7];
    const float* b3    = (const float*)d_in[8];
    const float* W4    = (const float*)d_in[9];
    const float* b4    = (const float*)d_in[10];
    const float* gamma = (const float*)d_in[11];
    const float* beta  = (const float*)d_in[12];
    float* out = (float*)d_out;

    cudaFuncSetAttribute(gemm_kernel<1>, cudaFuncAttributeMaxDynamicSharedMemorySize, SMEM_BYTES);
    cudaFuncSetAttribute(gemm_kernel<2>, cudaFuncAttributeMaxDynamicSharedMemorySize, SMEM_BYTES);
    cudaFuncSetAttribute(gemm_kernel<3>, cudaFuncAttributeMaxDynamicSharedMemorySize, SMEM_BYTES);
    cudaFuncSetAttribute(gemm_kernel<4>, cudaFuncAttributeMaxDynamicSharedMemorySize, SMEM_BYTES);
    cudaFuncSetAttribute(gemm_kernel<7>, cudaFuncAttributeMaxDynamicSharedMemorySize, SMEM_BYTES);

    k_split_all  <<<(SPLIT_ALL_TOT + 255)/256, 256>>>(x, W1, W2, W3, W4);   // 1
    k_split_ea   <<<(NE*ED + 255)/256, 256>>>(ea);                          // 2
    k_decode_zero<<<(NN*HID + 255)/256, 256>>>(ei);                         // 3

    dim3 gPQ(2*HID/BN, (NN + BM - 1)/BM);    // (8, 157)
    dim3 gE(HID/BN, NE/BM);                  // (4, 2500)
    dim3 gN(HID/BN, (NN + BM - 1)/BM);       // (4, 157)
    gemm_kernel<7><<<gPQ, 256, SMEM_BYTES>>>(nullptr, nullptr);  // 4: P|Q
    gemm_kernel<1><<<gE, 256, SMEM_BYTES>>>(b1, nullptr);        // 5: h
    gemm_kernel<2><<<gE, 256, SMEM_BYTES>>>(b2, nullptr);        // 6: messages+scatter  <- ncu
    k_split_agg  <<<(NN*HID + 255)/256, 256>>>();                // 7
    gemm_kernel<3><<<gN, 256, SMEM_BYTES>>>(b3, nullptr);        // 8: u
    gemm_kernel<4><<<gN, 256, SMEM_BYTES>>>(b4, x);              // 9: y
    ln_kernel<<<NN, 128>>>(gamma, beta, out);                    // 10
}

// round 13
// speedup vs baseline: 4.6362x; 1.1094x over previous
#include <cuda_runtime.h>
#include <cuda_fp16.h>
#include <math.h>
#include <stdint.h>

using fp16 = __half;

constexpr int NN  = 20000;      // nodes
constexpr int NE  = 320000;     // edges
constexpr int HID = 512;
constexpr int ED  = 64;
constexpr int KC3 = 2*HID;      // 1024

constexpr int BM = 128, BN = 128, BK = 32, PAD = 8, BKP = BK + PAD;

constexpr int ASZ = BM*BKP;             // A tile
constexpr int BSZ = BN*BKP;             // B tile
constexpr int STG = ASZ + BSZ;          // per-stage elements
constexpr int NSTAGE = 3;
constexpr int SMEM_BYTES = NSTAGE*STG*(int)sizeof(fp16);   // 61440

constexpr float WSC  = 32.0f;           // weight pre-scale (power of 2, exact)
constexpr float WINV = 1.0f/32.0f;

// ---------------- device scratch ----------------
__device__ fp16 g_x[NN*HID];
__device__ fp16 g_ea[NE*ED];
__device__ fp16 g_w1a[HID*HID];
__device__ fp16 g_w1b[HID*HID];
__device__ fp16 g_w1c[HID*ED];
__device__ fp16 g_w2t[HID*HID];
__device__ fp16 g_w3t[HID*KC3];
__device__ fp16 g_w4t[HID*HID];
__device__ int   g_ei[2*NE];
__device__ float g_P[NN*HID];
__device__ float g_Q[NN*HID];
__device__ fp16  g_h[(size_t)NE*HID];
__device__ float g_agg[NN*HID];
__device__ fp16  g_agg_h[NN*HID];
__device__ fp16  g_u[NN*HID];
__device__ float g_y[NN*HID];

// ---------------- helpers ----------------
__device__ __forceinline__ float mishf(float x){
    float t   = __expf(fminf(x, 15.f));
    float num = t * (t + 2.f);
    return x * __fdividef(num, num + 2.f);
}
__device__ __forceinline__ unsigned smem_u32(const void* p){
    return (unsigned)__cvta_generic_to_shared(p);
}
__device__ __forceinline__ void ldsm_x4(unsigned &r0, unsigned &r1, unsigned &r2, unsigned &r3, unsigned addr){
    asm volatile("ldmatrix.sync.aligned.m8n8.x4.shared.b16 {%0,%1,%2,%3}, [%4];"
                 : "=r"(r0), "=r"(r1), "=r"(r2), "=r"(r3) : "r"(addr));
}
__device__ __forceinline__ void mma_f16(float* c, unsigned a0, unsigned a1, unsigned a2, unsigned a3,
                                        unsigned b0, unsigned b1){
    asm volatile("mma.sync.aligned.m16n8k16.row.col.f32.f16.f16.f32 "
                 "{%0,%1,%2,%3}, {%4,%5,%6,%7}, {%8,%9}, {%0,%1,%2,%3};"
                 : "+f"(c[0]), "+f"(c[1]), "+f"(c[2]), "+f"(c[3])
                 : "r"(a0), "r"(a1), "r"(a2), "r"(a3), "r"(b0), "r"(b1));
}
__device__ __forceinline__ uint32_t pack2h(fp16 a, fp16 b){
    __half2 p; p.x = a; p.y = b;
    return *(uint32_t*)&p;
}
__device__ __forceinline__ void cp16(uint32_t dst, const void* src){
    asm volatile("cp.async.cg.shared.global [%0], [%1], 16;" :: "r"(dst), "l"(src));
}
#define CP_COMMIT() asm volatile("cp.async.commit_group;" ::: "memory")
#define CP_WAIT1()  asm volatile("cp.async.wait_group 1;" ::: "memory")
#define CP_WAIT0()  asm volatile("cp.async.wait_group 0;" ::: "memory")

// ---------------- prep kernels (fused) ----------------
constexpr int NX   = NN*HID;
constexpr int NW1A = HID*HID;
constexpr int NW1B = HID*HID;
constexpr int NW1C = ED*HID;
constexpr int NW2  = HID*HID;
constexpr int NW3  = KC3*HID;
constexpr int NW4  = HID*HID;
constexpr int SPLIT_ALL_TOT = NX + NW1A + NW1B + NW1C + NW2 + NW3 + NW4;

__global__ void k_split_all(const float* __restrict__ x,
                            const float* __restrict__ W1,
                            const float* __restrict__ W2,
                            const float* __restrict__ W3,
                            const float* __restrict__ W4){
    int i = blockIdx.x * blockDim.x + threadIdx.x;
    if (i >= SPLIT_ALL_TOT) return;
    if (i < NX){
        g_x[i] = __float2half(x[i]);
        return;
    }
    i -= NX;
    const float* src; fp16 *w; int K;
    if      (i < NW1A){                              src = W1;                     w=g_w1a; K=HID; }
    else if ((i -= NW1A) < NW1B){                    src = W1 + (size_t)HID*HID;   w=g_w1b; K=HID; }
    else if ((i -= NW1B) < NW1C){                    src = W1 + (size_t)2*HID*HID; w=g_w1c; K=ED; }
    else if ((i -= NW1C) < NW2){                     src = W2;                     w=g_w2t; K=HID; }
    else if ((i -= NW2)  < NW3){                     src = W3;                     w=g_w3t; K=KC3; }
    else { i -= NW3;                                 src = W4;                     w=g_w4t; K=HID; }
    int k = i / HID, n = i % HID;
    w[(size_t)n*K + k] = __float2half(src[i] * WSC);
}
__global__ void k_split_ea(const float* __restrict__ s){
    int i = blockIdx.x * blockDim.x + threadIdx.x;
    if (i < NE*ED) g_ea[i] = __float2half(s[i]);
}
// decode edge_index (int64 vs int32 defensive) + zero agg
__global__ void k_decode_zero(const void* __restrict__ ei_raw){
    int i = blockIdx.x * blockDim.x + threadIdx.x;
    if (i < 2*NE){
        const long long* p64 = (const long long*)ei_raw;
        bool is64 = true;
        #pragma unroll
        for (int j = 0; j < 4; j++){
            long long v = p64[j];
            if (v < 0 || v >= NN) is64 = false;
        }
        g_ei[i] = is64 ? (int)p64[i] : ((const int*)ei_raw)[i];
    }
    if (i < NN*HID) g_agg[i] = 0.f;
}
__global__ void k_split_agg(){
    int i = blockIdx.x * blockDim.x + threadIdx.x;
    if (i < NN*HID) g_agg_h[i] = __float2half(g_agg[i]);
}

// ---------------- fp16 GEMM, BN=128, 3-stage cp.async, 1 sync/chunk ----------------
// MODE 7: [P|Q] = x @ [W1a|W1b]
// MODE 1: h = mish(ea@W1c + P[src] + Q[dst] + b1)
// MODE 2: msg = mish(h @ W2 + b2); float4 RED scatter into agg[dst]
// MODE 3: u = mish([x|agg_h] @ W3 + b3)
// MODE 4: y = x + u @ W4 + b4
template<int MODE>
__global__ __launch_bounds__(256, 2)
void gemm_kernel(const float* __restrict__ bias, const float* __restrict__ xres)
{
    constexpr int KTOT  = (MODE==1) ? ED : (MODE==3) ? KC3 : HID;
    constexpr int NCK   = KTOT / BK;
    constexpr bool HAS_BIAS = (MODE != 7);

    extern __shared__ __align__(16) char smem_raw[];
    fp16* sm = (fp16*)smem_raw;
    __shared__ int sSrc[BM];
    __shared__ int sDst[BM];

    const int tid = threadIdx.x;
    const int n0  = blockIdx.x * BN;
    const int m0  = blockIdx.y * BM;

    if constexpr (MODE==1 || MODE==2){
        if (tid < BM){
            if (MODE == 1) sSrc[tid] = g_ei[m0 + tid];
            sDst[tid] = g_ei[NE + m0 + tid];
        }
    }

    const int wid = tid >> 5, lane = tid & 31;
    const int wm  = wid >> 1, wn = wid & 1;   // 4x2 warp grid, warp tile 32x64
    const int g   = lane >> 2, t = lane & 3;

    float acc[2][8][4];
    #pragma unroll
    for (int a = 0; a < 2; a++)
        #pragma unroll
        for (int b = 0; b < 8; b++)
            #pragma unroll
            for (int c = 0; c < 4; c++) acc[a][b][c] = 0.f;

    const fp16 *W;
    if      constexpr (MODE==1){ W = g_w1c; }
    else if constexpr (MODE==2){ W = g_w2t; }
    else if constexpr (MODE==3){ W = g_w3t; }
    else if constexpr (MODE==4){ W = g_w4t; }
    else { W = (n0 < HID) ? g_w1a : g_w1b; }
    const int nW = (MODE==7 && n0 >= HID) ? (n0 - HID) : n0;

    auto load_chunk = [&](int kc, int st){
        const int k0 = kc * BK;
        fp16* stg = sm + st*STG;
        // A: 128x32 fp16 = 512 16B-chunks -> 2 per thread
        #pragma unroll
        for (int j = 0; j < 2; j++){
            int p = tid + j*256;
            int r = p >> 2, c = (p & 3) * 8;
            int k = k0 + c;
            const fp16 *pa;
            if constexpr (MODE==1){
                pa = g_ea + (size_t)(m0 + r)*ED + k;
            } else if constexpr (MODE==2){
                pa = g_h + (size_t)(m0 + r)*HID + k;
            } else if constexpr (MODE==3){
                int node = min(m0 + r, NN-1);
                if (k < HID) pa = g_x     + (size_t)node*HID + k;
                else         pa = g_agg_h + (size_t)node*HID + (k - HID);
            } else if constexpr (MODE==4){
                int node = min(m0 + r, NN-1);
                pa = g_u + (size_t)node*HID + k;
            } else {
                int node = min(m0 + r, NN-1);
                pa = g_x + (size_t)node*HID + k;
            }
            cp16(smem_u32(stg + r*BKP + c), pa);
        }
        // B: 128x32 = 512 chunks -> 2 per thread
        #pragma unroll
        for (int j = 0; j < 2; j++){
            int p = tid + j*256;
            int r = p >> 2, c = (p & 3) * 8;
            size_t o = (size_t)(nW + r)*KTOT + k0 + c;
            cp16(smem_u32(stg + ASZ + r*BKP + c), W + o);
        }
        CP_COMMIT();
    };

    // prologue: stages 0 and 1
    load_chunk(0, 0);
    if (NCK > 1) load_chunk(1, 1);

    for (int kc = 0; kc < NCK; ++kc){
        if (kc + 1 < NCK) CP_WAIT1();   // chunk kc complete (newest group may be in flight)
        else              CP_WAIT0();
        __syncthreads();                // all warps done computing stage (kc+2)%3's old data
        if (kc + 2 < NCK) load_chunk(kc + 2, (kc + 2) % NSTAGE);

        fp16* stg = sm + (kc % NSTAGE)*STG;
        fp16* sA  = stg;
        fp16* sB  = stg + ASZ;

        #pragma unroll
        for (int ks = 0; ks < 2; ++ks){
            const int kk = ks * 16;
            unsigned af[2][4];
            #pragma unroll
            for (int mt = 0; mt < 2; ++mt){
                int row = wm*32 + mt*16 + (lane & 7) + ((lane >> 3) & 1) * 8;
                int col = kk + (lane >> 4) * 8;
                ldsm_x4(af[mt][0], af[mt][1], af[mt][2], af[mt][3],
                        smem_u32(sA + row*BKP + col));
            }
            unsigned bf[8][2];
            #pragma unroll
            for (int np = 0; np < 4; ++np){
                int ntl = 2*np + (lane >> 4);
                int row = wn*64 + ntl*8 + (lane & 7);
                int col = kk + ((lane >> 3) & 1) * 8;
                unsigned r0, r1, r2, r3;
                ldsm_x4(r0, r1, r2, r3, smem_u32(sB + row*BKP + col));
                bf[2*np][0]=r0; bf[2*np][1]=r1; bf[2*np+1][0]=r2; bf[2*np+1][1]=r3;
            }
            #pragma unroll
            for (int mt = 0; mt < 2; ++mt)
                #pragma unroll
                for (int nt = 0; nt < 8; ++nt)
                    mma_f16(acc[mt][nt], af[mt][0], af[mt][1], af[mt][2], af[mt][3],
                            bf[nt][0], bf[nt][1]);
        }
    }

    // ---- epilogue (scale by WINV) ----
    #pragma unroll
    for (int mt = 0; mt < 2; ++mt){
        const int rl0 = wm*32 + mt*16 + g;
        const int rl1 = rl0 + 8;
        int s0 = 0, s1 = 0, d0 = 0, d1 = 0;
        if constexpr (MODE==1){ s0 = sSrc[rl0]; s1 = sSrc[rl1]; d0 = sDst[rl0]; d1 = sDst[rl1]; }
        if constexpr (MODE==2){ d0 = sDst[rl0]; d1 = sDst[rl1]; }
        #pragma unroll
        for (int nt = 0; nt < 8; ++nt){
            const int col = n0 + wn*64 + nt*8 + t*2;
            float bv0 = 0.f, bv1 = 0.f;
            if constexpr (HAS_BIAS){ bv0 = bias[col]; bv1 = bias[col+1]; }
            float v00 = acc[mt][nt][0]*WINV + bv0;
            float v01 = acc[mt][nt][1]*WINV + bv1;
            float v10 = acc[mt][nt][2]*WINV + bv0;
            float v11 = acc[mt][nt][3]*WINV + bv1;
            if constexpr (MODE==1){
                float2 p0 = *(const float2*)&g_P[(size_t)s0*HID + col];
                float2 q0 = *(const float2*)&g_Q[(size_t)d0*HID + col];
                float2 p1 = *(const float2*)&g_P[(size_t)s1*HID + col];
                float2 q1 = *(const float2*)&g_Q[(size_t)d1*HID + col];
                v00 = mishf(v00 + p0.x + q0.x);
                v01 = mishf(v01 + p0.y + q0.y);
                v10 = mishf(v10 + p1.x + q1.x);
                v11 = mishf(v11 + p1.y + q1.y);
                size_t o0 = (size_t)(m0+rl0)*HID + col;
                size_t o1 = (size_t)(m0+rl1)*HID + col;
                *(uint32_t*)&g_h[o0] = pack2h(__float2half(v00), __float2half(v01));
                *(uint32_t*)&g_h[o1] = pack2h(__float2half(v10), __float2half(v11));
            } else if constexpr (MODE==2){
                v00 = mishf(v00); v01 = mishf(v01); v10 = mishf(v10); v11 = mishf(v11);
                float p00 = __shfl_xor_sync(0xffffffffu, v00, 1);
                float p01 = __shfl_xor_sync(0xffffffffu, v01, 1);
                float p10 = __shfl_xor_sync(0xffffffffu, v10, 1);
                float p11 = __shfl_xor_sync(0xffffffffu, v11, 1);
                if ((t & 1) == 0){
                    atomicAdd((float4*)&g_agg[(size_t)d0*HID + col], make_float4(v00, v01, p00, p01));
                    atomicAdd((float4*)&g_agg[(size_t)d1*HID + col], make_float4(v10, v11, p10, p11));
                }
            } else if constexpr (MODE==3){
                const int r0i = m0 + rl0, r1i = m0 + rl1;
                if (r0i < NN){
                    size_t o = (size_t)r0i*HID + col;
                    *(uint32_t*)&g_u[o] = pack2h(__float2half(mishf(v00)), __float2half(mishf(v01)));
                }
                if (r1i < NN){
                    size_t o = (size_t)r1i*HID + col;
                    *(uint32_t*)&g_u[o] = pack2h(__float2half(mishf(v10)), __float2half(mishf(v11)));
                }
            } else if constexpr (MODE==4){
                const int r0i = m0 + rl0, r1i = m0 + rl1;
                if (r0i < NN){
                    float2 xv = *(const float2*)&xres[(size_t)r0i*HID + col];
                    *(float2*)&g_y[(size_t)r0i*HID + col] = make_float2(v00 + xv.x, v01 + xv.y);
                }
                if (r1i < NN){
                    float2 xv = *(const float2*)&xres[(size_t)r1i*HID + col];
                    *(float2*)&g_y[(size_t)r1i*HID + col] = make_float2(v10 + xv.x, v11 + xv.y);
                }
            } else { // MODE 7
                float* dst = (n0 < HID) ? g_P : g_Q;
                const int cw = nW + wn*64 + nt*8 + t*2;
                const int r0i = m0 + rl0, r1i = m0 + rl1;
                if (r0i < NN)
                    *(float2*)&dst[(size_t)r0i*HID + cw] = make_float2(v00, v01);
                if (r1i < NN)
                    *(float2*)&dst[(size_t)r1i*HID + cw] = make_float2(v10, v11);
            }
        }
    }
}

// ---------------- LayerNorm ----------------
__global__ __launch_bounds__(128)
void ln_kernel(const float* __restrict__ gamma, const float* __restrict__ beta,
               float* __restrict__ out)
{
    const int row = blockIdx.x, tid = threadIdx.x;
    float4 v = *((const float4*)(g_y + (size_t)row*HID) + tid);
    float s  = v.x + v.y + v.z + v.w;
    float ss = fmaf(v.x, v.x, fmaf(v.y, v.y, fmaf(v.z, v.z, v.w*v.w)));
    #pragma unroll
    for (int o = 16; o > 0; o >>= 1){
        s  += __shfl_xor_sync(0xffffffffu, s,  o);
        ss += __shfl_xor_sync(0xffffffffu, ss, o);
    }
    __shared__ float sh_s[4], sh_ss[4];
    if ((tid & 31) == 0){ sh_s[tid >> 5] = s; sh_ss[tid >> 5] = ss; }
    __syncthreads();
    s  = sh_s[0]  + sh_s[1]  + sh_s[2]  + sh_s[3];
    ss = sh_ss[0] + sh_ss[1] + sh_ss[2] + sh_ss[3];
    const float mu  = s * (1.f / HID);
    const float var = ss * (1.f / HID) - mu * mu;
    const float inv = rsqrtf(var + 1e-5f);
    float4 gm = ((const float4*)gamma)[tid];
    float4 bt = ((const float4*)beta)[tid];
    float4 o;
    o.x = (v.x - mu) * inv * gm.x + bt.x;
    o.y = (v.y - mu) * inv * gm.y + bt.y;
    o.z = (v.z - mu) * inv * gm.z + bt.z;
    o.w = (v.w - mu) * inv * gm.w + bt.w;
    *((float4*)(out + (size_t)row*HID) + tid) = o;
}

// ---------------- launch ----------------
extern "C" void kernel_launch(void* const* d_in, const int* in_sizes, int n_in,
                              void* d_out, int out_size)
{
    (void)in_sizes; (void)n_in; (void)out_size;
    const float* x     = (const float*)d_in[0];
    const void*  ei    = d_in[1];
    const float* ea    = (const float*)d_in[2];
    const float* W1    = (const float*)d_in[3];
    const float* b1    = (const float*)d_in[4];
    const float* W2    = (const float*)d_in[5];
    const float* b2    = (const float*)d_in[6];
    const float* W3    = (const float*)d_in[7];
    const float* b3    = (const float*)d_in[8];
    const float* W4    = (const float*)d_in[9];
    const float* b4    = (const float*)d_in[10];
    const float* gamma = (const float*)d_in[11];
    const float* beta  = (const float*)d_in[12];
    float* out = (float*)d_out;

    cudaFuncSetAttribute(gemm_kernel<1>, cudaFuncAttributeMaxDynamicSharedMemorySize, SMEM_BYTES);
    cudaFuncSetAttribute(gemm_kernel<2>, cudaFuncAttributeMaxDynamicSharedMemorySize, SMEM_BYTES);
    cudaFuncSetAttribute(gemm_kernel<3>, cudaFuncAttributeMaxDynamicSharedMemorySize, SMEM_BYTES);
    cudaFuncSetAttribute(gemm_kernel<4>, cudaFuncAttributeMaxDynamicSharedMemorySize, SMEM_BYTES);
    cudaFuncSetAttribute(gemm_kernel<7>, cudaFuncAttributeMaxDynamicSharedMemorySize, SMEM_BYTES);

    k_split_all  <<<(SPLIT_ALL_TOT + 255)/256, 256>>>(x, W1, W2, W3, W4);   // 1
    k_split_ea   <<<(NE*ED + 255)/256, 256>>>(ea);                          // 2
    k_decode_zero<<<(NN*HID + 255)/256, 256>>>(ei);                         // 3

    dim3 gPQ(2*HID/BN, (NN + BM - 1)/BM);    // (8, 157)
    dim3 gE(HID/BN, NE/BM);                  // (4, 2500)
    dim3 gN(HID/BN, (NN + BM - 1)/BM);       // (4, 157)
    gemm_kernel<7><<<gPQ, 256, SMEM_BYTES>>>(nullptr, nullptr);  // 4: P|Q
    gemm_kernel<1><<<gE, 256, SMEM_BYTES>>>(b1, nullptr);        // 5: h
    gemm_kernel<2><<<gE, 256, SMEM_BYTES>>>(b2, nullptr);        // 6: messages+scatter
    k_split_agg  <<<(NN*HID + 255)/256, 256>>>();                // 7
    gemm_kernel<3><<<gN, 256, SMEM_BYTES>>>(b3, nullptr);        // 8: u
    gemm_kernel<4><<<gN, 256, SMEM_BYTES>>>(b4, x);              // 9: y
    ln_kernel<<<NN, 128>>>(gamma, beta, out);                    // 10
}